// round 2
// baseline (speedup 1.0000x reference)
#include <cuda_runtime.h>
#include <math.h>

// Problem dims (fixed by the dataset)
#define NB     8
#define B_SZ   4
#define S_SZ   4096
#define DIN    2048
#define DHID   2048
#define DH     1024
#define MROWS  (B_SZ * S_SZ)   // 16384

// GEMM tile config
#define BM 128
#define BN 128
#define BK 16

// ---------------------------------------------------------------------------
// Scratch (device globals -- no allocation allowed in kernel_launch)
// ---------------------------------------------------------------------------
__device__ float g_xh [(size_t)MROWS * DHID];  // x @ W_in + b_in
__device__ float g_gx [(size_t)MROWS * DH];    // pre-sigmoid gate_x
__device__ float g_ga [(size_t)MROWS * DH];    // pre-sigmoid gate_a
__device__ float g_are[(size_t)MROWS * DH];
__device__ float g_aim[(size_t)MROWS * DH];
__device__ float g_xr [(size_t)MROWS * DH];
__device__ float g_xi [(size_t)MROWS * DH];
__device__ float g_h  [(size_t)MROWS * DHID];  // scan output [hr | hi]

// ---------------------------------------------------------------------------
// Shared 128x128 fp32 GEMM tile (8x8 per-thread, 256 threads)
// A row-major [.. x K] (pre-offset to block row), B row-major [K x ..]
// (pre-offset to block col). C = A*B + bias(col).
// ---------------------------------------------------------------------------
__device__ __forceinline__ void sgemm_tile(
    const float* __restrict__ A, int lda,
    const float* __restrict__ Bm, int ldb,
    const float* __restrict__ bias,
    float* __restrict__ C, int ldc, int K)
{
    __shared__ float As[BK][BM];
    __shared__ float Bs[BK][BN];
    const int tid = threadIdx.x;
    const int tx = tid & 15;
    const int ty = tid >> 4;

    float acc[8][8];
#pragma unroll
    for (int m = 0; m < 8; m++)
#pragma unroll
        for (int n = 0; n < 8; n++) acc[m][n] = 0.f;

    for (int kt = 0; kt < K; kt += BK) {
        // Load A tile (128 rows x 16 cols), store transposed
#pragma unroll
        for (int i = 0; i < 2; i++) {
            int f = tid + i * 256;
            int r = f >> 2;
            int c = (f & 3) << 2;
            float4 v = *reinterpret_cast<const float4*>(A + (size_t)r * lda + kt + c);
            As[c + 0][r] = v.x;
            As[c + 1][r] = v.y;
            As[c + 2][r] = v.z;
            As[c + 3][r] = v.w;
        }
        // Load B tile (16 rows x 128 cols)
#pragma unroll
        for (int i = 0; i < 2; i++) {
            int f = tid + i * 256;
            int r = f >> 5;
            int c = (f & 31) << 2;
            *reinterpret_cast<float4*>(&Bs[r][c]) =
                *reinterpret_cast<const float4*>(Bm + (size_t)(kt + r) * ldb + c);
        }
        __syncthreads();
#pragma unroll
        for (int k = 0; k < BK; k++) {
            float4 a0 = *reinterpret_cast<const float4*>(&As[k][ty * 8]);
            float4 a1 = *reinterpret_cast<const float4*>(&As[k][ty * 8 + 4]);
            float4 b0 = *reinterpret_cast<const float4*>(&Bs[k][tx * 8]);
            float4 b1 = *reinterpret_cast<const float4*>(&Bs[k][tx * 8 + 4]);
            float ra[8] = {a0.x, a0.y, a0.z, a0.w, a1.x, a1.y, a1.z, a1.w};
            float rb[8] = {b0.x, b0.y, b0.z, b0.w, b1.x, b1.y, b1.z, b1.w};
#pragma unroll
            for (int m = 0; m < 8; m++)
#pragma unroll
                for (int n = 0; n < 8; n++)
                    acc[m][n] = fmaf(ra[m], rb[n], acc[m][n]);
        }
        __syncthreads();
    }

#pragma unroll
    for (int m = 0; m < 8; m++) {
        int r = ty * 8 + m;
#pragma unroll
        for (int n = 0; n < 8; n += 4) {
            int c = tx * 8 + n;
            float4 o;
            o.x = acc[m][n + 0] + bias[c + 0];
            o.y = acc[m][n + 1] + bias[c + 1];
            o.z = acc[m][n + 2] + bias[c + 2];
            o.w = acc[m][n + 3] + bias[c + 3];
            *reinterpret_cast<float4*>(C + (size_t)r * ldc + c) = o;
        }
    }
}

// Dense GEMM: C[M x N] = A[M x K] @ B[K x N] + bias
__global__ __launch_bounds__(256) void sgemm_kernel(
    const float* __restrict__ A, const float* __restrict__ Bm,
    const float* __restrict__ bias, float* __restrict__ C, int K, int N)
{
    const float* Ab = A + (size_t)blockIdx.y * BM * K;
    const float* Bb = Bm + (size_t)blockIdx.x * BN;
    float* Cb = C + (size_t)blockIdx.y * BM * N + (size_t)blockIdx.x * BN;
    sgemm_tile(Ab, K, Bb, N, bias + blockIdx.x * BN, Cb, N, K);
}

// Block-diagonal gate GEMMs: for each of 8 blocks, [16384 x 256] @ [256 x 128]
// grid = (MROWS/BM, NB, 2); z selects gate_x vs gate_a weights.
__global__ __launch_bounds__(256) void blockdiag_kernel(
    const float* __restrict__ xh,
    const float* __restrict__ Wgx, const float* __restrict__ bgx,
    const float* __restrict__ Wga, const float* __restrict__ bga,
    float* __restrict__ gx, float* __restrict__ ga)
{
    const int nb = blockIdx.y;
    const int which = blockIdx.z;
    const float* W    = which ? Wga : Wgx;
    const float* bias = which ? bga : bgx;
    float*       out  = which ? ga  : gx;
    const float* Ab = xh + (size_t)blockIdx.x * BM * DHID + nb * 256;
    const float* Bb = W + (size_t)nb * 256 * 128;
    float* Cb = out + (size_t)blockIdx.x * BM * DH + nb * 128;
    sgemm_tile(Ab, DHID, Bb, 128, bias + nb * 128, Cb, DH, 256);
}

// ---------------------------------------------------------------------------
// Pointwise: gates -> a_re, a_im, gated/normalized xr, xi
// ---------------------------------------------------------------------------
__global__ __launch_bounds__(256) void pointwise_kernel(
    const float* __restrict__ xh,
    const float* __restrict__ gxl, const float* __restrict__ gal,
    const float* __restrict__ arp, const float* __restrict__ aip,
    float* __restrict__ are, float* __restrict__ aim,
    float* __restrict__ xr, float* __restrict__ xi)
{
    size_t e = (size_t)blockIdx.x * blockDim.x + threadIdx.x;
    int d = (int)(e & (DH - 1));
    size_t row = e >> 10;

    float gxv = 1.f / (1.f + expf(-gxl[e]));
    float gav = 1.f / (1.f + expf(-gal[e]));
    float v = arp[d];
    float sp = fmaxf(v, 0.f) + log1pf(expf(-fabsf(v)));  // softplus
    float log_a = -8.f * gav * sp;
    float mag = expf(log_a);
    float th = aip[d] * gav;
    float sn, cs;
    sincosf(th, &sn, &cs);
    float asq = mag * mag;                 // exp(2*log_a)
    float nrm = sqrtf(fmaxf(1.f - asq, 0.f));
    float scale = gxv * nrm;

    size_t xrow = row * DHID + d;
    are[e] = mag * cs;
    aim[e] = mag * sn;
    xr[e] = scale * xh[xrow];
    xi[e] = scale * xh[xrow + DH];
}

// ---------------------------------------------------------------------------
// Sequential complex scan along S, one thread per (b, d) chain.
// Coalesced: at step s, adjacent threads (adjacent d) touch adjacent floats.
// Writes h = [hr | hi] rows and h_last at s = S-1.
// ---------------------------------------------------------------------------
__global__ __launch_bounds__(128) void scan_kernel(
    const float* __restrict__ are, const float* __restrict__ aim,
    const float* __restrict__ xr, const float* __restrict__ xi,
    float* __restrict__ h, float* __restrict__ h_last)
{
    int chain = blockIdx.x * blockDim.x + threadIdx.x;  // 0..4095
    int b = chain >> 10;
    int d = chain & (DH - 1);
    float hr = 0.f, hi = 0.f;
    size_t base  = (size_t)b * S_SZ * DH + d;
    size_t hbase = (size_t)b * S_SZ * DHID + d;

#pragma unroll 4
    for (int s = 0; s < S_SZ; s++) {
        size_t idx = base + (size_t)s * DH;
        float ar = are[idx];
        float ai = aim[idx];
        float vr = xr[idx];
        float vi = xi[idx];
        float nhr = fmaf(ar, hr, fmaf(-ai, hi, vr));
        float nhi = fmaf(ar, hi, fmaf(ai, hr, vi));
        hr = nhr;
        hi = nhi;
        size_t hrow = hbase + (size_t)s * DHID;
        h[hrow]      = hr;
        h[hrow + DH] = hi;
    }
    h_last[(size_t)b * DHID + d]      = hr;
    h_last[(size_t)b * DHID + d + DH] = hi;
}

// ---------------------------------------------------------------------------
// Launch
// ---------------------------------------------------------------------------
extern "C" void kernel_launch(void* const* d_in, const int* in_sizes, int n_in,
                              void* d_out, int out_size)
{
    const float* x     = (const float*)d_in[0];
    const float* arp   = (const float*)d_in[1];
    const float* aip   = (const float*)d_in[2];
    const float* W_in  = (const float*)d_in[3];
    const float* b_in  = (const float*)d_in[4];
    const float* Wgx   = (const float*)d_in[5];
    const float* bgx   = (const float*)d_in[6];
    const float* Wga   = (const float*)d_in[7];
    const float* bga   = (const float*)d_in[8];
    const float* W_out = (const float*)d_in[9];
    const float* b_out = (const float*)d_in[10];

    float* y = (float*)d_out;
    float* h_last = (float*)d_out + ((size_t)out_size - (size_t)B_SZ * DHID);

    float *xh, *gx, *ga, *are, *aim, *xr, *xi, *h;
    cudaGetSymbolAddress((void**)&xh,  g_xh);
    cudaGetSymbolAddress((void**)&gx,  g_gx);
    cudaGetSymbolAddress((void**)&ga,  g_ga);
    cudaGetSymbolAddress((void**)&are, g_are);
    cudaGetSymbolAddress((void**)&aim, g_aim);
    cudaGetSymbolAddress((void**)&xr,  g_xr);
    cudaGetSymbolAddress((void**)&xi,  g_xi);
    cudaGetSymbolAddress((void**)&h,   g_h);

    dim3 blk(256);

    // 1) x_h = x @ W_in + b_in   [16384 x 2048]
    sgemm_kernel<<<dim3(DHID / BN, MROWS / BM), blk>>>(x, W_in, b_in, xh, DIN, DHID);

    // 2) gate linears (block-diagonal), bias added in epilogue
    blockdiag_kernel<<<dim3(MROWS / BM, NB, 2), blk>>>(xh, Wgx, bgx, Wga, bga, gx, ga);

    // 3) pointwise: produce a_re, a_im, xr, xi
    pointwise_kernel<<<(MROWS * (size_t)DH) / 256, 256>>>(xh, gx, ga, arp, aip,
                                                          are, aim, xr, xi);

    // 4) complex linear scan along S
    scan_kernel<<<(B_SZ * DH) / 128, 128>>>(are, aim, xr, xi, h, h_last);

    // 5) y = h @ W_out + b_out   [16384 x 2048]
    sgemm_kernel<<<dim3(DIN / BN, MROWS / BM), blk>>>(h, W_out, b_out, y, DHID, DIN);
}

// round 3
// speedup vs baseline: 1.3472x; 1.3472x over previous
#include <cuda_runtime.h>
#include <cuda_bf16.h>
#include <mma.h>
#include <math.h>

using namespace nvcuda;

// Problem dims (fixed by the dataset)
#define NB     8
#define B_SZ   4
#define S_SZ   4096
#define DIN    2048
#define DHID   2048
#define DH     1024
#define MROWS  (B_SZ * S_SZ)   // 16384

// fp32 GEMM tile config (block-diag gates only)
#define BM 128
#define BN 128
#define BK 16

// wmma tile strides (bf16 elements)
#define LDA 40
#define LDB 136

// ---------------------------------------------------------------------------
// Scratch (device globals -- no allocation allowed in kernel_launch)
// ---------------------------------------------------------------------------
__device__ float g_xh [(size_t)MROWS * DHID];  // x @ W_in + b_in
__device__ float g_gx [(size_t)MROWS * DH];    // pre-sigmoid gate_x
__device__ float g_ga [(size_t)MROWS * DH];    // pre-sigmoid gate_a
__device__ float g_are[(size_t)MROWS * DH];
__device__ float g_aim[(size_t)MROWS * DH];
__device__ float g_xr [(size_t)MROWS * DH];
__device__ float g_xi [(size_t)MROWS * DH];
__device__ float g_h  [(size_t)MROWS * DHID];  // scan output [hr | hi]

// split-bf16 staging (activations reused for x then h; weights for W_in then W_out)
__device__ __nv_bfloat16 g_ahi[(size_t)MROWS * DIN];
__device__ __nv_bfloat16 g_alo[(size_t)MROWS * DIN];
__device__ __nv_bfloat16 g_whi[(size_t)DIN * DHID];
__device__ __nv_bfloat16 g_wlo[(size_t)DIN * DHID];

// ---------------------------------------------------------------------------
// fp32 -> (hi, lo) bf16 split. 4 elements per thread.
// ---------------------------------------------------------------------------
__global__ __launch_bounds__(256) void cvt_hilo_kernel(
    const float4* __restrict__ in, uint2* __restrict__ hi, uint2* __restrict__ lo,
    size_t n4)
{
    size_t i = (size_t)blockIdx.x * 256 + threadIdx.x;
    if (i >= n4) return;
    float4 v = in[i];
    __nv_bfloat16 h0 = __float2bfloat16(v.x);
    __nv_bfloat16 h1 = __float2bfloat16(v.y);
    __nv_bfloat16 h2 = __float2bfloat16(v.z);
    __nv_bfloat16 h3 = __float2bfloat16(v.w);
    __nv_bfloat16 l0 = __float2bfloat16(v.x - __bfloat162float(h0));
    __nv_bfloat16 l1 = __float2bfloat16(v.y - __bfloat162float(h1));
    __nv_bfloat16 l2 = __float2bfloat16(v.z - __bfloat162float(h2));
    __nv_bfloat16 l3 = __float2bfloat16(v.w - __bfloat162float(h3));
    __nv_bfloat162 ha = {h0, h1}, hb = {h2, h3};
    __nv_bfloat162 la = {l0, l1}, lb = {l2, l3};
    hi[i] = make_uint2(*reinterpret_cast<unsigned*>(&ha), *reinterpret_cast<unsigned*>(&hb));
    lo[i] = make_uint2(*reinterpret_cast<unsigned*>(&la), *reinterpret_cast<unsigned*>(&lb));
}

// ---------------------------------------------------------------------------
// Split-bf16 tensor-core GEMM:
//   C[M x N] = (Ahi+Alo)[M x K] @ (Bhi+Blo)[K x N] + bias   (drop lo*lo term)
// Block tile 128x128, 8 warps (2 n-cols x 4 m-rows), warp tile 32x64, BK=32.
// ---------------------------------------------------------------------------
__global__ __launch_bounds__(256) void wmma_gemm_kernel(
    const __nv_bfloat16* __restrict__ Ahi, const __nv_bfloat16* __restrict__ Alo,
    const __nv_bfloat16* __restrict__ Bhi, const __nv_bfloat16* __restrict__ Blo,
    const float* __restrict__ bias, float* __restrict__ C, int K, int N)
{
    __shared__ __align__(32) char smem[38912];
    __nv_bfloat16* As_hi = reinterpret_cast<__nv_bfloat16*>(smem);          // [128][LDA]
    __nv_bfloat16* As_lo = reinterpret_cast<__nv_bfloat16*>(smem + 10240);  // [128][LDA]
    __nv_bfloat16* Bs_hi = reinterpret_cast<__nv_bfloat16*>(smem + 20480);  // [32][LDB]
    __nv_bfloat16* Bs_lo = reinterpret_cast<__nv_bfloat16*>(smem + 29184);  // [32][LDB]
    float* stage = reinterpret_cast<float*>(smem);                          // epilogue reuse

    const int tid    = threadIdx.x;
    const int wid    = tid >> 5;
    const int lane   = tid & 31;
    const int warp_m = wid >> 1;   // 0..3
    const int warp_n = wid & 1;    // 0..1
    const int row0   = blockIdx.y * 128;
    const int bn     = blockIdx.x * 128;

    wmma::fragment<wmma::accumulator, 16, 16, 16, float> acc[2][4];
#pragma unroll
    for (int m = 0; m < 2; m++)
#pragma unroll
        for (int n = 0; n < 4; n++) wmma::fill_fragment(acc[m][n], 0.0f);

    for (int kt = 0; kt < K; kt += 32) {
        // A tiles: 128 rows x 32 cols (hi & lo), 8-elem vector chunks
#pragma unroll
        for (int i = 0; i < 2; i++) {
            int c = tid + i * 256;          // 0..511
            int r = c >> 2;
            int col = (c & 3) << 3;
            size_t g = (size_t)(row0 + r) * K + kt + col;
            *reinterpret_cast<uint4*>(As_hi + r * LDA + col) =
                *reinterpret_cast<const uint4*>(Ahi + g);
            *reinterpret_cast<uint4*>(As_lo + r * LDA + col) =
                *reinterpret_cast<const uint4*>(Alo + g);
        }
        // B tiles: 32 rows x 128 cols (hi & lo)
#pragma unroll
        for (int i = 0; i < 2; i++) {
            int c = tid + i * 256;
            int r = c >> 4;
            int col = (c & 15) << 3;
            size_t g = (size_t)(kt + r) * N + bn + col;
            *reinterpret_cast<uint4*>(Bs_hi + r * LDB + col) =
                *reinterpret_cast<const uint4*>(Bhi + g);
            *reinterpret_cast<uint4*>(Bs_lo + r * LDB + col) =
                *reinterpret_cast<const uint4*>(Blo + g);
        }
        __syncthreads();

#pragma unroll
        for (int kk = 0; kk < 32; kk += 16) {
            wmma::fragment<wmma::matrix_a, 16, 16, 16, __nv_bfloat16, wmma::row_major> a_hi[2], a_lo[2];
            wmma::fragment<wmma::matrix_b, 16, 16, 16, __nv_bfloat16, wmma::row_major> b_hi[4], b_lo[4];
#pragma unroll
            for (int m = 0; m < 2; m++) {
                int ar = warp_m * 32 + m * 16;
                wmma::load_matrix_sync(a_hi[m], As_hi + ar * LDA + kk, LDA);
                wmma::load_matrix_sync(a_lo[m], As_lo + ar * LDA + kk, LDA);
            }
#pragma unroll
            for (int n = 0; n < 4; n++) {
                int bc = warp_n * 64 + n * 16;
                wmma::load_matrix_sync(b_hi[n], Bs_hi + kk * LDB + bc, LDB);
                wmma::load_matrix_sync(b_lo[n], Bs_lo + kk * LDB + bc, LDB);
            }
#pragma unroll
            for (int m = 0; m < 2; m++)
#pragma unroll
                for (int n = 0; n < 4; n++) {
                    wmma::mma_sync(acc[m][n], a_hi[m], b_hi[n], acc[m][n]);
                    wmma::mma_sync(acc[m][n], a_hi[m], b_lo[n], acc[m][n]);
                    wmma::mma_sync(acc[m][n], a_lo[m], b_hi[n], acc[m][n]);
                }
        }
        __syncthreads();
    }

    // Epilogue: per-warp smem stage (16x64 fp32), exact fp32 bias add.
    float* st = stage + wid * (16 * 64);
#pragma unroll
    for (int m = 0; m < 2; m++) {
#pragma unroll
        for (int n = 0; n < 4; n++)
            wmma::store_matrix_sync(st + n * 16, acc[m][n], 64, wmma::mem_row_major);
        __syncwarp();
        int r = lane >> 1;
        int cseg = (lane & 1) * 32;
        int grow = row0 + warp_m * 32 + m * 16 + r;
        int gcol = bn + warp_n * 64 + cseg;
#pragma unroll
        for (int c = 0; c < 32; c += 4) {
            float4 v = *reinterpret_cast<float4*>(st + r * 64 + cseg + c);
            v.x += bias[gcol + c + 0];
            v.y += bias[gcol + c + 1];
            v.z += bias[gcol + c + 2];
            v.w += bias[gcol + c + 3];
            *reinterpret_cast<float4*>(C + (size_t)grow * N + gcol + c) = v;
        }
        __syncwarp();
    }
}

// ---------------------------------------------------------------------------
// fp32 128x128 GEMM tile (8x8 per-thread, 256 threads) -- block-diag gates
// ---------------------------------------------------------------------------
__device__ __forceinline__ void sgemm_tile(
    const float* __restrict__ A, int lda,
    const float* __restrict__ Bm, int ldb,
    const float* __restrict__ bias,
    float* __restrict__ C, int ldc, int K)
{
    __shared__ float As[BK][BM];
    __shared__ float Bs[BK][BN];
    const int tid = threadIdx.x;
    const int tx = tid & 15;
    const int ty = tid >> 4;

    float acc[8][8];
#pragma unroll
    for (int m = 0; m < 8; m++)
#pragma unroll
        for (int n = 0; n < 8; n++) acc[m][n] = 0.f;

    for (int kt = 0; kt < K; kt += BK) {
#pragma unroll
        for (int i = 0; i < 2; i++) {
            int f = tid + i * 256;
            int r = f >> 2;
            int c = (f & 3) << 2;
            float4 v = *reinterpret_cast<const float4*>(A + (size_t)r * lda + kt + c);
            As[c + 0][r] = v.x;
            As[c + 1][r] = v.y;
            As[c + 2][r] = v.z;
            As[c + 3][r] = v.w;
        }
#pragma unroll
        for (int i = 0; i < 2; i++) {
            int f = tid + i * 256;
            int r = f >> 5;
            int c = (f & 31) << 2;
            *reinterpret_cast<float4*>(&Bs[r][c]) =
                *reinterpret_cast<const float4*>(Bm + (size_t)(kt + r) * ldb + c);
        }
        __syncthreads();
#pragma unroll
        for (int k = 0; k < BK; k++) {
            float4 a0 = *reinterpret_cast<const float4*>(&As[k][ty * 8]);
            float4 a1 = *reinterpret_cast<const float4*>(&As[k][ty * 8 + 4]);
            float4 b0 = *reinterpret_cast<const float4*>(&Bs[k][tx * 8]);
            float4 b1 = *reinterpret_cast<const float4*>(&Bs[k][tx * 8 + 4]);
            float ra[8] = {a0.x, a0.y, a0.z, a0.w, a1.x, a1.y, a1.z, a1.w};
            float rb[8] = {b0.x, b0.y, b0.z, b0.w, b1.x, b1.y, b1.z, b1.w};
#pragma unroll
            for (int m = 0; m < 8; m++)
#pragma unroll
                for (int n = 0; n < 8; n++)
                    acc[m][n] = fmaf(ra[m], rb[n], acc[m][n]);
        }
        __syncthreads();
    }

#pragma unroll
    for (int m = 0; m < 8; m++) {
        int r = ty * 8 + m;
#pragma unroll
        for (int n = 0; n < 8; n += 4) {
            int c = tx * 8 + n;
            float4 o;
            o.x = acc[m][n + 0] + bias[c + 0];
            o.y = acc[m][n + 1] + bias[c + 1];
            o.z = acc[m][n + 2] + bias[c + 2];
            o.w = acc[m][n + 3] + bias[c + 3];
            *reinterpret_cast<float4*>(C + (size_t)r * ldc + c) = o;
        }
    }
}

// Block-diagonal gate GEMMs: for each of 8 blocks, [16384 x 256] @ [256 x 128]
__global__ __launch_bounds__(256) void blockdiag_kernel(
    const float* __restrict__ xh,
    const float* __restrict__ Wgx, const float* __restrict__ bgx,
    const float* __restrict__ Wga, const float* __restrict__ bga,
    float* __restrict__ gx, float* __restrict__ ga)
{
    const int nb = blockIdx.y;
    const int which = blockIdx.z;
    const float* W    = which ? Wga : Wgx;
    const float* bias = which ? bga : bgx;
    float*       out  = which ? ga  : gx;
    const float* Ab = xh + (size_t)blockIdx.x * BM * DHID + nb * 256;
    const float* Bb = W + (size_t)nb * 256 * 128;
    float* Cb = out + (size_t)blockIdx.x * BM * DH + nb * 128;
    sgemm_tile(Ab, DHID, Bb, 128, bias + nb * 128, Cb, DH, 256);
}

// ---------------------------------------------------------------------------
// Pointwise: gates -> a_re, a_im, gated/normalized xr, xi
// ---------------------------------------------------------------------------
__global__ __launch_bounds__(256) void pointwise_kernel(
    const float* __restrict__ xh,
    const float* __restrict__ gxl, const float* __restrict__ gal,
    const float* __restrict__ arp, const float* __restrict__ aip,
    float* __restrict__ are, float* __restrict__ aim,
    float* __restrict__ xr, float* __restrict__ xi)
{
    size_t e = (size_t)blockIdx.x * blockDim.x + threadIdx.x;
    int d = (int)(e & (DH - 1));
    size_t row = e >> 10;

    float gxv = 1.f / (1.f + expf(-gxl[e]));
    float gav = 1.f / (1.f + expf(-gal[e]));
    float v = arp[d];
    float sp = fmaxf(v, 0.f) + log1pf(expf(-fabsf(v)));  // softplus
    float log_a = -8.f * gav * sp;
    float mag = expf(log_a);
    float th = aip[d] * gav;
    float sn, cs;
    sincosf(th, &sn, &cs);
    float asq = mag * mag;
    float nrm = sqrtf(fmaxf(1.f - asq, 0.f));
    float scale = gxv * nrm;

    size_t xrow = row * DHID + d;
    are[e] = mag * cs;
    aim[e] = mag * sn;
    xr[e] = scale * xh[xrow];
    xi[e] = scale * xh[xrow + DH];
}

// ---------------------------------------------------------------------------
// Sequential complex scan along S, one thread per (b, d) chain.
// ---------------------------------------------------------------------------
__global__ __launch_bounds__(128) void scan_kernel(
    const float* __restrict__ are, const float* __restrict__ aim,
    const float* __restrict__ xr, const float* __restrict__ xi,
    float* __restrict__ h, float* __restrict__ h_last)
{
    int chain = blockIdx.x * blockDim.x + threadIdx.x;  // 0..4095
    int b = chain >> 10;
    int d = chain & (DH - 1);
    float hr = 0.f, hi = 0.f;
    size_t base  = (size_t)b * S_SZ * DH + d;
    size_t hbase = (size_t)b * S_SZ * DHID + d;

#pragma unroll 4
    for (int s = 0; s < S_SZ; s++) {
        size_t idx = base + (size_t)s * DH;
        float ar = are[idx];
        float ai = aim[idx];
        float vr = xr[idx];
        float vi = xi[idx];
        float nhr = fmaf(ar, hr, fmaf(-ai, hi, vr));
        float nhi = fmaf(ar, hi, fmaf(ai, hr, vi));
        hr = nhr;
        hi = nhi;
        size_t hrow = hbase + (size_t)s * DHID;
        h[hrow]      = hr;
        h[hrow + DH] = hi;
    }
    h_last[(size_t)b * DHID + d]      = hr;
    h_last[(size_t)b * DHID + d + DH] = hi;
}

// ---------------------------------------------------------------------------
// Launch
// ---------------------------------------------------------------------------
extern "C" void kernel_launch(void* const* d_in, const int* in_sizes, int n_in,
                              void* d_out, int out_size)
{
    const float* x     = (const float*)d_in[0];
    const float* arp   = (const float*)d_in[1];
    const float* aip   = (const float*)d_in[2];
    const float* W_in  = (const float*)d_in[3];
    const float* b_in  = (const float*)d_in[4];
    const float* Wgx   = (const float*)d_in[5];
    const float* bgx   = (const float*)d_in[6];
    const float* Wga   = (const float*)d_in[7];
    const float* bga   = (const float*)d_in[8];
    const float* W_out = (const float*)d_in[9];
    const float* b_out = (const float*)d_in[10];

    float* y = (float*)d_out;
    float* h_last = (float*)d_out + ((size_t)out_size - (size_t)B_SZ * DHID);

    float *xh, *gx, *ga, *are, *aim, *xr, *xi, *h;
    __nv_bfloat16 *ahi, *alo, *whi, *wlo;
    cudaGetSymbolAddress((void**)&xh,  g_xh);
    cudaGetSymbolAddress((void**)&gx,  g_gx);
    cudaGetSymbolAddress((void**)&ga,  g_ga);
    cudaGetSymbolAddress((void**)&are, g_are);
    cudaGetSymbolAddress((void**)&aim, g_aim);
    cudaGetSymbolAddress((void**)&xr,  g_xr);
    cudaGetSymbolAddress((void**)&xi,  g_xi);
    cudaGetSymbolAddress((void**)&h,   g_h);
    cudaGetSymbolAddress((void**)&ahi, g_ahi);
    cudaGetSymbolAddress((void**)&alo, g_alo);
    cudaGetSymbolAddress((void**)&whi, g_whi);
    cudaGetSymbolAddress((void**)&wlo, g_wlo);

    const size_t nx4 = (size_t)MROWS * DIN / 4;        // activation elems / 4
    const size_t nw4 = (size_t)DIN * DHID / 4;         // weight elems / 4

    // 1) split x, W_in to bf16 hi/lo; x_h = x @ W_in + b_in (tensor cores)
    cvt_hilo_kernel<<<(unsigned)((nx4 + 255) / 256), 256>>>(
        (const float4*)x, (uint2*)ahi, (uint2*)alo, nx4);
    cvt_hilo_kernel<<<(unsigned)((nw4 + 255) / 256), 256>>>(
        (const float4*)W_in, (uint2*)whi, (uint2*)wlo, nw4);
    wmma_gemm_kernel<<<dim3(DHID / 128, MROWS / 128), 256>>>(
        ahi, alo, whi, wlo, b_in, xh, DIN, DHID);

    // 2) gate linears (block-diagonal, fp32)
    blockdiag_kernel<<<dim3(MROWS / BM, NB, 2), 256>>>(xh, Wgx, bgx, Wga, bga, gx, ga);

    // 3) pointwise: produce a_re, a_im, xr, xi
    pointwise_kernel<<<(unsigned)((MROWS * (size_t)DH) / 256), 256>>>(
        xh, gx, ga, arp, aip, are, aim, xr, xi);

    // 4) complex linear scan along S
    scan_kernel<<<(B_SZ * DH) / 128, 128>>>(are, aim, xr, xi, h, h_last);

    // 5) split h, W_out; y = h @ W_out + b_out (tensor cores)
    cvt_hilo_kernel<<<(unsigned)((nx4 + 255) / 256), 256>>>(
        (const float4*)h, (uint2*)ahi, (uint2*)alo, nx4);
    cvt_hilo_kernel<<<(unsigned)((nw4 + 255) / 256), 256>>>(
        (const float4*)W_out, (uint2*)whi, (uint2*)wlo, nw4);
    wmma_gemm_kernel<<<dim3(DIN / 128, MROWS / 128), 256>>>(
        ahi, alo, whi, wlo, b_out, y, DHID, DIN);
}

// round 5
// speedup vs baseline: 1.5238x; 1.1311x over previous
#include <cuda_runtime.h>
#include <cuda_bf16.h>
#include <mma.h>
#include <math.h>
#include <stdint.h>

using namespace nvcuda;

// Problem dims (fixed by the dataset)
#define NB     8
#define B_SZ   4
#define S_SZ   4096
#define DIN    2048
#define DHID   2048
#define DH     1024
#define MROWS  (B_SZ * S_SZ)   // 16384
#define GK     2048            // K (and N) for both big GEMMs

// fp32 GEMM tile config (block-diag gates only)
#define BM 128
#define BN 128
#define BK 16

// wmma GEMM tiling: CTA 128x128, BK=64, double buffered
#define TLDA 72     // A smem stride (elems): 144B, 16B-aligned, padded
#define TLDB 136    // B smem stride (elems): 272B, 16B-aligned, padded
#define A_T_BYTES (128 * TLDA * 2)            // 18432 per tensor
#define B_T_BYTES (64 * TLDB * 2)             // 17408 per tensor
#define STAGE_BYTES (2 * A_T_BYTES + 2 * B_T_BYTES)   // 71680
#define SMEM_DYN (2 * STAGE_BYTES)                    // 143360

// ---------------------------------------------------------------------------
// Scratch (device globals -- no allocation allowed in kernel_launch)
// ---------------------------------------------------------------------------
__device__ __align__(256) float g_xh [(size_t)MROWS * DHID];
__device__ __align__(256) float g_gx [(size_t)MROWS * DH];
__device__ __align__(256) float g_ga [(size_t)MROWS * DH];
__device__ __align__(256) float g_are[(size_t)MROWS * DH];
__device__ __align__(256) float g_aim[(size_t)MROWS * DH];
__device__ __align__(256) float g_xr [(size_t)MROWS * DH];
__device__ __align__(256) float g_xi [(size_t)MROWS * DH];
__device__ __align__(256) float g_h  [(size_t)MROWS * DHID];

__device__ __align__(256) __nv_bfloat16 g_ahi[(size_t)MROWS * GK];
__device__ __align__(256) __nv_bfloat16 g_alo[(size_t)MROWS * GK];
__device__ __align__(256) __nv_bfloat16 g_whi[(size_t)GK * GK];
__device__ __align__(256) __nv_bfloat16 g_wlo[(size_t)GK * GK];

// ---------------------------------------------------------------------------
// helpers
// ---------------------------------------------------------------------------
__device__ __forceinline__ uint32_t smem_u32(const void* p) {
    uint32_t a;
    asm("{ .reg .u64 t; cvta.to.shared.u64 t, %1; cvt.u32.u64 %0, t; }"
        : "=r"(a) : "l"(p));
    return a;
}
__device__ __forceinline__ void cp16(uint32_t s, const void* g) {
    asm volatile("cp.async.cg.shared.global [%0], [%1], 16;" :: "r"(s), "l"(g));
}

// ---------------------------------------------------------------------------
// fp32 -> (hi, lo) bf16 split. 4 elements per thread.
// ---------------------------------------------------------------------------
__global__ __launch_bounds__(256) void cvt_hilo_kernel(
    const float4* __restrict__ in, uint2* __restrict__ hi, uint2* __restrict__ lo,
    size_t n4)
{
    size_t i = (size_t)blockIdx.x * 256 + threadIdx.x;
    if (i >= n4) return;
    float4 v = in[i];
    __nv_bfloat16 h0 = __float2bfloat16(v.x);
    __nv_bfloat16 h1 = __float2bfloat16(v.y);
    __nv_bfloat16 h2 = __float2bfloat16(v.z);
    __nv_bfloat16 h3 = __float2bfloat16(v.w);
    __nv_bfloat16 l0 = __float2bfloat16(v.x - __bfloat162float(h0));
    __nv_bfloat16 l1 = __float2bfloat16(v.y - __bfloat162float(h1));
    __nv_bfloat16 l2 = __float2bfloat16(v.z - __bfloat162float(h2));
    __nv_bfloat16 l3 = __float2bfloat16(v.w - __bfloat162float(h3));
    __nv_bfloat162 ha = {h0, h1}, hb = {h2, h3};
    __nv_bfloat162 la = {l0, l1}, lb = {l2, l3};
    hi[i] = make_uint2(*reinterpret_cast<unsigned*>(&ha), *reinterpret_cast<unsigned*>(&hb));
    lo[i] = make_uint2(*reinterpret_cast<unsigned*>(&la), *reinterpret_cast<unsigned*>(&lb));
}

// ---------------------------------------------------------------------------
// Double-buffered split-bf16 wmma GEMM:
//   C[M x 2048] = (Ahi+Alo)[M x 2048] @ (Bhi+Blo)[2048 x 2048] + bias
// CTA tile 128x128, BK=64, cp.async 2-stage pipeline, 8 warps (4m x 2n),
// warp tile 32x64, 3 mma products (hi*hi + hi*lo + lo*hi), fp32 accum.
// ---------------------------------------------------------------------------
__device__ __forceinline__ void load_stage(
    const __nv_bfloat16* __restrict__ Ah, const __nv_bfloat16* __restrict__ Al,
    const __nv_bfloat16* __restrict__ Bh, const __nv_bfloat16* __restrict__ Bl,
    int row0, int bn, int kt, uint32_t base, int tid)
{
    // A: 128 rows x 64 k-cols (128B/row -> 8 x 16B chunks), hi & lo
#pragma unroll
    for (int i = 0; i < 4; i++) {
        int u = tid + (i << 8);      // 0..1023
        int r = u >> 3;
        int ch = u & 7;
        uint32_t so = (uint32_t)(r * (TLDA * 2) + ch * 16);
        size_t go = (size_t)(row0 + r) * GK + kt + ch * 8;
        cp16(base + so,             Ah + go);
        cp16(base + A_T_BYTES + so, Al + go);
    }
    // B: 64 k-rows x 128 n-cols (256B/row -> 16 x 16B chunks), hi & lo
#pragma unroll
    for (int i = 0; i < 4; i++) {
        int u = tid + (i << 8);
        int r = u >> 4;
        int ch = u & 15;
        uint32_t so = (uint32_t)(r * (TLDB * 2) + ch * 16);
        size_t go = (size_t)(kt + r) * GK + bn + ch * 8;
        cp16(base + 2 * A_T_BYTES + so,             Bh + go);
        cp16(base + 2 * A_T_BYTES + B_T_BYTES + so, Bl + go);
    }
}

__global__ __launch_bounds__(256) void wmma_gemm_kernel(
    const __nv_bfloat16* __restrict__ Ahi, const __nv_bfloat16* __restrict__ Alo,
    const __nv_bfloat16* __restrict__ Bhi, const __nv_bfloat16* __restrict__ Blo,
    const float* __restrict__ bias, float* __restrict__ C)
{
    extern __shared__ __align__(256) char smem[];
    const uint32_t sb = smem_u32(smem);
    const int tid    = threadIdx.x;
    const int wid    = tid >> 5;
    const int lane   = tid & 31;
    const int warp_m = wid >> 1;   // 0..3
    const int warp_n = wid & 1;    // 0..1
    const int row0   = blockIdx.y * 128;
    const int bn     = blockIdx.x * 128;

    wmma::fragment<wmma::accumulator, 16, 16, 16, float> acc[2][4];
#pragma unroll
    for (int m = 0; m < 2; m++)
#pragma unroll
        for (int n = 0; n < 4; n++) wmma::fill_fragment(acc[m][n], 0.0f);

    // Prologue: stage 0
    load_stage(Ahi, Alo, Bhi, Blo, row0, bn, 0, sb, tid);
    asm volatile("cp.async.commit_group;");

    const int nIter = GK / 64;   // 32
    for (int it = 0; it < nIter; ++it) {
        if (it + 1 < nIter) {
            load_stage(Ahi, Alo, Bhi, Blo, row0, bn, (it + 1) * 64,
                       sb + ((it + 1) & 1) * STAGE_BYTES, tid);
            asm volatile("cp.async.commit_group;");
            asm volatile("cp.async.wait_group 1;");
        } else {
            asm volatile("cp.async.wait_group 0;");
        }
        __syncthreads();

        char* stg = smem + (it & 1) * STAGE_BYTES;
        const __nv_bfloat16* As_hi = reinterpret_cast<const __nv_bfloat16*>(stg);
        const __nv_bfloat16* As_lo = reinterpret_cast<const __nv_bfloat16*>(stg + A_T_BYTES);
        const __nv_bfloat16* Bs_hi = reinterpret_cast<const __nv_bfloat16*>(stg + 2 * A_T_BYTES);
        const __nv_bfloat16* Bs_lo = reinterpret_cast<const __nv_bfloat16*>(stg + 2 * A_T_BYTES + B_T_BYTES);

#pragma unroll
        for (int kk = 0; kk < 64; kk += 16) {
            wmma::fragment<wmma::matrix_a, 16, 16, 16, __nv_bfloat16, wmma::row_major> a_hi[2], a_lo[2];
            wmma::fragment<wmma::matrix_b, 16, 16, 16, __nv_bfloat16, wmma::row_major> b_hi[4], b_lo[4];
#pragma unroll
            for (int m = 0; m < 2; m++) {
                int ar = warp_m * 32 + m * 16;
                wmma::load_matrix_sync(a_hi[m], As_hi + ar * TLDA + kk, TLDA);
                wmma::load_matrix_sync(a_lo[m], As_lo + ar * TLDA + kk, TLDA);
            }
#pragma unroll
            for (int n = 0; n < 4; n++) {
                int bc = warp_n * 64 + n * 16;
                wmma::load_matrix_sync(b_hi[n], Bs_hi + kk * TLDB + bc, TLDB);
                wmma::load_matrix_sync(b_lo[n], Bs_lo + kk * TLDB + bc, TLDB);
            }
#pragma unroll
            for (int m = 0; m < 2; m++)
#pragma unroll
                for (int n = 0; n < 4; n++) {
                    wmma::mma_sync(acc[m][n], a_hi[m], b_hi[n], acc[m][n]);
                    wmma::mma_sync(acc[m][n], a_hi[m], b_lo[n], acc[m][n]);
                    wmma::mma_sync(acc[m][n], a_lo[m], b_hi[n], acc[m][n]);
                }
        }
        __syncthreads();   // stage (it&1) free for prefetch issued next iter
    }

    // Epilogue: per-warp smem stage (16x64 fp32), exact fp32 bias add.
    float* stage = reinterpret_cast<float*>(smem);
    float* st = stage + wid * (16 * 64);
#pragma unroll
    for (int m = 0; m < 2; m++) {
#pragma unroll
        for (int n = 0; n < 4; n++)
            wmma::store_matrix_sync(st + n * 16, acc[m][n], 64, wmma::mem_row_major);
        __syncwarp();
        int r = lane >> 1;
        int cseg = (lane & 1) * 32;
        int grow = row0 + warp_m * 32 + m * 16 + r;
        int gcol = bn + warp_n * 64 + cseg;
#pragma unroll
        for (int c = 0; c < 32; c += 4) {
            float4 v = *reinterpret_cast<float4*>(st + r * 64 + cseg + c);
            v.x += bias[gcol + c + 0];
            v.y += bias[gcol + c + 1];
            v.z += bias[gcol + c + 2];
            v.w += bias[gcol + c + 3];
            *reinterpret_cast<float4*>(C + (size_t)grow * GK + gcol + c) = v;
        }
        __syncwarp();
    }
}

// ---------------------------------------------------------------------------
// fp32 128x128 GEMM tile (8x8 per-thread, 256 threads) -- block-diag gates
// ---------------------------------------------------------------------------
__device__ __forceinline__ void sgemm_tile(
    const float* __restrict__ A, int lda,
    const float* __restrict__ Bm, int ldb,
    const float* __restrict__ bias,
    float* __restrict__ C, int ldc, int K)
{
    __shared__ float As[BK][BM];
    __shared__ float Bs[BK][BN];
    const int tid = threadIdx.x;
    const int tx = tid & 15;
    const int ty = tid >> 4;

    float acc[8][8];
#pragma unroll
    for (int m = 0; m < 8; m++)
#pragma unroll
        for (int n = 0; n < 8; n++) acc[m][n] = 0.f;

    for (int kt = 0; kt < K; kt += BK) {
#pragma unroll
        for (int i = 0; i < 2; i++) {
            int f = tid + i * 256;
            int r = f >> 2;
            int c = (f & 3) << 2;
            float4 v = *reinterpret_cast<const float4*>(A + (size_t)r * lda + kt + c);
            As[c + 0][r] = v.x;
            As[c + 1][r] = v.y;
            As[c + 2][r] = v.z;
            As[c + 3][r] = v.w;
        }
#pragma unroll
        for (int i = 0; i < 2; i++) {
            int f = tid + i * 256;
            int r = f >> 5;
            int c = (f & 31) << 2;
            *reinterpret_cast<float4*>(&Bs[r][c]) =
                *reinterpret_cast<const float4*>(Bm + (size_t)(kt + r) * ldb + c);
        }
        __syncthreads();
#pragma unroll
        for (int k = 0; k < BK; k++) {
            float4 a0 = *reinterpret_cast<const float4*>(&As[k][ty * 8]);
            float4 a1 = *reinterpret_cast<const float4*>(&As[k][ty * 8 + 4]);
            float4 b0 = *reinterpret_cast<const float4*>(&Bs[k][tx * 8]);
            float4 b1 = *reinterpret_cast<const float4*>(&Bs[k][tx * 8 + 4]);
            float ra[8] = {a0.x, a0.y, a0.z, a0.w, a1.x, a1.y, a1.z, a1.w};
            float rb[8] = {b0.x, b0.y, b0.z, b0.w, b1.x, b1.y, b1.z, b1.w};
#pragma unroll
            for (int m = 0; m < 8; m++)
#pragma unroll
                for (int n = 0; n < 8; n++)
                    acc[m][n] = fmaf(ra[m], rb[n], acc[m][n]);
        }
        __syncthreads();
    }

#pragma unroll
    for (int m = 0; m < 8; m++) {
        int r = ty * 8 + m;
#pragma unroll
        for (int n = 0; n < 8; n += 4) {
            int c = tx * 8 + n;
            float4 o;
            o.x = acc[m][n + 0] + bias[c + 0];
            o.y = acc[m][n + 1] + bias[c + 1];
            o.z = acc[m][n + 2] + bias[c + 2];
            o.w = acc[m][n + 3] + bias[c + 3];
            *reinterpret_cast<float4*>(C + (size_t)r * ldc + c) = o;
        }
    }
}

__global__ __launch_bounds__(256) void blockdiag_kernel(
    const float* __restrict__ xh,
    const float* __restrict__ Wgx, const float* __restrict__ bgx,
    const float* __restrict__ Wga, const float* __restrict__ bga,
    float* __restrict__ gx, float* __restrict__ ga)
{
    const int nb = blockIdx.y;
    const int which = blockIdx.z;
    const float* W    = which ? Wga : Wgx;
    const float* bias = which ? bga : bgx;
    float*       out  = which ? ga  : gx;
    const float* Ab = xh + (size_t)blockIdx.x * BM * DHID + nb * 256;
    const float* Bb = W + (size_t)nb * 256 * 128;
    float* Cb = out + (size_t)blockIdx.x * BM * DH + nb * 128;
    sgemm_tile(Ab, DHID, Bb, 128, bias + nb * 128, Cb, DH, 256);
}

// ---------------------------------------------------------------------------
// Pointwise: gates -> a_re, a_im, gated/normalized xr, xi
// ---------------------------------------------------------------------------
__global__ __launch_bounds__(256) void pointwise_kernel(
    const float* __restrict__ xh,
    const float* __restrict__ gxl, const float* __restrict__ gal,
    const float* __restrict__ arp, const float* __restrict__ aip,
    float* __restrict__ are, float* __restrict__ aim,
    float* __restrict__ xr, float* __restrict__ xi)
{
    size_t e = (size_t)blockIdx.x * blockDim.x + threadIdx.x;
    int d = (int)(e & (DH - 1));
    size_t row = e >> 10;

    float gxv = 1.f / (1.f + expf(-gxl[e]));
    float gav = 1.f / (1.f + expf(-gal[e]));
    float v = arp[d];
    float sp = fmaxf(v, 0.f) + log1pf(expf(-fabsf(v)));  // softplus
    float log_a = -8.f * gav * sp;
    float mag = expf(log_a);
    float th = aip[d] * gav;
    float sn, cs;
    sincosf(th, &sn, &cs);
    float asq = mag * mag;
    float nrm = sqrtf(fmaxf(1.f - asq, 0.f));
    float scale = gxv * nrm;

    size_t xrow = row * DHID + d;
    are[e] = mag * cs;
    aim[e] = mag * sn;
    xr[e] = scale * xh[xrow];
    xi[e] = scale * xh[xrow + DH];
}

// ---------------------------------------------------------------------------
// Sequential complex scan along S, one thread per (b, d) chain.
// ---------------------------------------------------------------------------
__global__ __launch_bounds__(128) void scan_kernel(
    const float* __restrict__ are, const float* __restrict__ aim,
    const float* __restrict__ xr, const float* __restrict__ xi,
    float* __restrict__ h, float* __restrict__ h_last)
{
    int chain = blockIdx.x * blockDim.x + threadIdx.x;  // 0..4095
    int b = chain >> 10;
    int d = chain & (DH - 1);
    float hr = 0.f, hi = 0.f;
    size_t base  = (size_t)b * S_SZ * DH + d;
    size_t hbase = (size_t)b * S_SZ * DHID + d;

#pragma unroll 4
    for (int s = 0; s < S_SZ; s++) {
        size_t idx = base + (size_t)s * DH;
        float ar = are[idx];
        float ai = aim[idx];
        float vr = xr[idx];
        float vi = xi[idx];
        float nhr = fmaf(ar, hr, fmaf(-ai, hi, vr));
        float nhi = fmaf(ar, hi, fmaf(ai, hr, vi));
        hr = nhr;
        hi = nhi;
        size_t hrow = hbase + (size_t)s * DHID;
        h[hrow]      = hr;
        h[hrow + DH] = hi;
    }
    h_last[(size_t)b * DHID + d]      = hr;
    h_last[(size_t)b * DHID + d + DH] = hi;
}

// ---------------------------------------------------------------------------
// Launch
// ---------------------------------------------------------------------------
extern "C" void kernel_launch(void* const* d_in, const int* in_sizes, int n_in,
                              void* d_out, int out_size)
{
    const float* x     = (const float*)d_in[0];
    const float* arp   = (const float*)d_in[1];
    const float* aip   = (const float*)d_in[2];
    const float* W_in  = (const float*)d_in[3];
    const float* b_in  = (const float*)d_in[4];
    const float* Wgx   = (const float*)d_in[5];
    const float* bgx   = (const float*)d_in[6];
    const float* Wga   = (const float*)d_in[7];
    const float* bga   = (const float*)d_in[8];
    const float* W_out = (const float*)d_in[9];
    const float* b_out = (const float*)d_in[10];

    float* y = (float*)d_out;
    float* h_last = (float*)d_out + ((size_t)out_size - (size_t)B_SZ * DHID);

    float *xh, *gx, *ga, *are, *aim, *xr, *xi, *h;
    __nv_bfloat16 *ahi, *alo, *whi, *wlo;
    cudaGetSymbolAddress((void**)&xh,  g_xh);
    cudaGetSymbolAddress((void**)&gx,  g_gx);
    cudaGetSymbolAddress((void**)&ga,  g_ga);
    cudaGetSymbolAddress((void**)&are, g_are);
    cudaGetSymbolAddress((void**)&aim, g_aim);
    cudaGetSymbolAddress((void**)&xr,  g_xr);
    cudaGetSymbolAddress((void**)&xi,  g_xi);
    cudaGetSymbolAddress((void**)&h,   g_h);
    cudaGetSymbolAddress((void**)&ahi, g_ahi);
    cudaGetSymbolAddress((void**)&alo, g_alo);
    cudaGetSymbolAddress((void**)&whi, g_whi);
    cudaGetSymbolAddress((void**)&wlo, g_wlo);

    cudaFuncSetAttribute(wmma_gemm_kernel,
                         cudaFuncAttributeMaxDynamicSharedMemorySize, SMEM_DYN);

    const size_t nx4 = (size_t)MROWS * GK / 4;   // activation elems / 4
    const size_t nw4 = (size_t)GK * GK / 4;      // weight elems / 4

    // 1) split x, W_in; x_h = x @ W_in + b_in (double-buffered wmma)
    cvt_hilo_kernel<<<(unsigned)((nx4 + 255) / 256), 256>>>(
        (const float4*)x, (uint2*)ahi, (uint2*)alo, nx4);
    cvt_hilo_kernel<<<(unsigned)((nw4 + 255) / 256), 256>>>(
        (const float4*)W_in, (uint2*)whi, (uint2*)wlo, nw4);
    wmma_gemm_kernel<<<dim3(DHID / 128, MROWS / 128), 256, SMEM_DYN>>>(
        ahi, alo, whi, wlo, b_in, xh);

    // 2) gate linears (block-diagonal, fp32)
    blockdiag_kernel<<<dim3(MROWS / BM, NB, 2), 256>>>(xh, Wgx, bgx, Wga, bga, gx, ga);

    // 3) pointwise: produce a_re, a_im, xr, xi
    pointwise_kernel<<<(unsigned)((MROWS * (size_t)DH) / 256), 256>>>(
        xh, gx, ga, arp, aip, are, aim, xr, xi);

    // 4) complex linear scan along S
    scan_kernel<<<(B_SZ * DH) / 128, 128>>>(are, aim, xr, xi, h, h_last);

    // 5) split h, W_out; y = h @ W_out + b_out (double-buffered wmma)
    cvt_hilo_kernel<<<(unsigned)((nx4 + 255) / 256), 256>>>(
        (const float4*)h, (uint2*)ahi, (uint2*)alo, nx4);
    cvt_hilo_kernel<<<(unsigned)((nw4 + 255) / 256), 256>>>(
        (const float4*)W_out, (uint2*)whi, (uint2*)wlo, nw4);
    wmma_gemm_kernel<<<dim3(DIN / 128, MROWS / 128), 256, SMEM_DYN>>>(
        ahi, alo, whi, wlo, b_out, y);
}

// round 6
// speedup vs baseline: 2.2878x; 1.5013x over previous
#include <cuda_runtime.h>
#include <cuda_bf16.h>
#include <mma.h>
#include <math.h>
#include <stdint.h>

using namespace nvcuda;

// Problem dims (fixed by the dataset)
#define NB     8
#define B_SZ   4
#define S_SZ   4096
#define DIN    2048
#define DHID   2048
#define DH     1024
#define MROWS  (B_SZ * S_SZ)   // 16384
#define GK     2048            // K (and N) for both big GEMMs

// fp32 GEMM tile config (block-diag gates only)
#define BM 128
#define BN 128
#define BK 16

// wmma GEMM tiling: CTA 128x128, BK=64, 3-stage pipeline
#define TLDA 72     // A smem stride (elems)
#define TLDB 136    // B smem stride (elems)
#define A_T_BYTES (128 * TLDA * 2)            // 18432 per tensor
#define B_T_BYTES (64 * TLDB * 2)             // 17408 per tensor
#define STAGE_BYTES (2 * A_T_BYTES + 2 * B_T_BYTES)   // 71680
#define SMEM_DYN (3 * STAGE_BYTES)                    // 215040

// ---------------------------------------------------------------------------
// Scratch (device globals -- no allocation allowed in kernel_launch)
// ---------------------------------------------------------------------------
__device__ __align__(256) float g_xh [(size_t)MROWS * DHID];
__device__ __align__(256) float g_gx [(size_t)MROWS * DH];
__device__ __align__(256) float g_ga [(size_t)MROWS * DH];

__device__ __align__(256) __nv_bfloat16 g_ahi[(size_t)MROWS * GK];
__device__ __align__(256) __nv_bfloat16 g_alo[(size_t)MROWS * GK];
__device__ __align__(256) __nv_bfloat16 g_whi[(size_t)GK * GK];
__device__ __align__(256) __nv_bfloat16 g_wlo[(size_t)GK * GK];

// ---------------------------------------------------------------------------
// helpers
// ---------------------------------------------------------------------------
__device__ __forceinline__ void cp16(uint32_t s, const void* g) {
    asm volatile("cp.async.cg.shared.global [%0], [%1], 16;" :: "r"(s), "l"(g));
}
__device__ __forceinline__ uint32_t smem_u32(const void* p) {
    uint32_t a;
    asm("{ .reg .u64 t; cvta.to.shared.u64 t, %1; cvt.u32.u64 %0, t; }"
        : "=r"(a) : "l"(p));
    return a;
}

// ---------------------------------------------------------------------------
// fp32 -> (hi, lo) bf16 split. 4 elements per thread.
// ---------------------------------------------------------------------------
__global__ __launch_bounds__(256) void cvt_hilo_kernel(
    const float4* __restrict__ in, uint2* __restrict__ hi, uint2* __restrict__ lo,
    size_t n4)
{
    size_t i = (size_t)blockIdx.x * 256 + threadIdx.x;
    if (i >= n4) return;
    float4 v = in[i];
    __nv_bfloat16 h0 = __float2bfloat16(v.x);
    __nv_bfloat16 h1 = __float2bfloat16(v.y);
    __nv_bfloat16 h2 = __float2bfloat16(v.z);
    __nv_bfloat16 h3 = __float2bfloat16(v.w);
    __nv_bfloat16 l0 = __float2bfloat16(v.x - __bfloat162float(h0));
    __nv_bfloat16 l1 = __float2bfloat16(v.y - __bfloat162float(h1));
    __nv_bfloat16 l2 = __float2bfloat16(v.z - __bfloat162float(h2));
    __nv_bfloat16 l3 = __float2bfloat16(v.w - __bfloat162float(h3));
    __nv_bfloat162 ha = {h0, h1}, hb = {h2, h3};
    __nv_bfloat162 la = {l0, l1}, lb = {l2, l3};
    hi[i] = make_uint2(*reinterpret_cast<unsigned*>(&ha), *reinterpret_cast<unsigned*>(&hb));
    lo[i] = make_uint2(*reinterpret_cast<unsigned*>(&la), *reinterpret_cast<unsigned*>(&lb));
}

// ---------------------------------------------------------------------------
// 3-stage pipelined split-bf16 wmma GEMM:
//   C[M x 2048] = (Ahi+Alo)[M x 2048] @ (Bhi+Blo)[2048 x 2048] + bias
// ---------------------------------------------------------------------------
__device__ __forceinline__ void load_stage(
    const __nv_bfloat16* __restrict__ Ah, const __nv_bfloat16* __restrict__ Al,
    const __nv_bfloat16* __restrict__ Bh, const __nv_bfloat16* __restrict__ Bl,
    int row0, int bn, int kt, uint32_t base, int tid)
{
#pragma unroll
    for (int i = 0; i < 4; i++) {
        int u = tid + (i << 8);      // 0..1023
        int r = u >> 3;
        int ch = u & 7;
        uint32_t so = (uint32_t)(r * (TLDA * 2) + ch * 16);
        size_t go = (size_t)(row0 + r) * GK + kt + ch * 8;
        cp16(base + so,             Ah + go);
        cp16(base + A_T_BYTES + so, Al + go);
    }
#pragma unroll
    for (int i = 0; i < 4; i++) {
        int u = tid + (i << 8);
        int r = u >> 4;
        int ch = u & 15;
        uint32_t so = (uint32_t)(r * (TLDB * 2) + ch * 16);
        size_t go = (size_t)(kt + r) * GK + bn + ch * 8;
        cp16(base + 2 * A_T_BYTES + so,             Bh + go);
        cp16(base + 2 * A_T_BYTES + B_T_BYTES + so, Bl + go);
    }
}

__global__ __launch_bounds__(256, 1) void wmma_gemm_kernel(
    const __nv_bfloat16* __restrict__ Ahi, const __nv_bfloat16* __restrict__ Alo,
    const __nv_bfloat16* __restrict__ Bhi, const __nv_bfloat16* __restrict__ Blo,
    const float* __restrict__ bias, float* __restrict__ C)
{
    extern __shared__ __align__(256) char smem[];
    const uint32_t sb = smem_u32(smem);
    const int tid    = threadIdx.x;
    const int wid    = tid >> 5;
    const int lane   = tid & 31;
    const int warp_m = wid >> 1;   // 0..3
    const int warp_n = wid & 1;    // 0..1
    const int row0   = blockIdx.y * 128;
    const int bn     = blockIdx.x * 128;

    wmma::fragment<wmma::accumulator, 16, 16, 16, float> acc[2][4];
#pragma unroll
    for (int m = 0; m < 2; m++)
#pragma unroll
        for (int n = 0; n < 4; n++) wmma::fill_fragment(acc[m][n], 0.0f);

    load_stage(Ahi, Alo, Bhi, Blo, row0, bn, 0, sb, tid);
    asm volatile("cp.async.commit_group;");
    load_stage(Ahi, Alo, Bhi, Blo, row0, bn, 64, sb + STAGE_BYTES, tid);
    asm volatile("cp.async.commit_group;");

    const int nIter = GK / 64;   // 32
    for (int it = 0; it < nIter; ++it) {
        if (it < nIter - 1) asm volatile("cp.async.wait_group 1;");
        else                asm volatile("cp.async.wait_group 0;");
        __syncthreads();
        if (it + 2 < nIter) {
            load_stage(Ahi, Alo, Bhi, Blo, row0, bn, (it + 2) * 64,
                       sb + (uint32_t)((it + 2) % 3) * STAGE_BYTES, tid);
            asm volatile("cp.async.commit_group;");
        }

        char* stg = smem + (it % 3) * STAGE_BYTES;
        const __nv_bfloat16* As_hi = reinterpret_cast<const __nv_bfloat16*>(stg);
        const __nv_bfloat16* As_lo = reinterpret_cast<const __nv_bfloat16*>(stg + A_T_BYTES);
        const __nv_bfloat16* Bs_hi = reinterpret_cast<const __nv_bfloat16*>(stg + 2 * A_T_BYTES);
        const __nv_bfloat16* Bs_lo = reinterpret_cast<const __nv_bfloat16*>(stg + 2 * A_T_BYTES + B_T_BYTES);

#pragma unroll
        for (int kk = 0; kk < 64; kk += 16) {
            wmma::fragment<wmma::matrix_a, 16, 16, 16, __nv_bfloat16, wmma::row_major> a_hi[2], a_lo[2];
            wmma::fragment<wmma::matrix_b, 16, 16, 16, __nv_bfloat16, wmma::row_major> b_hi[4], b_lo[4];
#pragma unroll
            for (int m = 0; m < 2; m++) {
                int ar = warp_m * 32 + m * 16;
                wmma::load_matrix_sync(a_hi[m], As_hi + ar * TLDA + kk, TLDA);
                wmma::load_matrix_sync(a_lo[m], As_lo + ar * TLDA + kk, TLDA);
            }
#pragma unroll
            for (int n = 0; n < 4; n++) {
                int bc = warp_n * 64 + n * 16;
                wmma::load_matrix_sync(b_hi[n], Bs_hi + kk * TLDB + bc, TLDB);
                wmma::load_matrix_sync(b_lo[n], Bs_lo + kk * TLDB + bc, TLDB);
            }
#pragma unroll
            for (int m = 0; m < 2; m++)
#pragma unroll
                for (int n = 0; n < 4; n++) {
                    wmma::mma_sync(acc[m][n], a_hi[m], b_hi[n], acc[m][n]);
                    wmma::mma_sync(acc[m][n], a_hi[m], b_lo[n], acc[m][n]);
                    wmma::mma_sync(acc[m][n], a_lo[m], b_hi[n], acc[m][n]);
                }
        }
    }
    __syncthreads();

    // Epilogue: per-warp smem stage (16x64 fp32), exact fp32 bias add.
    float* stage = reinterpret_cast<float*>(smem);
    float* st = stage + wid * (16 * 64);
#pragma unroll
    for (int m = 0; m < 2; m++) {
#pragma unroll
        for (int n = 0; n < 4; n++)
            wmma::store_matrix_sync(st + n * 16, acc[m][n], 64, wmma::mem_row_major);
        __syncwarp();
        int r = lane >> 1;
        int cseg = (lane & 1) * 32;
        int grow = row0 + warp_m * 32 + m * 16 + r;
        int gcol = bn + warp_n * 64 + cseg;
#pragma unroll
        for (int c = 0; c < 32; c += 4) {
            float4 v = *reinterpret_cast<float4*>(st + r * 64 + cseg + c);
            v.x += bias[gcol + c + 0];
            v.y += bias[gcol + c + 1];
            v.z += bias[gcol + c + 2];
            v.w += bias[gcol + c + 3];
            *reinterpret_cast<float4*>(C + (size_t)grow * GK + gcol + c) = v;
        }
        __syncwarp();
    }
}

// ---------------------------------------------------------------------------
// fp32 128x128 GEMM tile (8x8 per-thread, 256 threads) -- block-diag gates
// ---------------------------------------------------------------------------
__device__ __forceinline__ void sgemm_tile(
    const float* __restrict__ A, int lda,
    const float* __restrict__ Bm, int ldb,
    const float* __restrict__ bias,
    float* __restrict__ C, int ldc, int K)
{
    __shared__ float As[BK][BM];
    __shared__ float Bs[BK][BN];
    const int tid = threadIdx.x;
    const int tx = tid & 15;
    const int ty = tid >> 4;

    float acc[8][8];
#pragma unroll
    for (int m = 0; m < 8; m++)
#pragma unroll
        for (int n = 0; n < 8; n++) acc[m][n] = 0.f;

    for (int kt = 0; kt < K; kt += BK) {
#pragma unroll
        for (int i = 0; i < 2; i++) {
            int f = tid + i * 256;
            int r = f >> 2;
            int c = (f & 3) << 2;
            float4 v = *reinterpret_cast<const float4*>(A + (size_t)r * lda + kt + c);
            As[c + 0][r] = v.x;
            As[c + 1][r] = v.y;
            As[c + 2][r] = v.z;
            As[c + 3][r] = v.w;
        }
#pragma unroll
        for (int i = 0; i < 2; i++) {
            int f = tid + i * 256;
            int r = f >> 5;
            int c = (f & 31) << 2;
            *reinterpret_cast<float4*>(&Bs[r][c]) =
                *reinterpret_cast<const float4*>(Bm + (size_t)(kt + r) * ldb + c);
        }
        __syncthreads();
#pragma unroll
        for (int k = 0; k < BK; k++) {
            float4 a0 = *reinterpret_cast<const float4*>(&As[k][ty * 8]);
            float4 a1 = *reinterpret_cast<const float4*>(&As[k][ty * 8 + 4]);
            float4 b0 = *reinterpret_cast<const float4*>(&Bs[k][tx * 8]);
            float4 b1 = *reinterpret_cast<const float4*>(&Bs[k][tx * 8 + 4]);
            float ra[8] = {a0.x, a0.y, a0.z, a0.w, a1.x, a1.y, a1.z, a1.w};
            float rb[8] = {b0.x, b0.y, b0.z, b0.w, b1.x, b1.y, b1.z, b1.w};
#pragma unroll
            for (int m = 0; m < 8; m++)
#pragma unroll
                for (int n = 0; n < 8; n++)
                    acc[m][n] = fmaf(ra[m], rb[n], acc[m][n]);
        }
        __syncthreads();
    }

#pragma unroll
    for (int m = 0; m < 8; m++) {
        int r = ty * 8 + m;
#pragma unroll
        for (int n = 0; n < 8; n += 4) {
            int c = tx * 8 + n;
            float4 o;
            o.x = acc[m][n + 0] + bias[c + 0];
            o.y = acc[m][n + 1] + bias[c + 1];
            o.z = acc[m][n + 2] + bias[c + 2];
            o.w = acc[m][n + 3] + bias[c + 3];
            *reinterpret_cast<float4*>(C + (size_t)r * ldc + c) = o;
        }
    }
}

__global__ __launch_bounds__(256) void blockdiag_kernel(
    const float* __restrict__ xh,
    const float* __restrict__ Wgx, const float* __restrict__ bgx,
    const float* __restrict__ Wga, const float* __restrict__ bga,
    float* __restrict__ gx, float* __restrict__ ga)
{
    const int nb = blockIdx.y;
    const int which = blockIdx.z;
    const float* W    = which ? Wga : Wgx;
    const float* bias = which ? bga : bgx;
    float*       out  = which ? ga  : gx;
    const float* Ab = xh + (size_t)blockIdx.x * BM * DHID + nb * 256;
    const float* Bb = W + (size_t)nb * 256 * 128;
    float* Cb = out + (size_t)blockIdx.x * BM * DH + nb * 128;
    sgemm_tile(Ab, DHID, Bb, 128, bias + nb * 128, Cb, DH, 256);
}

// ---------------------------------------------------------------------------
// Fused pointwise + warp-parallel complex scan.
// Grid: 128 CTAs (4 batches x 32 d-blocks), 1024 threads (32 warps).
// Warp w owns chain d = db + w; lanes are 32 consecutive s-steps per tile.
// Inclusive warp scan via shfl (combine = complex affine composition).
// Output h written directly as split hi/lo bf16 for GEMM2.
// ---------------------------------------------------------------------------
__global__ __launch_bounds__(1024) void scanfused_kernel(
    const float* __restrict__ xh,
    const float* __restrict__ gxl, const float* __restrict__ gal,
    const float* __restrict__ arp, const float* __restrict__ aip,
    __nv_bfloat16* __restrict__ hhi, __nv_bfloat16* __restrict__ hlo,
    float* __restrict__ h_last)
{
    __shared__ float sGx[32][33], sGa[32][33], sXr[32][33], sXi[32][33];
    __shared__ float sHr[32][33], sHi[32][33];

    const int b  = blockIdx.x >> 5;          // 0..3
    const int db = (blockIdx.x & 31) * 32;   // d-block base
    const int tid = threadIdx.x;
    const int w = tid >> 5;    // warp -> chain d = db + w ; also load row s
    const int j = tid & 31;    // lane -> s within tile  ; also load col d
    const int d = db + w;

    // per-warp (per-d) constants
    float av = arp[d];
    float sp = fmaxf(av, 0.f) + log1pf(expf(-fabsf(av)));   // softplus
    float aipd = aip[d];

    float cr = 0.f, ci = 0.f;   // scan carry (same in all lanes)

    for (int s0 = 0; s0 < S_SZ; s0 += 32) {
        // ---- stage inputs: thread (w=srow, j=dcol), coalesced per warp ----
        size_t grow = (size_t)(b * S_SZ + s0 + w);
        sGx[w][j] = gxl[grow * DH + db + j];
        sGa[w][j] = gal[grow * DH + db + j];
        sXr[w][j] = xh[grow * DHID + db + j];
        sXi[w][j] = xh[grow * DHID + DH + db + j];
        __syncthreads();

        // ---- pointwise (lane j = step s0+j, chain d) ----
        float gx_s = 1.f / (1.f + expf(-sGx[j][w]));
        float ga_s = 1.f / (1.f + expf(-sGa[j][w]));
        float log_a = -8.f * ga_s * sp;
        float mag = expf(log_a);
        float sn, cs;
        sincosf(aipd * ga_s, &sn, &cs);
        float ar = mag * cs;
        float ai = mag * sn;
        float nrm = sqrtf(fmaxf(1.f - mag * mag, 0.f));
        float scale = gx_s * nrm;
        float xr = scale * sXr[j][w];
        float xi = scale * sXi[j][w];

        // ---- inclusive warp scan (complex affine compose) ----
#pragma unroll
        for (int off = 1; off < 32; off <<= 1) {
            float p_ar = __shfl_up_sync(0xffffffffu, ar, off);
            float p_ai = __shfl_up_sync(0xffffffffu, ai, off);
            float p_xr = __shfl_up_sync(0xffffffffu, xr, off);
            float p_xi = __shfl_up_sync(0xffffffffu, xi, off);
            if (j >= off) {
                float nar = ar * p_ar - ai * p_ai;
                float nai = ar * p_ai + ai * p_ar;
                float nxr = ar * p_xr - ai * p_xi + xr;
                float nxi = ar * p_xi + ai * p_xr + xi;
                ar = nar; ai = nai; xr = nxr; xi = nxi;
            }
        }

        // ---- apply carry: h = A_prefix * carry + X_prefix ----
        float hr  = fmaf(ar, cr, fmaf(-ai, ci, xr));
        float hi_ = fmaf(ar, ci, fmaf(ai, cr, xi));
        cr = __shfl_sync(0xffffffffu, hr, 31);
        ci = __shfl_sync(0xffffffffu, hi_, 31);

        sHr[j][w] = hr;
        sHi[j][w] = hi_;
        __syncthreads();

        // ---- store h as split bf16 (coalesced: thread (w=srow, j=dcol)) ----
        float vr = sHr[w][j];
        float vi = sHi[w][j];
        __nv_bfloat16 hbr = __float2bfloat16(vr);
        __nv_bfloat16 hbi = __float2bfloat16(vi);
        size_t orow = grow * (size_t)DHID;
        hhi[orow + db + j] = hbr;
        hlo[orow + db + j] = __float2bfloat16(vr - __bfloat162float(hbr));
        hhi[orow + DH + db + j] = hbi;
        hlo[orow + DH + db + j] = __float2bfloat16(vi - __bfloat162float(hbi));
    }

    if (j == 0) {
        h_last[(size_t)b * DHID + d]      = cr;
        h_last[(size_t)b * DHID + DH + d] = ci;
    }
}

// ---------------------------------------------------------------------------
// Launch
// ---------------------------------------------------------------------------
extern "C" void kernel_launch(void* const* d_in, const int* in_sizes, int n_in,
                              void* d_out, int out_size)
{
    const float* x     = (const float*)d_in[0];
    const float* arp   = (const float*)d_in[1];
    const float* aip   = (const float*)d_in[2];
    const float* W_in  = (const float*)d_in[3];
    const float* b_in  = (const float*)d_in[4];
    const float* Wgx   = (const float*)d_in[5];
    const float* bgx   = (const float*)d_in[6];
    const float* Wga   = (const float*)d_in[7];
    const float* bga   = (const float*)d_in[8];
    const float* W_out = (const float*)d_in[9];
    const float* b_out = (const float*)d_in[10];

    float* y = (float*)d_out;
    float* h_last = (float*)d_out + ((size_t)out_size - (size_t)B_SZ * DHID);

    float *xh, *gx, *ga;
    __nv_bfloat16 *ahi, *alo, *whi, *wlo;
    cudaGetSymbolAddress((void**)&xh,  g_xh);
    cudaGetSymbolAddress((void**)&gx,  g_gx);
    cudaGetSymbolAddress((void**)&ga,  g_ga);
    cudaGetSymbolAddress((void**)&ahi, g_ahi);
    cudaGetSymbolAddress((void**)&alo, g_alo);
    cudaGetSymbolAddress((void**)&whi, g_whi);
    cudaGetSymbolAddress((void**)&wlo, g_wlo);

    cudaFuncSetAttribute(wmma_gemm_kernel,
                         cudaFuncAttributeMaxDynamicSharedMemorySize, SMEM_DYN);

    const size_t nx4 = (size_t)MROWS * GK / 4;
    const size_t nw4 = (size_t)GK * GK / 4;

    // 1) split x, W_in; x_h = x @ W_in + b_in (3-stage wmma)
    cvt_hilo_kernel<<<(unsigned)((nx4 + 255) / 256), 256>>>(
        (const float4*)x, (uint2*)ahi, (uint2*)alo, nx4);
    cvt_hilo_kernel<<<(unsigned)((nw4 + 255) / 256), 256>>>(
        (const float4*)W_in, (uint2*)whi, (uint2*)wlo, nw4);
    wmma_gemm_kernel<<<dim3(DHID / 128, MROWS / 128), 256, SMEM_DYN>>>(
        ahi, alo, whi, wlo, b_in, xh);

    // 2) gate linears (block-diagonal, fp32)
    blockdiag_kernel<<<dim3(MROWS / BM, NB, 2), 256>>>(xh, Wgx, bgx, Wga, bga, gx, ga);

    // 3+4) fused pointwise + warp scan; writes h directly as split bf16
    scanfused_kernel<<<B_SZ * (DH / 32), 1024>>>(
        xh, gx, ga, arp, aip, ahi, alo, h_last);

    // 5) split W_out; y = h @ W_out + b_out (3-stage wmma)
    cvt_hilo_kernel<<<(unsigned)((nw4 + 255) / 256), 256>>>(
        (const float4*)W_out, (uint2*)whi, (uint2*)wlo, nw4);
    wmma_gemm_kernel<<<dim3(DIN / 128, MROWS / 128), 256, SMEM_DYN>>>(
        ahi, alo, whi, wlo, b_out, y);
}

// round 7
// speedup vs baseline: 2.3745x; 1.0379x over previous
#include <cuda_runtime.h>
#include <cuda_bf16.h>
#include <mma.h>
#include <math.h>
#include <stdint.h>

using namespace nvcuda;

// Problem dims (fixed by the dataset)
#define NB     8
#define B_SZ   4
#define S_SZ   4096
#define DIN    2048
#define DHID   2048
#define DH     1024
#define MROWS  (B_SZ * S_SZ)   // 16384
#define GK     2048            // K (and N) for both big GEMMs

// wmma GEMM tiling: CTA 128x128, BK=64, 3-stage pipeline
#define TLDA 72     // A smem stride (elems)
#define TLDB 136    // B smem stride (elems)
#define A_T_BYTES (128 * TLDA * 2)            // 18432 per tensor
#define B_T_BYTES (64 * TLDB * 2)             // 17408 per tensor
#define STAGE_BYTES (2 * A_T_BYTES + 2 * B_T_BYTES)   // 71680
#define SMEM_DYN (3 * STAGE_BYTES)                    // 215040

#define NGW (NB * 256 * 128)   // elems per gate weight set (262144)

// ---------------------------------------------------------------------------
// Scratch (device globals -- no allocation allowed in kernel_launch)
// ---------------------------------------------------------------------------
__device__ __align__(256) float g_gx [(size_t)MROWS * DH];
__device__ __align__(256) float g_ga [(size_t)MROWS * DH];

__device__ __align__(256) __nv_bfloat16 g_xhhi[(size_t)MROWS * DHID];
__device__ __align__(256) __nv_bfloat16 g_xhlo[(size_t)MROWS * DHID];
__device__ __align__(256) __nv_bfloat16 g_ahi [(size_t)MROWS * GK];
__device__ __align__(256) __nv_bfloat16 g_alo [(size_t)MROWS * GK];
__device__ __align__(256) __nv_bfloat16 g_whi [(size_t)GK * GK];
__device__ __align__(256) __nv_bfloat16 g_wlo [(size_t)GK * GK];
__device__ __align__(256) __nv_bfloat16 g_wghi[2 * NGW];
__device__ __align__(256) __nv_bfloat16 g_wglo[2 * NGW];

// ---------------------------------------------------------------------------
// helpers
// ---------------------------------------------------------------------------
__device__ __forceinline__ void cp16(uint32_t s, const void* g) {
    asm volatile("cp.async.cg.shared.global [%0], [%1], 16;" :: "r"(s), "l"(g));
}
__device__ __forceinline__ uint32_t smem_u32(const void* p) {
    uint32_t a;
    asm("{ .reg .u64 t; cvta.to.shared.u64 t, %1; cvt.u32.u64 %0, t; }"
        : "=r"(a) : "l"(p));
    return a;
}

// ---------------------------------------------------------------------------
// fp32 -> (hi, lo) bf16 split. 4 elements per thread.
// ---------------------------------------------------------------------------
__global__ __launch_bounds__(256) void cvt_hilo_kernel(
    const float4* __restrict__ in, uint2* __restrict__ hi, uint2* __restrict__ lo,
    size_t n4)
{
    size_t i = (size_t)blockIdx.x * 256 + threadIdx.x;
    if (i >= n4) return;
    float4 v = in[i];
    __nv_bfloat16 h0 = __float2bfloat16(v.x);
    __nv_bfloat16 h1 = __float2bfloat16(v.y);
    __nv_bfloat16 h2 = __float2bfloat16(v.z);
    __nv_bfloat16 h3 = __float2bfloat16(v.w);
    __nv_bfloat16 l0 = __float2bfloat16(v.x - __bfloat162float(h0));
    __nv_bfloat16 l1 = __float2bfloat16(v.y - __bfloat162float(h1));
    __nv_bfloat16 l2 = __float2bfloat16(v.z - __bfloat162float(h2));
    __nv_bfloat16 l3 = __float2bfloat16(v.w - __bfloat162float(h3));
    __nv_bfloat162 ha = {h0, h1}, hb = {h2, h3};
    __nv_bfloat162 la = {l0, l1}, lb = {l2, l3};
    hi[i] = make_uint2(*reinterpret_cast<unsigned*>(&ha), *reinterpret_cast<unsigned*>(&hb));
    lo[i] = make_uint2(*reinterpret_cast<unsigned*>(&la), *reinterpret_cast<unsigned*>(&lb));
}

// ---------------------------------------------------------------------------
// Generic 3-stage pipelined split-bf16 wmma GEMM body (CTA tile 128x128).
// A/B/bias/C pre-offset to tile origin. 8 warps (4m x 2n), warp tile 32x64,
// 3 mma products (hi*hi + hi*lo + lo*hi), fp32 accum.
// SPLIT_OUT: write (Chi, Clo) bf16 split of (acc + bias) instead of fp32 C.
// ---------------------------------------------------------------------------
__device__ __forceinline__ void load_stage(
    const __nv_bfloat16* __restrict__ Ah, const __nv_bfloat16* __restrict__ Al,
    int lda,
    const __nv_bfloat16* __restrict__ Bh, const __nv_bfloat16* __restrict__ Bl,
    int ldb, int kt, uint32_t base, int tid)
{
#pragma unroll
    for (int i = 0; i < 4; i++) {
        int u = tid + (i << 8);      // 0..1023
        int r = u >> 3;
        int ch = u & 7;
        uint32_t so = (uint32_t)(r * (TLDA * 2) + ch * 16);
        size_t go = (size_t)r * lda + kt + ch * 8;
        cp16(base + so,             Ah + go);
        cp16(base + A_T_BYTES + so, Al + go);
    }
#pragma unroll
    for (int i = 0; i < 4; i++) {
        int u = tid + (i << 8);
        int r = u >> 4;
        int ch = u & 15;
        uint32_t so = (uint32_t)(r * (TLDB * 2) + ch * 16);
        size_t go = (size_t)(kt + r) * ldb + ch * 8;
        cp16(base + 2 * A_T_BYTES + so,             Bh + go);
        cp16(base + 2 * A_T_BYTES + B_T_BYTES + so, Bl + go);
    }
}

template<bool SPLIT_OUT>
__device__ __forceinline__ void gemm_body(
    const __nv_bfloat16* __restrict__ Ahi, const __nv_bfloat16* __restrict__ Alo,
    int lda,
    const __nv_bfloat16* __restrict__ Bhi, const __nv_bfloat16* __restrict__ Blo,
    int ldb,
    const float* __restrict__ bias,
    float* __restrict__ C,
    __nv_bfloat16* __restrict__ Chi, __nv_bfloat16* __restrict__ Clo,
    int ldc, int K)
{
    extern __shared__ __align__(256) char smem[];
    const uint32_t sb = smem_u32(smem);
    const int tid    = threadIdx.x;
    const int wid    = tid >> 5;
    const int lane   = tid & 31;
    const int warp_m = wid >> 1;   // 0..3
    const int warp_n = wid & 1;    // 0..1

    wmma::fragment<wmma::accumulator, 16, 16, 16, float> acc[2][4];
#pragma unroll
    for (int m = 0; m < 2; m++)
#pragma unroll
        for (int n = 0; n < 4; n++) wmma::fill_fragment(acc[m][n], 0.0f);

    load_stage(Ahi, Alo, lda, Bhi, Blo, ldb, 0, sb, tid);
    asm volatile("cp.async.commit_group;");
    load_stage(Ahi, Alo, lda, Bhi, Blo, ldb, 64, sb + STAGE_BYTES, tid);
    asm volatile("cp.async.commit_group;");

    const int nIter = K / 64;
    for (int it = 0; it < nIter; ++it) {
        if (it < nIter - 1) asm volatile("cp.async.wait_group 1;");
        else                asm volatile("cp.async.wait_group 0;");
        __syncthreads();
        if (it + 2 < nIter) {
            load_stage(Ahi, Alo, lda, Bhi, Blo, ldb, (it + 2) * 64,
                       sb + (uint32_t)((it + 2) % 3) * STAGE_BYTES, tid);
            asm volatile("cp.async.commit_group;");
        }

        char* stg = smem + (it % 3) * STAGE_BYTES;
        const __nv_bfloat16* As_hi = reinterpret_cast<const __nv_bfloat16*>(stg);
        const __nv_bfloat16* As_lo = reinterpret_cast<const __nv_bfloat16*>(stg + A_T_BYTES);
        const __nv_bfloat16* Bs_hi = reinterpret_cast<const __nv_bfloat16*>(stg + 2 * A_T_BYTES);
        const __nv_bfloat16* Bs_lo = reinterpret_cast<const __nv_bfloat16*>(stg + 2 * A_T_BYTES + B_T_BYTES);

#pragma unroll
        for (int kk = 0; kk < 64; kk += 16) {
            wmma::fragment<wmma::matrix_a, 16, 16, 16, __nv_bfloat16, wmma::row_major> a_hi[2], a_lo[2];
            wmma::fragment<wmma::matrix_b, 16, 16, 16, __nv_bfloat16, wmma::row_major> b_hi[4], b_lo[4];
#pragma unroll
            for (int m = 0; m < 2; m++) {
                int ar = warp_m * 32 + m * 16;
                wmma::load_matrix_sync(a_hi[m], As_hi + ar * TLDA + kk, TLDA);
                wmma::load_matrix_sync(a_lo[m], As_lo + ar * TLDA + kk, TLDA);
            }
#pragma unroll
            for (int n = 0; n < 4; n++) {
                int bc = warp_n * 64 + n * 16;
                wmma::load_matrix_sync(b_hi[n], Bs_hi + kk * TLDB + bc, TLDB);
                wmma::load_matrix_sync(b_lo[n], Bs_lo + kk * TLDB + bc, TLDB);
            }
#pragma unroll
            for (int m = 0; m < 2; m++)
#pragma unroll
                for (int n = 0; n < 4; n++) {
                    wmma::mma_sync(acc[m][n], a_hi[m], b_hi[n], acc[m][n]);
                    wmma::mma_sync(acc[m][n], a_hi[m], b_lo[n], acc[m][n]);
                    wmma::mma_sync(acc[m][n], a_lo[m], b_hi[n], acc[m][n]);
                }
        }
    }
    __syncthreads();

    // Epilogue: per-warp smem stage (16x64 fp32), exact fp32 bias add.
    float* stage = reinterpret_cast<float*>(smem);
    float* st = stage + wid * (16 * 64);
#pragma unroll
    for (int m = 0; m < 2; m++) {
#pragma unroll
        for (int n = 0; n < 4; n++)
            wmma::store_matrix_sync(st + n * 16, acc[m][n], 64, wmma::mem_row_major);
        __syncwarp();
        int r = lane >> 1;
        int cseg = (lane & 1) * 32;
        int grow = warp_m * 32 + m * 16 + r;
        int gcol = warp_n * 64 + cseg;
#pragma unroll
        for (int c = 0; c < 32; c += 4) {
            float4 v = *reinterpret_cast<float4*>(st + r * 64 + cseg + c);
            v.x += bias[gcol + c + 0];
            v.y += bias[gcol + c + 1];
            v.z += bias[gcol + c + 2];
            v.w += bias[gcol + c + 3];
            if (SPLIT_OUT) {
                __nv_bfloat16 h0 = __float2bfloat16(v.x);
                __nv_bfloat16 h1 = __float2bfloat16(v.y);
                __nv_bfloat16 h2 = __float2bfloat16(v.z);
                __nv_bfloat16 h3 = __float2bfloat16(v.w);
                __nv_bfloat162 ha = {h0, h1}, hb = {h2, h3};
                __nv_bfloat16 l0 = __float2bfloat16(v.x - __bfloat162float(h0));
                __nv_bfloat16 l1 = __float2bfloat16(v.y - __bfloat162float(h1));
                __nv_bfloat16 l2 = __float2bfloat16(v.z - __bfloat162float(h2));
                __nv_bfloat16 l3 = __float2bfloat16(v.w - __bfloat162float(h3));
                __nv_bfloat162 la = {l0, l1}, lb = {l2, l3};
                uint2 uh = make_uint2(*reinterpret_cast<unsigned*>(&ha),
                                      *reinterpret_cast<unsigned*>(&hb));
                uint2 ul = make_uint2(*reinterpret_cast<unsigned*>(&la),
                                      *reinterpret_cast<unsigned*>(&lb));
                *reinterpret_cast<uint2*>(Chi + (size_t)grow * ldc + gcol + c) = uh;
                *reinterpret_cast<uint2*>(Clo + (size_t)grow * ldc + gcol + c) = ul;
            } else {
                *reinterpret_cast<float4*>(C + (size_t)grow * ldc + gcol + c) = v;
            }
        }
        __syncwarp();
    }
}

// Big GEMM, fp32 output (GEMM2: y = h @ W_out + b_out)
__global__ __launch_bounds__(256, 1) void gemm_f32out_kernel(
    const __nv_bfloat16* __restrict__ Ahi, const __nv_bfloat16* __restrict__ Alo,
    const __nv_bfloat16* __restrict__ Bhi, const __nv_bfloat16* __restrict__ Blo,
    const float* __restrict__ bias, float* __restrict__ C)
{
    const int row0 = blockIdx.y * 128;
    const int bn   = blockIdx.x * 128;
    gemm_body<false>(Ahi + (size_t)row0 * GK, Alo + (size_t)row0 * GK, GK,
                     Bhi + bn, Blo + bn, GK,
                     bias + bn,
                     C + (size_t)row0 * GK + bn, nullptr, nullptr, GK, GK);
}

// Big GEMM, split-bf16 output (GEMM1: xh = x @ W_in + b_in -> hi/lo)
__global__ __launch_bounds__(256, 1) void gemm_splitout_kernel(
    const __nv_bfloat16* __restrict__ Ahi, const __nv_bfloat16* __restrict__ Alo,
    const __nv_bfloat16* __restrict__ Bhi, const __nv_bfloat16* __restrict__ Blo,
    const float* __restrict__ bias,
    __nv_bfloat16* __restrict__ Chi, __nv_bfloat16* __restrict__ Clo)
{
    const int row0 = blockIdx.y * 128;
    const int bn   = blockIdx.x * 128;
    gemm_body<true>(Ahi + (size_t)row0 * GK, Alo + (size_t)row0 * GK, GK,
                    Bhi + bn, Blo + bn, GK,
                    bias + bn, nullptr,
                    Chi + (size_t)row0 * GK + bn,
                    Clo + (size_t)row0 * GK + bn, GK, GK);
}

// Block-diagonal gate GEMMs via wmma: per (mtile, nb, which):
//   [128 x 256] @ [256 x 128] + bias
__global__ __launch_bounds__(256, 1) void blockdiag_wmma_kernel(
    const __nv_bfloat16* __restrict__ xhhi, const __nv_bfloat16* __restrict__ xhlo,
    const __nv_bfloat16* __restrict__ wghi, const __nv_bfloat16* __restrict__ wglo,
    const float* __restrict__ bgx, const float* __restrict__ bga,
    float* __restrict__ gx, float* __restrict__ ga)
{
    const int mt    = blockIdx.x;   // 0..127
    const int nb    = blockIdx.y;   // 0..7
    const int which = blockIdx.z;   // 0: gate_x, 1: gate_a
    const float* bias = (which ? bga : bgx) + nb * 128;
    float* out = (which ? ga : gx) + (size_t)mt * 128 * DH + nb * 128;
    size_t aoff = (size_t)mt * 128 * DHID + nb * 256;
    size_t boff = (size_t)which * NGW + (size_t)nb * 256 * 128;
    gemm_body<false>(xhhi + aoff, xhlo + aoff, DHID,
                     wghi + boff, wglo + boff, 128,
                     bias, out, nullptr, nullptr, DH, 256);
}

// ---------------------------------------------------------------------------
// Fused pointwise + warp-parallel complex scan.
// Grid: 128 CTAs (4 batches x 32 d-blocks), 1024 threads (32 warps).
// Warp w owns chain d = db + w; lanes are 32 consecutive s-steps per tile.
// Output h written directly as split hi/lo bf16 for GEMM2.
// ---------------------------------------------------------------------------
__global__ __launch_bounds__(1024) void scanfused_kernel(
    const __nv_bfloat16* __restrict__ xhhi, const __nv_bfloat16* __restrict__ xhlo,
    const float* __restrict__ gxl, const float* __restrict__ gal,
    const float* __restrict__ arp, const float* __restrict__ aip,
    __nv_bfloat16* __restrict__ hhi, __nv_bfloat16* __restrict__ hlo,
    float* __restrict__ h_last)
{
    __shared__ float sGx[32][33], sGa[32][33], sXr[32][33], sXi[32][33];
    __shared__ float sHr[32][33], sHi[32][33];

    const int b  = blockIdx.x >> 5;          // 0..3
    const int db = (blockIdx.x & 31) * 32;   // d-block base
    const int tid = threadIdx.x;
    const int w = tid >> 5;    // warp -> chain d = db + w ; also load row s
    const int j = tid & 31;    // lane -> s within tile  ; also load col d
    const int d = db + w;

    float av = arp[d];
    float sp = fmaxf(av, 0.f) + log1pf(expf(-fabsf(av)));   // softplus
    float aipd = aip[d];

    float cr = 0.f, ci = 0.f;   // scan carry

    for (int s0 = 0; s0 < S_SZ; s0 += 32) {
        size_t grow = (size_t)(b * S_SZ + s0 + w);
        sGx[w][j] = gxl[grow * DH + db + j];
        sGa[w][j] = gal[grow * DH + db + j];
        size_t xb = grow * DHID + db + j;
        sXr[w][j] = __bfloat162float(xhhi[xb]) + __bfloat162float(xhlo[xb]);
        sXi[w][j] = __bfloat162float(xhhi[xb + DH]) + __bfloat162float(xhlo[xb + DH]);
        __syncthreads();

        float gx_s = 1.f / (1.f + expf(-sGx[j][w]));
        float ga_s = 1.f / (1.f + expf(-sGa[j][w]));
        float log_a = -8.f * ga_s * sp;
        float mag = expf(log_a);
        float sn, cs;
        sincosf(aipd * ga_s, &sn, &cs);
        float ar = mag * cs;
        float ai = mag * sn;
        float nrm = sqrtf(fmaxf(1.f - mag * mag, 0.f));
        float scale = gx_s * nrm;
        float xr = scale * sXr[j][w];
        float xi = scale * sXi[j][w];

#pragma unroll
        for (int off = 1; off < 32; off <<= 1) {
            float p_ar = __shfl_up_sync(0xffffffffu, ar, off);
            float p_ai = __shfl_up_sync(0xffffffffu, ai, off);
            float p_xr = __shfl_up_sync(0xffffffffu, xr, off);
            float p_xi = __shfl_up_sync(0xffffffffu, xi, off);
            if (j >= off) {
                float nar = ar * p_ar - ai * p_ai;
                float nai = ar * p_ai + ai * p_ar;
                float nxr = ar * p_xr - ai * p_xi + xr;
                float nxi = ar * p_xi + ai * p_xr + xi;
                ar = nar; ai = nai; xr = nxr; xi = nxi;
            }
        }

        float hr  = fmaf(ar, cr, fmaf(-ai, ci, xr));
        float hi_ = fmaf(ar, ci, fmaf(ai, cr, xi));
        cr = __shfl_sync(0xffffffffu, hr, 31);
        ci = __shfl_sync(0xffffffffu, hi_, 31);

        sHr[j][w] = hr;
        sHi[j][w] = hi_;
        __syncthreads();

        float vr = sHr[w][j];
        float vi = sHi[w][j];
        __nv_bfloat16 hbr = __float2bfloat16(vr);
        __nv_bfloat16 hbi = __float2bfloat16(vi);
        size_t orow = grow * (size_t)DHID;
        hhi[orow + db + j] = hbr;
        hlo[orow + db + j] = __float2bfloat16(vr - __bfloat162float(hbr));
        hhi[orow + DH + db + j] = hbi;
        hlo[orow + DH + db + j] = __float2bfloat16(vi - __bfloat162float(hbi));
    }

    if (j == 0) {
        h_last[(size_t)b * DHID + d]      = cr;
        h_last[(size_t)b * DHID + DH + d] = ci;
    }
}

// ---------------------------------------------------------------------------
// Launch
// ---------------------------------------------------------------------------
extern "C" void kernel_launch(void* const* d_in, const int* in_sizes, int n_in,
                              void* d_out, int out_size)
{
    const float* x     = (const float*)d_in[0];
    const float* arp   = (const float*)d_in[1];
    const float* aip   = (const float*)d_in[2];
    const float* W_in  = (const float*)d_in[3];
    const float* b_in  = (const float*)d_in[4];
    const float* Wgx   = (const float*)d_in[5];
    const float* bgx   = (const float*)d_in[6];
    const float* Wga   = (const float*)d_in[7];
    const float* bga   = (const float*)d_in[8];
    const float* W_out = (const float*)d_in[9];
    const float* b_out = (const float*)d_in[10];

    float* y = (float*)d_out;
    float* h_last = (float*)d_out + ((size_t)out_size - (size_t)B_SZ * DHID);

    float *gx, *ga;
    __nv_bfloat16 *xhhi, *xhlo, *ahi, *alo, *whi, *wlo, *wghi, *wglo;
    cudaGetSymbolAddress((void**)&gx,   g_gx);
    cudaGetSymbolAddress((void**)&ga,   g_ga);
    cudaGetSymbolAddress((void**)&xhhi, g_xhhi);
    cudaGetSymbolAddress((void**)&xhlo, g_xhlo);
    cudaGetSymbolAddress((void**)&ahi,  g_ahi);
    cudaGetSymbolAddress((void**)&alo,  g_alo);
    cudaGetSymbolAddress((void**)&whi,  g_whi);
    cudaGetSymbolAddress((void**)&wlo,  g_wlo);
    cudaGetSymbolAddress((void**)&wghi, g_wghi);
    cudaGetSymbolAddress((void**)&wglo, g_wglo);

    cudaFuncSetAttribute(gemm_f32out_kernel,
                         cudaFuncAttributeMaxDynamicSharedMemorySize, SMEM_DYN);
    cudaFuncSetAttribute(gemm_splitout_kernel,
                         cudaFuncAttributeMaxDynamicSharedMemorySize, SMEM_DYN);
    cudaFuncSetAttribute(blockdiag_wmma_kernel,
                         cudaFuncAttributeMaxDynamicSharedMemorySize, SMEM_DYN);

    const size_t nx4 = (size_t)MROWS * GK / 4;
    const size_t nw4 = (size_t)GK * GK / 4;
    const size_t ng4 = (size_t)NGW / 4;

    // 0) input splits
    cvt_hilo_kernel<<<(unsigned)((nx4 + 255) / 256), 256>>>(
        (const float4*)x, (uint2*)ahi, (uint2*)alo, nx4);
    cvt_hilo_kernel<<<(unsigned)((nw4 + 255) / 256), 256>>>(
        (const float4*)W_in, (uint2*)whi, (uint2*)wlo, nw4);
    cvt_hilo_kernel<<<(unsigned)((ng4 + 255) / 256), 256>>>(
        (const float4*)Wgx, (uint2*)wghi, (uint2*)wglo, ng4);
    cvt_hilo_kernel<<<(unsigned)((ng4 + 255) / 256), 256>>>(
        (const float4*)Wga, (uint2*)(wghi + NGW), (uint2*)(wglo + NGW), ng4);

    // 1) xh = x @ W_in + b_in  -> split bf16 (hi/lo) directly
    gemm_splitout_kernel<<<dim3(DHID / 128, MROWS / 128), 256, SMEM_DYN>>>(
        ahi, alo, whi, wlo, b_in, xhhi, xhlo);

    // 2) gate linears (block-diagonal, split-bf16 wmma)
    blockdiag_wmma_kernel<<<dim3(MROWS / 128, NB, 2), 256, SMEM_DYN>>>(
        xhhi, xhlo, wghi, wglo, bgx, bga, gx, ga);

    // 3+4) fused pointwise + warp scan; writes h as split bf16 into ahi/alo
    scanfused_kernel<<<B_SZ * (DH / 32), 1024>>>(
        xhhi, xhlo, gx, ga, arp, aip, ahi, alo, h_last);

    // 5) y = h @ W_out + b_out
    cvt_hilo_kernel<<<(unsigned)((nw4 + 255) / 256), 256>>>(
        (const float4*)W_out, (uint2*)whi, (uint2*)wlo, nw4);
    gemm_f32out_kernel<<<dim3(DIN / 128, MROWS / 128), 256, SMEM_DYN>>>(
        ahi, alo, whi, wlo, b_out, y);
}

// round 8
// speedup vs baseline: 3.8427x; 1.6183x over previous
#include <cuda_runtime.h>
#include <cuda_fp16.h>
#include <mma.h>
#include <math.h>
#include <stdint.h>

using namespace nvcuda;

// Problem dims (fixed by the dataset)
#define NB     8
#define B_SZ   4
#define S_SZ   4096
#define DIN    2048
#define DHID   2048
#define DH     1024
#define MROWS  (B_SZ * S_SZ)   // 16384
#define GK     2048            // K (and N) for both big GEMMs

// wmma GEMM tiling: CTA 128x128, BK=64, 3-stage pipeline, fp16 split
#define TLDA 72     // A smem stride (halves): 144B
#define TLDB 136    // B smem stride (halves): 272B
#define A_T_BYTES (128 * TLDA * 2)            // 18432 per tensor
#define B_T_BYTES (64 * TLDB * 2)             // 17408 per tensor
#define STAGE_BYTES (2 * A_T_BYTES + 2 * B_T_BYTES)   // 71680
#define SMEM_DYN (3 * STAGE_BYTES)                    // 215040

#define NGW (NB * 256 * 128)   // elems per gate weight set (262144)

// ---------------------------------------------------------------------------
// Scratch (device globals -- no allocation allowed in kernel_launch)
// ---------------------------------------------------------------------------
__device__ __align__(256) float g_gx [(size_t)MROWS * DH];
__device__ __align__(256) float g_ga [(size_t)MROWS * DH];

__device__ __align__(256) __half g_xsp [(size_t)MROWS * DIN];   // x hi
__device__ __align__(256) __half g_h   [(size_t)MROWS * DHID];  // h hi
__device__ __align__(256) __half g_xhhi[(size_t)MROWS * DHID];
__device__ __align__(256) __half g_xhlo[(size_t)MROWS * DHID];
__device__ __align__(256) __half g_whi [(size_t)GK * GK];
__device__ __align__(256) __half g_wlo [(size_t)GK * GK];
__device__ __align__(256) __half g_wghi[2 * NGW];
__device__ __align__(256) __half g_wglo[2 * NGW];

// ---------------------------------------------------------------------------
// helpers
// ---------------------------------------------------------------------------
__device__ __forceinline__ void cp16(uint32_t s, const void* g) {
    asm volatile("cp.async.cg.shared.global [%0], [%1], 16;" :: "r"(s), "l"(g));
}
__device__ __forceinline__ uint32_t smem_u32(const void* p) {
    uint32_t a;
    asm("{ .reg .u64 t; cvta.to.shared.u64 t, %1; cvt.u32.u64 %0, t; }"
        : "=r"(a) : "l"(p));
    return a;
}
__device__ __forceinline__ uint32_t pack4h(__half a, __half b) {
    __half2 h2 = {a, b};
    return *reinterpret_cast<unsigned*>(&h2);
}

// ---------------------------------------------------------------------------
// fp32 -> fp16 hi (+ lo) split converters. 4 elements per thread.
// ---------------------------------------------------------------------------
__global__ __launch_bounds__(256) void cvt_hilo16_kernel(
    const float4* __restrict__ in, uint2* __restrict__ hi, uint2* __restrict__ lo,
    size_t n4)
{
    size_t i = (size_t)blockIdx.x * 256 + threadIdx.x;
    if (i >= n4) return;
    float4 v = in[i];
    __half h0 = __float2half_rn(v.x), h1 = __float2half_rn(v.y);
    __half h2 = __float2half_rn(v.z), h3 = __float2half_rn(v.w);
    __half l0 = __float2half_rn(v.x - __half2float(h0));
    __half l1 = __float2half_rn(v.y - __half2float(h1));
    __half l2 = __float2half_rn(v.z - __half2float(h2));
    __half l3 = __float2half_rn(v.w - __half2float(h3));
    hi[i] = make_uint2(pack4h(h0, h1), pack4h(h2, h3));
    lo[i] = make_uint2(pack4h(l0, l1), pack4h(l2, l3));
}

__global__ __launch_bounds__(256) void cvt_hi16_kernel(
    const float4* __restrict__ in, uint2* __restrict__ hi, size_t n4)
{
    size_t i = (size_t)blockIdx.x * 256 + threadIdx.x;
    if (i >= n4) return;
    float4 v = in[i];
    hi[i] = make_uint2(pack4h(__float2half_rn(v.x), __float2half_rn(v.y)),
                       pack4h(__float2half_rn(v.z), __float2half_rn(v.w)));
}

// ---------------------------------------------------------------------------
// Generic 3-stage pipelined split-fp16 wmma GEMM body (CTA tile 128x128).
// 8 warps (2m x 4n), warp tile 64x32, fp32 accum.
// Products: Ahi*Bhi + Ahi*Blo (+ Alo*Bhi when A_LO).
// SPLIT_OUT: write (Chi, Clo) fp16 split of (acc + bias) instead of fp32 C.
// ---------------------------------------------------------------------------
template<bool A_LO>
__device__ __forceinline__ void load_stage(
    const __half* __restrict__ Ah, const __half* __restrict__ Al, int lda,
    const __half* __restrict__ Bh, const __half* __restrict__ Bl, int ldb,
    int kt, uint32_t base, int tid)
{
#pragma unroll
    for (int i = 0; i < 4; i++) {
        int u = tid + (i << 8);      // 0..1023
        int r = u >> 3;
        int ch = u & 7;
        uint32_t so = (uint32_t)(r * (TLDA * 2) + ch * 16);
        size_t go = (size_t)r * lda + kt + ch * 8;
        cp16(base + so, Ah + go);
        if (A_LO) cp16(base + A_T_BYTES + so, Al + go);
    }
#pragma unroll
    for (int i = 0; i < 4; i++) {
        int u = tid + (i << 8);
        int r = u >> 4;
        int ch = u & 15;
        uint32_t so = (uint32_t)(r * (TLDB * 2) + ch * 16);
        size_t go = (size_t)(kt + r) * ldb + ch * 8;
        cp16(base + 2 * A_T_BYTES + so,             Bh + go);
        cp16(base + 2 * A_T_BYTES + B_T_BYTES + so, Bl + go);
    }
}

template<bool A_LO, bool SPLIT_OUT>
__device__ __forceinline__ void gemm_body(
    const __half* __restrict__ Ahi, const __half* __restrict__ Alo, int lda,
    const __half* __restrict__ Bhi, const __half* __restrict__ Blo, int ldb,
    const float* __restrict__ bias,
    float* __restrict__ C,
    __half* __restrict__ Chi, __half* __restrict__ Clo,
    int ldc, int K)
{
    extern __shared__ __align__(256) char smem[];
    const uint32_t sb = smem_u32(smem);
    const int tid    = threadIdx.x;
    const int wid    = tid >> 5;
    const int lane   = tid & 31;
    const int warp_m = wid >> 2;   // 0..1  (64-row slab)
    const int warp_n = wid & 3;    // 0..3  (32-col slab)

    wmma::fragment<wmma::accumulator, 16, 16, 16, float> acc[4][2];
#pragma unroll
    for (int m = 0; m < 4; m++)
#pragma unroll
        for (int n = 0; n < 2; n++) wmma::fill_fragment(acc[m][n], 0.0f);

    load_stage<A_LO>(Ahi, Alo, lda, Bhi, Blo, ldb, 0, sb, tid);
    asm volatile("cp.async.commit_group;");
    load_stage<A_LO>(Ahi, Alo, lda, Bhi, Blo, ldb, 64, sb + STAGE_BYTES, tid);
    asm volatile("cp.async.commit_group;");

    const int nIter = K / 64;
    for (int it = 0; it < nIter; ++it) {
        if (it < nIter - 1) asm volatile("cp.async.wait_group 1;");
        else                asm volatile("cp.async.wait_group 0;");
        __syncthreads();
        if (it + 2 < nIter) {
            load_stage<A_LO>(Ahi, Alo, lda, Bhi, Blo, ldb, (it + 2) * 64,
                             sb + (uint32_t)((it + 2) % 3) * STAGE_BYTES, tid);
            asm volatile("cp.async.commit_group;");
        }

        char* stg = smem + (it % 3) * STAGE_BYTES;
        const __half* As_hi = reinterpret_cast<const __half*>(stg);
        const __half* As_lo = reinterpret_cast<const __half*>(stg + A_T_BYTES);
        const __half* Bs_hi = reinterpret_cast<const __half*>(stg + 2 * A_T_BYTES);
        const __half* Bs_lo = reinterpret_cast<const __half*>(stg + 2 * A_T_BYTES + B_T_BYTES);

#pragma unroll
        for (int kk = 0; kk < 64; kk += 16) {
            wmma::fragment<wmma::matrix_a, 16, 16, 16, __half, wmma::row_major> a_hi[4], a_lo[4];
            wmma::fragment<wmma::matrix_b, 16, 16, 16, __half, wmma::row_major> b_hi[2], b_lo[2];
#pragma unroll
            for (int m = 0; m < 4; m++) {
                int ar = warp_m * 64 + m * 16;
                wmma::load_matrix_sync(a_hi[m], As_hi + ar * TLDA + kk, TLDA);
                if (A_LO) wmma::load_matrix_sync(a_lo[m], As_lo + ar * TLDA + kk, TLDA);
            }
#pragma unroll
            for (int n = 0; n < 2; n++) {
                int bc = warp_n * 32 + n * 16;
                wmma::load_matrix_sync(b_hi[n], Bs_hi + kk * TLDB + bc, TLDB);
                wmma::load_matrix_sync(b_lo[n], Bs_lo + kk * TLDB + bc, TLDB);
            }
#pragma unroll
            for (int m = 0; m < 4; m++)
#pragma unroll
                for (int n = 0; n < 2; n++) {
                    wmma::mma_sync(acc[m][n], a_hi[m], b_hi[n], acc[m][n]);
                    wmma::mma_sync(acc[m][n], a_hi[m], b_lo[n], acc[m][n]);
                    if (A_LO) wmma::mma_sync(acc[m][n], a_lo[m], b_hi[n], acc[m][n]);
                }
        }
    }
    __syncthreads();

    // Epilogue: per-warp smem stage (16x32 fp32 per m-frag), exact fp32 bias.
    float* st = reinterpret_cast<float*>(smem) + wid * (16 * 32);
#pragma unroll
    for (int m = 0; m < 4; m++) {
        wmma::store_matrix_sync(st,      acc[m][0], 32, wmma::mem_row_major);
        wmma::store_matrix_sync(st + 16, acc[m][1], 32, wmma::mem_row_major);
        __syncwarp();
        int r  = lane >> 1;
        int cs = (lane & 1) * 16;
        int grow = warp_m * 64 + m * 16 + r;
        int gcol = warp_n * 32 + cs;
#pragma unroll
        for (int c = 0; c < 16; c += 4) {
            float4 v = *reinterpret_cast<float4*>(st + r * 32 + cs + c);
            v.x += bias[gcol + c + 0];
            v.y += bias[gcol + c + 1];
            v.z += bias[gcol + c + 2];
            v.w += bias[gcol + c + 3];
            if (SPLIT_OUT) {
                __half h0 = __float2half_rn(v.x), h1 = __float2half_rn(v.y);
                __half h2 = __float2half_rn(v.z), h3 = __float2half_rn(v.w);
                __half l0 = __float2half_rn(v.x - __half2float(h0));
                __half l1 = __float2half_rn(v.y - __half2float(h1));
                __half l2 = __float2half_rn(v.z - __half2float(h2));
                __half l3 = __float2half_rn(v.w - __half2float(h3));
                *reinterpret_cast<uint2*>(Chi + (size_t)grow * ldc + gcol + c) =
                    make_uint2(pack4h(h0, h1), pack4h(h2, h3));
                *reinterpret_cast<uint2*>(Clo + (size_t)grow * ldc + gcol + c) =
                    make_uint2(pack4h(l0, l1), pack4h(l2, l3));
            } else {
                *reinterpret_cast<float4*>(C + (size_t)grow * ldc + gcol + c) = v;
            }
        }
        __syncwarp();
    }
}

// GEMM2: y = h @ W_out + b_out (A = h hi-only, fp32 out)
__global__ __launch_bounds__(256, 1) void gemm_f32out_kernel(
    const __half* __restrict__ Ahi,
    const __half* __restrict__ Bhi, const __half* __restrict__ Blo,
    const float* __restrict__ bias, float* __restrict__ C)
{
    const int row0 = blockIdx.y * 128;
    const int bn   = blockIdx.x * 128;
    gemm_body<false, false>(Ahi + (size_t)row0 * GK, nullptr, GK,
                            Bhi + bn, Blo + bn, GK,
                            bias + bn,
                            C + (size_t)row0 * GK + bn, nullptr, nullptr, GK, GK);
}

// GEMM1: xh = x @ W_in + b_in (A = x hi-only, split fp16 hi/lo out)
__global__ __launch_bounds__(256, 1) void gemm_splitout_kernel(
    const __half* __restrict__ Ahi,
    const __half* __restrict__ Bhi, const __half* __restrict__ Blo,
    const float* __restrict__ bias,
    __half* __restrict__ Chi, __half* __restrict__ Clo)
{
    const int row0 = blockIdx.y * 128;
    const int bn   = blockIdx.x * 128;
    gemm_body<false, true>(Ahi + (size_t)row0 * GK, nullptr, GK,
                           Bhi + bn, Blo + bn, GK,
                           bias + bn, nullptr,
                           Chi + (size_t)row0 * GK + bn,
                           Clo + (size_t)row0 * GK + bn, GK, GK);
}

// Block-diagonal gate GEMMs (full 3-product fp16): [128 x 256] @ [256 x 128]
__global__ __launch_bounds__(256, 1) void blockdiag_wmma_kernel(
    const __half* __restrict__ xhhi, const __half* __restrict__ xhlo,
    const __half* __restrict__ wghi, const __half* __restrict__ wglo,
    const float* __restrict__ bgx, const float* __restrict__ bga,
    float* __restrict__ gx, float* __restrict__ ga)
{
    const int mt    = blockIdx.x;   // 0..127
    const int nb    = blockIdx.y;   // 0..7
    const int which = blockIdx.z;   // 0: gate_x, 1: gate_a
    const float* bias = (which ? bga : bgx) + nb * 128;
    float* out = (which ? ga : gx) + (size_t)mt * 128 * DH + nb * 128;
    size_t aoff = (size_t)mt * 128 * DHID + nb * 256;
    size_t boff = (size_t)which * NGW + (size_t)nb * 256 * 128;
    gemm_body<true, false>(xhhi + aoff, xhlo + aoff, DHID,
                           wghi + boff, wglo + boff, 128,
                           bias, out, nullptr, nullptr, DH, 256);
}

// ---------------------------------------------------------------------------
// Fused pointwise + warp-parallel complex scan.
// Grid: 128 CTAs (4 batches x 32 d-blocks), 1024 threads (32 warps).
// Output h written as fp16 hi only (GEMM2 drops A_lo anyway).
// ---------------------------------------------------------------------------
__global__ __launch_bounds__(1024) void scanfused_kernel(
    const __half* __restrict__ xhhi, const __half* __restrict__ xhlo,
    const float* __restrict__ gxl, const float* __restrict__ gal,
    const float* __restrict__ arp, const float* __restrict__ aip,
    __half* __restrict__ hout, float* __restrict__ h_last)
{
    __shared__ float sGx[32][33], sGa[32][33], sXr[32][33], sXi[32][33];
    __shared__ float sHr[32][33], sHi[32][33];

    const int b  = blockIdx.x >> 5;          // 0..3
    const int db = (blockIdx.x & 31) * 32;   // d-block base
    const int tid = threadIdx.x;
    const int w = tid >> 5;    // warp -> chain d = db + w ; also load row s
    const int j = tid & 31;    // lane -> s within tile  ; also load col d
    const int d = db + w;

    float av = arp[d];
    float sp = fmaxf(av, 0.f) + log1pf(expf(-fabsf(av)));   // softplus
    float aipd = aip[d];

    float cr = 0.f, ci = 0.f;   // scan carry

    for (int s0 = 0; s0 < S_SZ; s0 += 32) {
        size_t grow = (size_t)(b * S_SZ + s0 + w);
        sGx[w][j] = gxl[grow * DH + db + j];
        sGa[w][j] = gal[grow * DH + db + j];
        size_t xb = grow * DHID + db + j;
        sXr[w][j] = __half2float(xhhi[xb]) + __half2float(xhlo[xb]);
        sXi[w][j] = __half2float(xhhi[xb + DH]) + __half2float(xhlo[xb + DH]);
        __syncthreads();

        float gx_s = 1.f / (1.f + expf(-sGx[j][w]));
        float ga_s = 1.f / (1.f + expf(-sGa[j][w]));
        float log_a = -8.f * ga_s * sp;
        float mag = expf(log_a);
        float sn, cs;
        sincosf(aipd * ga_s, &sn, &cs);
        float ar = mag * cs;
        float ai = mag * sn;
        float nrm = sqrtf(fmaxf(1.f - mag * mag, 0.f));
        float scale = gx_s * nrm;
        float xr = scale * sXr[j][w];
        float xi = scale * sXi[j][w];

#pragma unroll
        for (int off = 1; off < 32; off <<= 1) {
            float p_ar = __shfl_up_sync(0xffffffffu, ar, off);
            float p_ai = __shfl_up_sync(0xffffffffu, ai, off);
            float p_xr = __shfl_up_sync(0xffffffffu, xr, off);
            float p_xi = __shfl_up_sync(0xffffffffu, xi, off);
            if (j >= off) {
                float nar = ar * p_ar - ai * p_ai;
                float nai = ar * p_ai + ai * p_ar;
                float nxr = ar * p_xr - ai * p_xi + xr;
                float nxi = ar * p_xi + ai * p_xr + xi;
                ar = nar; ai = nai; xr = nxr; xi = nxi;
            }
        }

        float hr  = fmaf(ar, cr, fmaf(-ai, ci, xr));
        float hi_ = fmaf(ar, ci, fmaf(ai, cr, xi));
        cr = __shfl_sync(0xffffffffu, hr, 31);
        ci = __shfl_sync(0xffffffffu, hi_, 31);

        sHr[j][w] = hr;
        sHi[j][w] = hi_;
        __syncthreads();

        size_t orow = grow * (size_t)DHID;
        hout[orow + db + j]      = __float2half_rn(sHr[w][j]);
        hout[orow + DH + db + j] = __float2half_rn(sHi[w][j]);
    }

    if (j == 0) {
        h_last[(size_t)b * DHID + d]      = cr;
        h_last[(size_t)b * DHID + DH + d] = ci;
    }
}

// ---------------------------------------------------------------------------
// Launch
// ---------------------------------------------------------------------------
extern "C" void kernel_launch(void* const* d_in, const int* in_sizes, int n_in,
                              void* d_out, int out_size)
{
    const float* x     = (const float*)d_in[0];
    const float* arp   = (const float*)d_in[1];
    const float* aip   = (const float*)d_in[2];
    const float* W_in  = (const float*)d_in[3];
    const float* b_in  = (const float*)d_in[4];
    const float* Wgx   = (const float*)d_in[5];
    const float* bgx   = (const float*)d_in[6];
    const float* Wga   = (const float*)d_in[7];
    const float* bga   = (const float*)d_in[8];
    const float* W_out = (const float*)d_in[9];
    const float* b_out = (const float*)d_in[10];

    float* y = (float*)d_out;
    float* h_last = (float*)d_out + ((size_t)out_size - (size_t)B_SZ * DHID);

    float *gx, *ga;
    __half *xsp, *h, *xhhi, *xhlo, *whi, *wlo, *wghi, *wglo;
    cudaGetSymbolAddress((void**)&gx,   g_gx);
    cudaGetSymbolAddress((void**)&ga,   g_ga);
    cudaGetSymbolAddress((void**)&xsp,  g_xsp);
    cudaGetSymbolAddress((void**)&h,    g_h);
    cudaGetSymbolAddress((void**)&xhhi, g_xhhi);
    cudaGetSymbolAddress((void**)&xhlo, g_xhlo);
    cudaGetSymbolAddress((void**)&whi,  g_whi);
    cudaGetSymbolAddress((void**)&wlo,  g_wlo);
    cudaGetSymbolAddress((void**)&wghi, g_wghi);
    cudaGetSymbolAddress((void**)&wglo, g_wglo);

    cudaFuncSetAttribute(gemm_f32out_kernel,
                         cudaFuncAttributeMaxDynamicSharedMemorySize, SMEM_DYN);
    cudaFuncSetAttribute(gemm_splitout_kernel,
                         cudaFuncAttributeMaxDynamicSharedMemorySize, SMEM_DYN);
    cudaFuncSetAttribute(blockdiag_wmma_kernel,
                         cudaFuncAttributeMaxDynamicSharedMemorySize, SMEM_DYN);

    const size_t nx4 = (size_t)MROWS * GK / 4;
    const size_t nw4 = (size_t)GK * GK / 4;
    const size_t ng4 = (size_t)NGW / 4;

    // 0) input splits: x -> hi only; weights -> hi+lo
    cvt_hi16_kernel<<<(unsigned)((nx4 + 255) / 256), 256>>>(
        (const float4*)x, (uint2*)xsp, nx4);
    cvt_hilo16_kernel<<<(unsigned)((nw4 + 255) / 256), 256>>>(
        (const float4*)W_in, (uint2*)whi, (uint2*)wlo, nw4);
    cvt_hilo16_kernel<<<(unsigned)((ng4 + 255) / 256), 256>>>(
        (const float4*)Wgx, (uint2*)wghi, (uint2*)wglo, ng4);
    cvt_hilo16_kernel<<<(unsigned)((ng4 + 255) / 256), 256>>>(
        (const float4*)Wga, (uint2*)(wghi + NGW), (uint2*)(wglo + NGW), ng4);

    // 1) xh = x @ W_in + b_in  (2-product) -> split fp16 hi/lo
    gemm_splitout_kernel<<<dim3(DHID / 128, MROWS / 128), 256, SMEM_DYN>>>(
        xsp, whi, wlo, b_in, xhhi, xhlo);

    // 2) gate linears (block-diagonal, 3-product fp16)
    blockdiag_wmma_kernel<<<dim3(MROWS / 128, NB, 2), 256, SMEM_DYN>>>(
        xhhi, xhlo, wghi, wglo, bgx, bga, gx, ga);

    // 3+4) fused pointwise + warp scan; writes h as fp16 hi
    scanfused_kernel<<<B_SZ * (DH / 32), 1024>>>(
        xhhi, xhlo, gx, ga, arp, aip, h, h_last);

    // 5) y = h @ W_out + b_out (2-product)
    cvt_hilo16_kernel<<<(unsigned)((nw4 + 255) / 256), 256>>>(
        (const float4*)W_out, (uint2*)whi, (uint2*)wlo, nw4);
    gemm_f32out_kernel<<<dim3(DIN / 128, MROWS / 128), 256, SMEM_DYN>>>(
        h, whi, wlo, b_out, y);
}

// round 9
// speedup vs baseline: 5.4766x; 1.4252x over previous
#include <cuda_runtime.h>
#include <cuda_fp16.h>
#include <mma.h>
#include <math.h>
#include <stdint.h>

using namespace nvcuda;

// Problem dims (fixed by the dataset)
#define NB     8
#define B_SZ   4
#define S_SZ   4096
#define DIN    2048
#define DHID   2048
#define DH     1024
#define MROWS  (B_SZ * S_SZ)   // 16384
#define GK     2048            // K (and N) for both big GEMMs

// wmma GEMM tiling: CTA 128x128, BK=64
#define TLDA 72     // A smem stride (halves): 144B
#define TLDB 136    // B smem stride (halves): 272B
#define A_T_BYTES (128 * TLDA * 2)            // 18432 per tensor
#define B_T_BYTES (64 * TLDB * 2)             // 17408 per tensor

// stage sizes: big GEMM (hi-only A and B), blockdiag (A hi+lo, B hi+lo)
#define STAGE_BIG (A_T_BYTES + B_T_BYTES)             // 35840
#define STAGE_BD  (2 * A_T_BYTES + 2 * B_T_BYTES)     // 71680
#define SMEM_BIG  (4 * STAGE_BIG)                     // 143360
#define SMEM_BD   (3 * STAGE_BD)                      // 215040

#define NGW (NB * 256 * 128)   // elems per gate weight set (262144)

// ---------------------------------------------------------------------------
// Scratch (device globals -- no allocation allowed in kernel_launch)
// ---------------------------------------------------------------------------
__device__ __align__(256) float g_gx [(size_t)MROWS * DH];
__device__ __align__(256) float g_ga [(size_t)MROWS * DH];

__device__ __align__(256) __half g_xsp [(size_t)MROWS * DIN];   // x hi
__device__ __align__(256) __half g_h   [(size_t)MROWS * DHID];  // h hi
__device__ __align__(256) __half g_xhhi[(size_t)MROWS * DHID];
__device__ __align__(256) __half g_xhlo[(size_t)MROWS * DHID];
__device__ __align__(256) __half g_win [(size_t)GK * GK];       // W_in hi
__device__ __align__(256) __half g_wout[(size_t)GK * GK];       // W_out hi
__device__ __align__(256) __half g_wghi[2 * NGW];
__device__ __align__(256) __half g_wglo[2 * NGW];

// ---------------------------------------------------------------------------
// helpers
// ---------------------------------------------------------------------------
__device__ __forceinline__ void cp16(uint32_t s, const void* g) {
    asm volatile("cp.async.cg.shared.global [%0], [%1], 16;" :: "r"(s), "l"(g));
}
__device__ __forceinline__ uint32_t smem_u32(const void* p) {
    uint32_t a;
    asm("{ .reg .u64 t; cvta.to.shared.u64 t, %1; cvt.u32.u64 %0, t; }"
        : "=r"(a) : "l"(p));
    return a;
}
__device__ __forceinline__ uint32_t pack4h(__half a, __half b) {
    __half2 h2 = {a, b};
    return *reinterpret_cast<unsigned*>(&h2);
}

// ---------------------------------------------------------------------------
// fp32 -> fp16 hi (+ lo) split converters. 4 elements per thread.
// ---------------------------------------------------------------------------
__global__ __launch_bounds__(256) void cvt_hilo16_kernel(
    const float4* __restrict__ in, uint2* __restrict__ hi, uint2* __restrict__ lo,
    size_t n4)
{
    size_t i = (size_t)blockIdx.x * 256 + threadIdx.x;
    if (i >= n4) return;
    float4 v = in[i];
    __half h0 = __float2half_rn(v.x), h1 = __float2half_rn(v.y);
    __half h2 = __float2half_rn(v.z), h3 = __float2half_rn(v.w);
    __half l0 = __float2half_rn(v.x - __half2float(h0));
    __half l1 = __float2half_rn(v.y - __half2float(h1));
    __half l2 = __float2half_rn(v.z - __half2float(h2));
    __half l3 = __float2half_rn(v.w - __half2float(h3));
    hi[i] = make_uint2(pack4h(h0, h1), pack4h(h2, h3));
    lo[i] = make_uint2(pack4h(l0, l1), pack4h(l2, l3));
}

__global__ __launch_bounds__(256) void cvt_hi16_kernel(
    const float4* __restrict__ in, uint2* __restrict__ hi, size_t n4)
{
    size_t i = (size_t)blockIdx.x * 256 + threadIdx.x;
    if (i >= n4) return;
    float4 v = in[i];
    hi[i] = make_uint2(pack4h(__float2half_rn(v.x), __float2half_rn(v.y)),
                       pack4h(__float2half_rn(v.z), __float2half_rn(v.w)));
}

// ---------------------------------------------------------------------------
// Generic NSTAGE-pipelined fp16 wmma GEMM body (CTA tile 128x128, BK=64).
// 8 warps (2m x 4n), warp tile 64x32, fp32 accum.
// Products: Ahi*Bhi (+ Ahi*Blo if B_LO) (+ Alo*Bhi if A_LO).
// SPLIT_OUT: write (Chi, Clo) fp16 split of (acc + bias) instead of fp32 C.
// ---------------------------------------------------------------------------
template<bool A_LO, bool B_LO>
__device__ __forceinline__ void load_stage(
    const __half* __restrict__ Ah, const __half* __restrict__ Al, int lda,
    const __half* __restrict__ Bh, const __half* __restrict__ Bl, int ldb,
    int kt, uint32_t base, int tid)
{
    constexpr uint32_t BHI = A_T_BYTES * (A_LO ? 2 : 1);
#pragma unroll
    for (int i = 0; i < 4; i++) {
        int u = tid + (i << 8);      // 0..1023
        int r = u >> 3;
        int ch = u & 7;
        uint32_t so = (uint32_t)(r * (TLDA * 2) + ch * 16);
        size_t go = (size_t)r * lda + kt + ch * 8;
        cp16(base + so, Ah + go);
        if (A_LO) cp16(base + A_T_BYTES + so, Al + go);
    }
#pragma unroll
    for (int i = 0; i < 4; i++) {
        int u = tid + (i << 8);
        int r = u >> 4;
        int ch = u & 15;
        uint32_t so = (uint32_t)(r * (TLDB * 2) + ch * 16);
        size_t go = (size_t)(kt + r) * ldb + ch * 8;
        cp16(base + BHI + so, Bh + go);
        if (B_LO) cp16(base + BHI + B_T_BYTES + so, Bl + go);
    }
}

template<int NSTAGE, bool A_LO, bool B_LO, bool SPLIT_OUT>
__device__ __forceinline__ void gemm_body(
    const __half* __restrict__ Ahi, const __half* __restrict__ Alo, int lda,
    const __half* __restrict__ Bhi, const __half* __restrict__ Blo, int ldb,
    const float* __restrict__ bias,
    float* __restrict__ C,
    __half* __restrict__ Chi, __half* __restrict__ Clo,
    int ldc, int K)
{
    constexpr uint32_t BHI = A_T_BYTES * (A_LO ? 2 : 1);
    constexpr uint32_t STAGE = BHI + B_T_BYTES * (B_LO ? 2 : 1);

    extern __shared__ __align__(256) char smem[];
    const uint32_t sb = smem_u32(smem);
    const int tid    = threadIdx.x;
    const int wid    = tid >> 5;
    const int lane   = tid & 31;
    const int warp_m = wid >> 2;   // 0..1  (64-row slab)
    const int warp_n = wid & 3;    // 0..3  (32-col slab)

    wmma::fragment<wmma::accumulator, 16, 16, 16, float> acc[4][2];
#pragma unroll
    for (int m = 0; m < 4; m++)
#pragma unroll
        for (int n = 0; n < 2; n++) wmma::fill_fragment(acc[m][n], 0.0f);

    const int nIter = K / 64;
#pragma unroll
    for (int s = 0; s < NSTAGE - 1; s++) {
        load_stage<A_LO, B_LO>(Ahi, Alo, lda, Bhi, Blo, ldb, s * 64,
                               sb + (uint32_t)s * STAGE, tid);
        asm volatile("cp.async.commit_group;");
    }

    for (int it = 0; it < nIter; ++it) {
        if (it + NSTAGE - 2 < nIter)
            asm volatile("cp.async.wait_group %0;" :: "n"(NSTAGE - 2));
        else
            asm volatile("cp.async.wait_group 0;");
        __syncthreads();
        if (it + NSTAGE - 1 < nIter) {
            load_stage<A_LO, B_LO>(Ahi, Alo, lda, Bhi, Blo, ldb,
                                   (it + NSTAGE - 1) * 64,
                                   sb + (uint32_t)((it + NSTAGE - 1) % NSTAGE) * STAGE,
                                   tid);
            asm volatile("cp.async.commit_group;");
        }

        char* stg = smem + (it % NSTAGE) * STAGE;
        const __half* As_hi = reinterpret_cast<const __half*>(stg);
        const __half* As_lo = reinterpret_cast<const __half*>(stg + A_T_BYTES);
        const __half* Bs_hi = reinterpret_cast<const __half*>(stg + BHI);
        const __half* Bs_lo = reinterpret_cast<const __half*>(stg + BHI + B_T_BYTES);

#pragma unroll
        for (int kk = 0; kk < 64; kk += 16) {
            wmma::fragment<wmma::matrix_a, 16, 16, 16, __half, wmma::row_major> a_hi[4], a_lo[4];
            wmma::fragment<wmma::matrix_b, 16, 16, 16, __half, wmma::row_major> b_hi[2], b_lo[2];
#pragma unroll
            for (int m = 0; m < 4; m++) {
                int ar = warp_m * 64 + m * 16;
                wmma::load_matrix_sync(a_hi[m], As_hi + ar * TLDA + kk, TLDA);
                if (A_LO) wmma::load_matrix_sync(a_lo[m], As_lo + ar * TLDA + kk, TLDA);
            }
#pragma unroll
            for (int n = 0; n < 2; n++) {
                int bc = warp_n * 32 + n * 16;
                wmma::load_matrix_sync(b_hi[n], Bs_hi + kk * TLDB + bc, TLDB);
                if (B_LO) wmma::load_matrix_sync(b_lo[n], Bs_lo + kk * TLDB + bc, TLDB);
            }
#pragma unroll
            for (int m = 0; m < 4; m++)
#pragma unroll
                for (int n = 0; n < 2; n++) {
                    wmma::mma_sync(acc[m][n], a_hi[m], b_hi[n], acc[m][n]);
                    if (B_LO) wmma::mma_sync(acc[m][n], a_hi[m], b_lo[n], acc[m][n]);
                    if (A_LO) wmma::mma_sync(acc[m][n], a_lo[m], b_hi[n], acc[m][n]);
                }
        }
    }
    __syncthreads();

    // Epilogue: per-warp smem stage (16x32 fp32 per m-frag), exact fp32 bias.
    float* st = reinterpret_cast<float*>(smem) + wid * (16 * 32);
#pragma unroll
    for (int m = 0; m < 4; m++) {
        wmma::store_matrix_sync(st,      acc[m][0], 32, wmma::mem_row_major);
        wmma::store_matrix_sync(st + 16, acc[m][1], 32, wmma::mem_row_major);
        __syncwarp();
        int r  = lane >> 1;
        int cs = (lane & 1) * 16;
        int grow = warp_m * 64 + m * 16 + r;
        int gcol = warp_n * 32 + cs;
#pragma unroll
        for (int c = 0; c < 16; c += 4) {
            float4 v = *reinterpret_cast<float4*>(st + r * 32 + cs + c);
            v.x += bias[gcol + c + 0];
            v.y += bias[gcol + c + 1];
            v.z += bias[gcol + c + 2];
            v.w += bias[gcol + c + 3];
            if (SPLIT_OUT) {
                __half h0 = __float2half_rn(v.x), h1 = __float2half_rn(v.y);
                __half h2 = __float2half_rn(v.z), h3 = __float2half_rn(v.w);
                __half l0 = __float2half_rn(v.x - __half2float(h0));
                __half l1 = __float2half_rn(v.y - __half2float(h1));
                __half l2 = __float2half_rn(v.z - __half2float(h2));
                __half l3 = __float2half_rn(v.w - __half2float(h3));
                *reinterpret_cast<uint2*>(Chi + (size_t)grow * ldc + gcol + c) =
                    make_uint2(pack4h(h0, h1), pack4h(h2, h3));
                *reinterpret_cast<uint2*>(Clo + (size_t)grow * ldc + gcol + c) =
                    make_uint2(pack4h(l0, l1), pack4h(l2, l3));
            } else {
                *reinterpret_cast<float4*>(C + (size_t)grow * ldc + gcol + c) = v;
            }
        }
        __syncwarp();
    }
}

// GEMM1: xh = x @ W_in + b_in (1-product, split fp16 hi/lo out)
__global__ __launch_bounds__(256, 1) void gemm_splitout_kernel(
    const __half* __restrict__ Ahi, const __half* __restrict__ Bhi,
    const float* __restrict__ bias,
    __half* __restrict__ Chi, __half* __restrict__ Clo)
{
    const int row0 = blockIdx.y * 128;
    const int bn   = blockIdx.x * 128;
    gemm_body<4, false, false, true>(
        Ahi + (size_t)row0 * GK, nullptr, GK,
        Bhi + bn, nullptr, GK,
        bias + bn, nullptr,
        Chi + (size_t)row0 * GK + bn,
        Clo + (size_t)row0 * GK + bn, GK, GK);
}

// GEMM2: y = h @ W_out + b_out (1-product, fp32 out)
__global__ __launch_bounds__(256, 1) void gemm_f32out_kernel(
    const __half* __restrict__ Ahi, const __half* __restrict__ Bhi,
    const float* __restrict__ bias, float* __restrict__ C)
{
    const int row0 = blockIdx.y * 128;
    const int bn   = blockIdx.x * 128;
    gemm_body<4, false, false, false>(
        Ahi + (size_t)row0 * GK, nullptr, GK,
        Bhi + bn, nullptr, GK,
        bias + bn,
        C + (size_t)row0 * GK + bn, nullptr, nullptr, GK, GK);
}

// Block-diagonal gate GEMMs (3-product fp16): [128 x 256] @ [256 x 128]
__global__ __launch_bounds__(256, 1) void blockdiag_wmma_kernel(
    const __half* __restrict__ xhhi, const __half* __restrict__ xhlo,
    const __half* __restrict__ wghi, const __half* __restrict__ wglo,
    const float* __restrict__ bgx, const float* __restrict__ bga,
    float* __restrict__ gx, float* __restrict__ ga)
{
    const int mt    = blockIdx.x;   // 0..127
    const int nb    = blockIdx.y;   // 0..7
    const int which = blockIdx.z;   // 0: gate_x, 1: gate_a
    const float* bias = (which ? bga : bgx) + nb * 128;
    float* out = (which ? ga : gx) + (size_t)mt * 128 * DH + nb * 128;
    size_t aoff = (size_t)mt * 128 * DHID + nb * 256;
    size_t boff = (size_t)which * NGW + (size_t)nb * 256 * 128;
    gemm_body<3, true, true, false>(
        xhhi + aoff, xhlo + aoff, DHID,
        wghi + boff, wglo + boff, 128,
        bias, out, nullptr, nullptr, DH, 256);
}

// ---------------------------------------------------------------------------
// Fused pointwise + warp-parallel complex scan.
// Grid: 128 CTAs (4 batches x 32 d-blocks), 1024 threads (32 warps).
// Output h written as fp16 hi only (GEMM2 is 1-product anyway).
// ---------------------------------------------------------------------------
__global__ __launch_bounds__(1024) void scanfused_kernel(
    const __half* __restrict__ xhhi, const __half* __restrict__ xhlo,
    const float* __restrict__ gxl, const float* __restrict__ gal,
    const float* __restrict__ arp, const float* __restrict__ aip,
    __half* __restrict__ hout, float* __restrict__ h_last)
{
    __shared__ float sGx[32][33], sGa[32][33], sXr[32][33], sXi[32][33];
    __shared__ float sHr[32][33], sHi[32][33];

    const int b  = blockIdx.x >> 5;          // 0..3
    const int db = (blockIdx.x & 31) * 32;   // d-block base
    const int tid = threadIdx.x;
    const int w = tid >> 5;    // warp -> chain d = db + w ; also load row s
    const int j = tid & 31;    // lane -> s within tile  ; also load col d
    const int d = db + w;

    float av = arp[d];
    float sp = fmaxf(av, 0.f) + log1pf(expf(-fabsf(av)));   // softplus
    float aipd = aip[d];

    float cr = 0.f, ci = 0.f;   // scan carry

    for (int s0 = 0; s0 < S_SZ; s0 += 32) {
        size_t grow = (size_t)(b * S_SZ + s0 + w);
        sGx[w][j] = gxl[grow * DH + db + j];
        sGa[w][j] = gal[grow * DH + db + j];
        size_t xb = grow * DHID + db + j;
        sXr[w][j] = __half2float(xhhi[xb]) + __half2float(xhlo[xb]);
        sXi[w][j] = __half2float(xhhi[xb + DH]) + __half2float(xhlo[xb + DH]);
        __syncthreads();

        float gx_s = 1.f / (1.f + expf(-sGx[j][w]));
        float ga_s = 1.f / (1.f + expf(-sGa[j][w]));
        float log_a = -8.f * ga_s * sp;
        float mag = expf(log_a);
        float sn, cs;
        sincosf(aipd * ga_s, &sn, &cs);
        float ar = mag * cs;
        float ai = mag * sn;
        float nrm = sqrtf(fmaxf(1.f - mag * mag, 0.f));
        float scale = gx_s * nrm;
        float xr = scale * sXr[j][w];
        float xi = scale * sXi[j][w];

#pragma unroll
        for (int off = 1; off < 32; off <<= 1) {
            float p_ar = __shfl_up_sync(0xffffffffu, ar, off);
            float p_ai = __shfl_up_sync(0xffffffffu, ai, off);
            float p_xr = __shfl_up_sync(0xffffffffu, xr, off);
            float p_xi = __shfl_up_sync(0xffffffffu, xi, off);
            if (j >= off) {
                float nar = ar * p_ar - ai * p_ai;
                float nai = ar * p_ai + ai * p_ar;
                float nxr = ar * p_xr - ai * p_xi + xr;
                float nxi = ar * p_xi + ai * p_xr + xi;
                ar = nar; ai = nai; xr = nxr; xi = nxi;
            }
        }

        float hr  = fmaf(ar, cr, fmaf(-ai, ci, xr));
        float hi_ = fmaf(ar, ci, fmaf(ai, cr, xi));
        cr = __shfl_sync(0xffffffffu, hr, 31);
        ci = __shfl_sync(0xffffffffu, hi_, 31);

        sHr[j][w] = hr;
        sHi[j][w] = hi_;
        __syncthreads();

        size_t orow = grow * (size_t)DHID;
        hout[orow + db + j]      = __float2half_rn(sHr[w][j]);
        hout[orow + DH + db + j] = __float2half_rn(sHi[w][j]);
    }

    if (j == 0) {
        h_last[(size_t)b * DHID + d]      = cr;
        h_last[(size_t)b * DHID + DH + d] = ci;
    }
}

// ---------------------------------------------------------------------------
// Launch
// ---------------------------------------------------------------------------
extern "C" void kernel_launch(void* const* d_in, const int* in_sizes, int n_in,
                              void* d_out, int out_size)
{
    const float* x     = (const float*)d_in[0];
    const float* arp   = (const float*)d_in[1];
    const float* aip   = (const float*)d_in[2];
    const float* W_in  = (const float*)d_in[3];
    const float* b_in  = (const float*)d_in[4];
    const float* Wgx   = (const float*)d_in[5];
    const float* bgx   = (const float*)d_in[6];
    const float* Wga   = (const float*)d_in[7];
    const float* bga   = (const float*)d_in[8];
    const float* W_out = (const float*)d_in[9];
    const float* b_out = (const float*)d_in[10];

    float* y = (float*)d_out;
    float* h_last = (float*)d_out + ((size_t)out_size - (size_t)B_SZ * DHID);

    float *gx, *ga;
    __half *xsp, *h, *xhhi, *xhlo, *win, *wout, *wghi, *wglo;
    cudaGetSymbolAddress((void**)&gx,   g_gx);
    cudaGetSymbolAddress((void**)&ga,   g_ga);
    cudaGetSymbolAddress((void**)&xsp,  g_xsp);
    cudaGetSymbolAddress((void**)&h,    g_h);
    cudaGetSymbolAddress((void**)&xhhi, g_xhhi);
    cudaGetSymbolAddress((void**)&xhlo, g_xhlo);
    cudaGetSymbolAddress((void**)&win,  g_win);
    cudaGetSymbolAddress((void**)&wout, g_wout);
    cudaGetSymbolAddress((void**)&wghi, g_wghi);
    cudaGetSymbolAddress((void**)&wglo, g_wglo);

    cudaFuncSetAttribute(gemm_f32out_kernel,
                         cudaFuncAttributeMaxDynamicSharedMemorySize, SMEM_BIG);
    cudaFuncSetAttribute(gemm_splitout_kernel,
                         cudaFuncAttributeMaxDynamicSharedMemorySize, SMEM_BIG);
    cudaFuncSetAttribute(blockdiag_wmma_kernel,
                         cudaFuncAttributeMaxDynamicSharedMemorySize, SMEM_BD);

    const size_t nx4 = (size_t)MROWS * GK / 4;
    const size_t nw4 = (size_t)GK * GK / 4;
    const size_t ng4 = (size_t)NGW / 4;

    // 0) input conversions (all up front; independent)
    cvt_hi16_kernel<<<(unsigned)((nx4 + 255) / 256), 256>>>(
        (const float4*)x, (uint2*)xsp, nx4);
    cvt_hi16_kernel<<<(unsigned)((nw4 + 255) / 256), 256>>>(
        (const float4*)W_in, (uint2*)win, nw4);
    cvt_hi16_kernel<<<(unsigned)((nw4 + 255) / 256), 256>>>(
        (const float4*)W_out, (uint2*)wout, nw4);
    cvt_hilo16_kernel<<<(unsigned)((ng4 + 255) / 256), 256>>>(
        (const float4*)Wgx, (uint2*)wghi, (uint2*)wglo, ng4);
    cvt_hilo16_kernel<<<(unsigned)((ng4 + 255) / 256), 256>>>(
        (const float4*)Wga, (uint2*)(wghi + NGW), (uint2*)(wglo + NGW), ng4);

    // 1) xh = x @ W_in + b_in  (1-product) -> split fp16 hi/lo
    gemm_splitout_kernel<<<dim3(DHID / 128, MROWS / 128), 256, SMEM_BIG>>>(
        xsp, win, b_in, xhhi, xhlo);

    // 2) gate linears (block-diagonal, 3-product fp16)
    blockdiag_wmma_kernel<<<dim3(MROWS / 128, NB, 2), 256, SMEM_BD>>>(
        xhhi, xhlo, wghi, wglo, bgx, bga, gx, ga);

    // 3+4) fused pointwise + warp scan; writes h as fp16 hi
    scanfused_kernel<<<B_SZ * (DH / 32), 1024>>>(
        xhhi, xhlo, gx, ga, arp, aip, h, h_last);

    // 5) y = h @ W_out + b_out (1-product)
    gemm_f32out_kernel<<<dim3(DIN / 128, MROWS / 128), 256, SMEM_BIG>>>(
        h, wout, b_out, y);
}

// round 10
// speedup vs baseline: 6.1750x; 1.1275x over previous
#include <cuda_runtime.h>
#include <cuda_fp16.h>
#include <mma.h>
#include <math.h>
#include <stdint.h>

using namespace nvcuda;

// Problem dims (fixed by the dataset)
#define NB     8
#define B_SZ   4
#define S_SZ   4096
#define DIN    2048
#define DHID   2048
#define DH     1024
#define MROWS  (B_SZ * S_SZ)   // 16384
#define GK     2048            // K (and N) for both big GEMMs

// wmma GEMM tiling: CTA 128x256, BK=64, warp tile 64x64 (8 warps: 2m x 4n)
#define TLDA 72      // A smem stride (halves): 144B
#define TLDB 264     // B smem stride (halves): 528B (256 cols + 8 pad)
#define A_BYTES (128 * TLDA * 2)     // 18432
#define B_BYTES (64 * TLDB * 2)      // 33792
#define STAGE   (A_BYTES + B_BYTES)  // 52224
#define SMEM_BIG  (4 * STAGE)        // 208896
#define SMEM_GATE (3 * STAGE)        // 156672

// ---------------------------------------------------------------------------
// Scratch (device globals -- no allocation allowed in kernel_launch)
// ---------------------------------------------------------------------------
__device__ __align__(256) __half g_gx  [(size_t)MROWS * DH];    // gate_x logits (fp16)
__device__ __align__(256) __half g_ga  [(size_t)MROWS * DH];    // gate_a logits (fp16)
__device__ __align__(256) __half g_xsp [(size_t)MROWS * DIN];   // x hi
__device__ __align__(256) __half g_h   [(size_t)MROWS * DHID];  // h hi
__device__ __align__(256) __half g_xhhi[(size_t)MROWS * DHID];
__device__ __align__(256) __half g_xhlo[(size_t)MROWS * DHID];
__device__ __align__(256) __half g_win [(size_t)GK * GK];       // W_in hi
__device__ __align__(256) __half g_wout[(size_t)GK * GK];       // W_out hi
__device__ __align__(256) __half g_wg2 [(size_t)NB * 256 * 256]; // [Wgx|Wga] packed

// ---------------------------------------------------------------------------
// helpers
// ---------------------------------------------------------------------------
__device__ __forceinline__ void cp16(uint32_t s, const void* g) {
    asm volatile("cp.async.cg.shared.global [%0], [%1], 16;" :: "r"(s), "l"(g));
}
__device__ __forceinline__ uint32_t smem_u32(const void* p) {
    uint32_t a;
    asm("{ .reg .u64 t; cvta.to.shared.u64 t, %1; cvt.u32.u64 %0, t; }"
        : "=r"(a) : "l"(p));
    return a;
}
__device__ __forceinline__ uint32_t pack4h(__half a, __half b) {
    __half2 h2 = {a, b};
    return *reinterpret_cast<unsigned*>(&h2);
}

// ---------------------------------------------------------------------------
// Converters
// ---------------------------------------------------------------------------
__global__ __launch_bounds__(256) void cvt_hi16_kernel(
    const float4* __restrict__ in, uint2* __restrict__ hi, size_t n4)
{
    size_t i = (size_t)blockIdx.x * 256 + threadIdx.x;
    if (i >= n4) return;
    float4 v = in[i];
    hi[i] = make_uint2(pack4h(__float2half_rn(v.x), __float2half_rn(v.y)),
                       pack4h(__float2half_rn(v.z), __float2half_rn(v.w)));
}

// Pack gate weights: wg2[nb][k][c] = c<128 ? Wgx[nb][k][c] : Wga[nb][k][c-128]
__global__ __launch_bounds__(256) void cvt_gatew_kernel(
    const float* __restrict__ Wgx, const float* __restrict__ Wga,
    __half* __restrict__ out)
{
    int i = blockIdx.x * 256 + threadIdx.x;   // 0 .. NB*256*256-1
    int c  = i & 255;
    int k  = (i >> 8) & 255;
    int nb = i >> 16;
    float v = (c < 128) ? Wgx[nb * 32768 + k * 128 + c]
                        : Wga[nb * 32768 + k * 128 + (c - 128)];
    out[i] = __float2half_rn(v);
}

// ---------------------------------------------------------------------------
// Shared mainloop: CTA tile 128x256, BK=64, NSTAGE-deep cp.async pipeline.
// acc[4][4] per warp (warp tile 64x64). A [128 x K] row-major (pre-offset),
// B [K x 256-span] row-major (pre-offset), strides in halves.
// ---------------------------------------------------------------------------
__device__ __forceinline__ void load_stage(
    const __half* __restrict__ A, int lda,
    const __half* __restrict__ B, int ldb,
    int kt, uint32_t base, int tid)
{
#pragma unroll
    for (int i = 0; i < 4; i++) {            // A: 128 rows x 128B
        int u = tid + (i << 8);
        int r = u >> 3;
        int ch = u & 7;
        cp16(base + (uint32_t)(r * 144 + ch * 16),
             A + (size_t)r * lda + kt + ch * 8);
    }
#pragma unroll
    for (int i = 0; i < 8; i++) {            // B: 64 rows x 512B
        int u = tid + (i << 8);
        int r = u >> 5;
        int ch = u & 31;
        cp16(base + A_BYTES + (uint32_t)(r * 528 + ch * 16),
             B + (size_t)(kt + r) * ldb + ch * 8);
    }
}

template<int NSTAGE>
__device__ __forceinline__ void gemm_mainloop(
    const __half* __restrict__ A, int lda,
    const __half* __restrict__ B, int ldb, int K,
    wmma::fragment<wmma::accumulator, 16, 16, 16, float> (&acc)[4][4],
    char* smem, uint32_t sb, int tid, int warp_m, int warp_n)
{
#pragma unroll
    for (int m = 0; m < 4; m++)
#pragma unroll
        for (int n = 0; n < 4; n++) wmma::fill_fragment(acc[m][n], 0.0f);

    const int nIter = K / 64;
#pragma unroll
    for (int s = 0; s < NSTAGE - 1; s++) {
        load_stage(A, lda, B, ldb, s * 64, sb + (uint32_t)s * STAGE, tid);
        asm volatile("cp.async.commit_group;");
    }

    for (int it = 0; it < nIter; ++it) {
        if (it + NSTAGE - 2 < nIter)
            asm volatile("cp.async.wait_group %0;" :: "n"(NSTAGE - 2));
        else
            asm volatile("cp.async.wait_group 0;");
        __syncthreads();
        if (it + NSTAGE - 1 < nIter) {
            load_stage(A, lda, B, ldb, (it + NSTAGE - 1) * 64,
                       sb + (uint32_t)((it + NSTAGE - 1) % NSTAGE) * STAGE, tid);
            asm volatile("cp.async.commit_group;");
        }

        char* stg = smem + (it % NSTAGE) * STAGE;
        const __half* As = reinterpret_cast<const __half*>(stg);
        const __half* Bs = reinterpret_cast<const __half*>(stg + A_BYTES);

#pragma unroll
        for (int kk = 0; kk < 64; kk += 16) {
            wmma::fragment<wmma::matrix_a, 16, 16, 16, __half, wmma::row_major> a[4];
            wmma::fragment<wmma::matrix_b, 16, 16, 16, __half, wmma::row_major> b[4];
#pragma unroll
            for (int m = 0; m < 4; m++)
                wmma::load_matrix_sync(a[m], As + (warp_m * 64 + m * 16) * TLDA + kk, TLDA);
#pragma unroll
            for (int n = 0; n < 4; n++)
                wmma::load_matrix_sync(b[n], Bs + kk * TLDB + warp_n * 64 + n * 16, TLDB);
#pragma unroll
            for (int m = 0; m < 4; m++)
#pragma unroll
                for (int n = 0; n < 4; n++)
                    wmma::mma_sync(acc[m][n], a[m], b[n], acc[m][n]);
        }
    }
    __syncthreads();
}

// ---------------------------------------------------------------------------
// GEMM1: xh = x @ W_in + b_in -> split fp16 hi/lo. Grid (GK/256, MROWS/128).
// ---------------------------------------------------------------------------
__global__ __launch_bounds__(256, 1) void gemm_splitout_kernel(
    const __half* __restrict__ Ahi, const __half* __restrict__ Bhi,
    const float* __restrict__ bias,
    __half* __restrict__ Chi, __half* __restrict__ Clo)
{
    extern __shared__ __align__(256) char smem[];
    const uint32_t sb = smem_u32(smem);
    const int tid = threadIdx.x, wid = tid >> 5, lane = tid & 31;
    const int warp_m = wid >> 2, warp_n = wid & 3;
    const int row0 = blockIdx.y * 128;
    const int bn   = blockIdx.x * 256;

    wmma::fragment<wmma::accumulator, 16, 16, 16, float> acc[4][4];
    gemm_mainloop<4>(Ahi + (size_t)row0 * GK, GK, Bhi + bn, GK, GK,
                     acc, smem, sb, tid, warp_m, warp_n);

    float* st = reinterpret_cast<float*>(smem) + wid * (16 * 64);
#pragma unroll
    for (int m = 0; m < 4; m++) {
#pragma unroll
        for (int n = 0; n < 4; n++)
            wmma::store_matrix_sync(st + n * 16, acc[m][n], 64, wmma::mem_row_major);
        __syncwarp();
        int r = lane >> 1, cs = (lane & 1) * 32;
        int grow = row0 + warp_m * 64 + m * 16 + r;
        int gcol = bn + warp_n * 64 + cs;
#pragma unroll
        for (int c = 0; c < 32; c += 4) {
            float4 v = *reinterpret_cast<float4*>(st + r * 64 + cs + c);
            v.x += bias[gcol + c + 0];
            v.y += bias[gcol + c + 1];
            v.z += bias[gcol + c + 2];
            v.w += bias[gcol + c + 3];
            __half h0 = __float2half_rn(v.x), h1 = __float2half_rn(v.y);
            __half h2 = __float2half_rn(v.z), h3 = __float2half_rn(v.w);
            __half l0 = __float2half_rn(v.x - __half2float(h0));
            __half l1 = __float2half_rn(v.y - __half2float(h1));
            __half l2 = __float2half_rn(v.z - __half2float(h2));
            __half l3 = __float2half_rn(v.w - __half2float(h3));
            *reinterpret_cast<uint2*>(Chi + (size_t)grow * GK + gcol + c) =
                make_uint2(pack4h(h0, h1), pack4h(h2, h3));
            *reinterpret_cast<uint2*>(Clo + (size_t)grow * GK + gcol + c) =
                make_uint2(pack4h(l0, l1), pack4h(l2, l3));
        }
        __syncwarp();
    }
}

// ---------------------------------------------------------------------------
// GEMM2: y = h @ W_out + b_out -> fp32. Grid (GK/256, MROWS/128).
// ---------------------------------------------------------------------------
__global__ __launch_bounds__(256, 1) void gemm_f32out_kernel(
    const __half* __restrict__ Ahi, const __half* __restrict__ Bhi,
    const float* __restrict__ bias, float* __restrict__ C)
{
    extern __shared__ __align__(256) char smem[];
    const uint32_t sb = smem_u32(smem);
    const int tid = threadIdx.x, wid = tid >> 5, lane = tid & 31;
    const int warp_m = wid >> 2, warp_n = wid & 3;
    const int row0 = blockIdx.y * 128;
    const int bn   = blockIdx.x * 256;

    wmma::fragment<wmma::accumulator, 16, 16, 16, float> acc[4][4];
    gemm_mainloop<4>(Ahi + (size_t)row0 * GK, GK, Bhi + bn, GK, GK,
                     acc, smem, sb, tid, warp_m, warp_n);

    float* st = reinterpret_cast<float*>(smem) + wid * (16 * 64);
#pragma unroll
    for (int m = 0; m < 4; m++) {
#pragma unroll
        for (int n = 0; n < 4; n++)
            wmma::store_matrix_sync(st + n * 16, acc[m][n], 64, wmma::mem_row_major);
        __syncwarp();
        int r = lane >> 1, cs = (lane & 1) * 32;
        int grow = row0 + warp_m * 64 + m * 16 + r;
        int gcol = bn + warp_n * 64 + cs;
#pragma unroll
        for (int c = 0; c < 32; c += 4) {
            float4 v = *reinterpret_cast<float4*>(st + r * 64 + cs + c);
            v.x += bias[gcol + c + 0];
            v.y += bias[gcol + c + 1];
            v.z += bias[gcol + c + 2];
            v.w += bias[gcol + c + 3];
            *reinterpret_cast<float4*>(C + (size_t)grow * GK + gcol + c) = v;
        }
        __syncwarp();
    }
}

// ---------------------------------------------------------------------------
// Merged gate GEMM: per (m-tile, nb): [128 x 256] @ [256 x 256] where B cols
// 0-127 = Wgx_nb, 128-255 = Wga_nb. 1-product fp16, fp16 logits out.
// ---------------------------------------------------------------------------
__global__ __launch_bounds__(256, 1) void gate_gemm_kernel(
    const __half* __restrict__ xhhi, const __half* __restrict__ wg2,
    const float* __restrict__ bgx, const float* __restrict__ bga,
    __half* __restrict__ gx, __half* __restrict__ ga)
{
    extern __shared__ __align__(256) char smem[];
    const uint32_t sb = smem_u32(smem);
    const int tid = threadIdx.x, wid = tid >> 5, lane = tid & 31;
    const int warp_m = wid >> 2, warp_n = wid & 3;
    const int mt = blockIdx.x;   // 0..127
    const int nb = blockIdx.y;   // 0..7

    wmma::fragment<wmma::accumulator, 16, 16, 16, float> acc[4][4];
    gemm_mainloop<3>(xhhi + (size_t)mt * 128 * DHID + nb * 256, DHID,
                     wg2 + (size_t)nb * 65536, 256, 256,
                     acc, smem, sb, tid, warp_m, warp_n);

    float* st = reinterpret_cast<float*>(smem) + wid * (16 * 64);
#pragma unroll
    for (int m = 0; m < 4; m++) {
#pragma unroll
        for (int n = 0; n < 4; n++)
            wmma::store_matrix_sync(st + n * 16, acc[m][n], 64, wmma::mem_row_major);
        __syncwarp();
        int r = lane >> 1, cs = (lane & 1) * 32;
        int grow = warp_m * 64 + m * 16 + r;
        int row = mt * 128 + grow;
        int gcol = warp_n * 64 + cs;     // 0..255, 32-col segment
        bool isx = gcol < 128;
        int col = isx ? gcol : gcol - 128;
        const float* bp = (isx ? bgx : bga) + nb * 128 + col;
        __half* op = (isx ? gx : ga) + (size_t)row * DH + nb * 128 + col;
#pragma unroll
        for (int c = 0; c < 32; c += 4) {
            float4 v = *reinterpret_cast<float4*>(st + r * 64 + cs + c);
            v.x += bp[c + 0];
            v.y += bp[c + 1];
            v.z += bp[c + 2];
            v.w += bp[c + 3];
            *reinterpret_cast<uint2*>(op + c) =
                make_uint2(pack4h(__float2half_rn(v.x), __float2half_rn(v.y)),
                           pack4h(__float2half_rn(v.z), __float2half_rn(v.w)));
        }
        __syncwarp();
    }
}

// ---------------------------------------------------------------------------
// Fused pointwise + warp-parallel complex scan (gates fp16 in, h fp16 out).
// ---------------------------------------------------------------------------
__global__ __launch_bounds__(1024) void scanfused_kernel(
    const __half* __restrict__ xhhi, const __half* __restrict__ xhlo,
    const __half* __restrict__ gxl, const __half* __restrict__ gal,
    const float* __restrict__ arp, const float* __restrict__ aip,
    __half* __restrict__ hout, float* __restrict__ h_last)
{
    __shared__ float sGx[32][33], sGa[32][33], sXr[32][33], sXi[32][33];
    __shared__ float sHr[32][33], sHi[32][33];

    const int b  = blockIdx.x >> 5;          // 0..3
    const int db = (blockIdx.x & 31) * 32;   // d-block base
    const int tid = threadIdx.x;
    const int w = tid >> 5;
    const int j = tid & 31;
    const int d = db + w;

    float av = arp[d];
    float sp = fmaxf(av, 0.f) + log1pf(expf(-fabsf(av)));   // softplus
    float aipd = aip[d];

    float cr = 0.f, ci = 0.f;   // scan carry

    for (int s0 = 0; s0 < S_SZ; s0 += 32) {
        size_t grow = (size_t)(b * S_SZ + s0 + w);
        sGx[w][j] = __half2float(gxl[grow * DH + db + j]);
        sGa[w][j] = __half2float(gal[grow * DH + db + j]);
        size_t xb = grow * DHID + db + j;
        sXr[w][j] = __half2float(xhhi[xb]) + __half2float(xhlo[xb]);
        sXi[w][j] = __half2float(xhhi[xb + DH]) + __half2float(xhlo[xb + DH]);
        __syncthreads();

        float gx_s = 1.f / (1.f + expf(-sGx[j][w]));
        float ga_s = 1.f / (1.f + expf(-sGa[j][w]));
        float log_a = -8.f * ga_s * sp;
        float mag = expf(log_a);
        float sn, cs;
        sincosf(aipd * ga_s, &sn, &cs);
        float ar = mag * cs;
        float ai = mag * sn;
        float nrm = sqrtf(fmaxf(1.f - mag * mag, 0.f));
        float scale = gx_s * nrm;
        float xr = scale * sXr[j][w];
        float xi = scale * sXi[j][w];

#pragma unroll
        for (int off = 1; off < 32; off <<= 1) {
            float p_ar = __shfl_up_sync(0xffffffffu, ar, off);
            float p_ai = __shfl_up_sync(0xffffffffu, ai, off);
            float p_xr = __shfl_up_sync(0xffffffffu, xr, off);
            float p_xi = __shfl_up_sync(0xffffffffu, xi, off);
            if (j >= off) {
                float nar = ar * p_ar - ai * p_ai;
                float nai = ar * p_ai + ai * p_ar;
                float nxr = ar * p_xr - ai * p_xi + xr;
                float nxi = ar * p_xi + ai * p_xr + xi;
                ar = nar; ai = nai; xr = nxr; xi = nxi;
            }
        }

        float hr  = fmaf(ar, cr, fmaf(-ai, ci, xr));
        float hi_ = fmaf(ar, ci, fmaf(ai, cr, xi));
        cr = __shfl_sync(0xffffffffu, hr, 31);
        ci = __shfl_sync(0xffffffffu, hi_, 31);

        sHr[j][w] = hr;
        sHi[j][w] = hi_;
        __syncthreads();

        size_t orow = grow * (size_t)DHID;
        hout[orow + db + j]      = __float2half_rn(sHr[w][j]);
        hout[orow + DH + db + j] = __float2half_rn(sHi[w][j]);
    }

    if (j == 0) {
        h_last[(size_t)b * DHID + d]      = cr;
        h_last[(size_t)b * DHID + DH + d] = ci;
    }
}

// ---------------------------------------------------------------------------
// Launch
// ---------------------------------------------------------------------------
extern "C" void kernel_launch(void* const* d_in, const int* in_sizes, int n_in,
                              void* d_out, int out_size)
{
    const float* x     = (const float*)d_in[0];
    const float* arp   = (const float*)d_in[1];
    const float* aip   = (const float*)d_in[2];
    const float* W_in  = (const float*)d_in[3];
    const float* b_in  = (const float*)d_in[4];
    const float* Wgx   = (const float*)d_in[5];
    const float* bgx   = (const float*)d_in[6];
    const float* Wga   = (const float*)d_in[7];
    const float* bga   = (const float*)d_in[8];
    const float* W_out = (const float*)d_in[9];
    const float* b_out = (const float*)d_in[10];

    float* y = (float*)d_out;
    float* h_last = (float*)d_out + ((size_t)out_size - (size_t)B_SZ * DHID);

    __half *gx, *ga, *xsp, *h, *xhhi, *xhlo, *win, *wout, *wg2;
    cudaGetSymbolAddress((void**)&gx,   g_gx);
    cudaGetSymbolAddress((void**)&ga,   g_ga);
    cudaGetSymbolAddress((void**)&xsp,  g_xsp);
    cudaGetSymbolAddress((void**)&h,    g_h);
    cudaGetSymbolAddress((void**)&xhhi, g_xhhi);
    cudaGetSymbolAddress((void**)&xhlo, g_xhlo);
    cudaGetSymbolAddress((void**)&win,  g_win);
    cudaGetSymbolAddress((void**)&wout, g_wout);
    cudaGetSymbolAddress((void**)&wg2,  g_wg2);

    cudaFuncSetAttribute(gemm_splitout_kernel,
                         cudaFuncAttributeMaxDynamicSharedMemorySize, SMEM_BIG);
    cudaFuncSetAttribute(gemm_f32out_kernel,
                         cudaFuncAttributeMaxDynamicSharedMemorySize, SMEM_BIG);
    cudaFuncSetAttribute(gate_gemm_kernel,
                         cudaFuncAttributeMaxDynamicSharedMemorySize, SMEM_GATE);

    const size_t nx4 = (size_t)MROWS * GK / 4;
    const size_t nw4 = (size_t)GK * GK / 4;

    // 0) conversions (independent)
    cvt_hi16_kernel<<<(unsigned)((nx4 + 255) / 256), 256>>>(
        (const float4*)x, (uint2*)xsp, nx4);
    cvt_hi16_kernel<<<(unsigned)((nw4 + 255) / 256), 256>>>(
        (const float4*)W_in, (uint2*)win, nw4);
    cvt_hi16_kernel<<<(unsigned)((nw4 + 255) / 256), 256>>>(
        (const float4*)W_out, (uint2*)wout, nw4);
    cvt_gatew_kernel<<<(NB * 256 * 256) / 256, 256>>>(Wgx, Wga, wg2);

    // 1) xh = x @ W_in + b_in (1-product) -> split fp16 hi/lo
    gemm_splitout_kernel<<<dim3(GK / 256, MROWS / 128), 256, SMEM_BIG>>>(
        xsp, win, b_in, xhhi, xhlo);

    // 2) merged gate linears (1-product, fp16 logits)
    gate_gemm_kernel<<<dim3(MROWS / 128, NB), 256, SMEM_GATE>>>(
        xhhi, wg2, bgx, bga, gx, ga);

    // 3+4) fused pointwise + warp scan; writes h as fp16 hi
    scanfused_kernel<<<B_SZ * (DH / 32), 1024>>>(
        xhhi, xhlo, gx, ga, arp, aip, h, h_last);

    // 5) y = h @ W_out + b_out (1-product)
    gemm_f32out_kernel<<<dim3(GK / 256, MROWS / 128), 256, SMEM_BIG>>>(
        h, wout, b_out, y);
}

// round 11
// speedup vs baseline: 6.3584x; 1.0297x over previous
#include <cuda_runtime.h>
#include <cuda_fp16.h>
#include <mma.h>
#include <math.h>
#include <stdint.h>

using namespace nvcuda;

// Problem dims (fixed by the dataset)
#define NB     8
#define B_SZ   4
#define S_SZ   4096
#define DIN    2048
#define DHID   2048
#define DH     1024
#define MROWS  (B_SZ * S_SZ)   // 16384
#define GK     2048            // K (and N) for both big GEMMs

// wmma GEMM tiling: CTA 128x256, BK=64, warp tile 64x64 (8 warps: 2m x 4n)
#define TLDA 72      // A smem stride (halves): 144B
#define TLDB 264     // B smem stride (halves): 528B (256 cols + 8 pad)
#define A_BYTES (128 * TLDA * 2)     // 18432
#define B_BYTES (64 * TLDB * 2)      // 33792
#define STAGE   (A_BYTES + B_BYTES)  // 52224
#define SMEM_BIG (4 * STAGE)         // 208896

// post-mainloop layout inside smem (fused GEMM1):
#define XHS_BYTES (128 * TLDB * 2)        // 67584: xh tile fp16 [128][264]
#define ST_OFF    XHS_BYTES               // fp32 staging (8 warps * 16*64*4 = 32KB)
#define GB_OFF    (XHS_BYTES + 32768)     // gate B double buffer (2 * 33792)

// ---------------------------------------------------------------------------
// Scratch (device globals -- no allocation allowed in kernel_launch)
// ---------------------------------------------------------------------------
__device__ __align__(256) __half g_gx  [(size_t)MROWS * DH];    // gate_x logits
__device__ __align__(256) __half g_ga  [(size_t)MROWS * DH];    // gate_a logits
__device__ __align__(256) __half g_xsp [(size_t)MROWS * DIN];   // x hi
__device__ __align__(256) __half g_h   [(size_t)MROWS * DHID];  // h hi
__device__ __align__(256) __half g_xhhi[(size_t)MROWS * DHID];  // xh hi
__device__ __align__(256) __half g_win [(size_t)GK * GK];       // W_in hi
__device__ __align__(256) __half g_wout[(size_t)GK * GK];       // W_out hi
__device__ __align__(256) __half g_wg2 [(size_t)NB * 256 * 256]; // [Wgx|Wga]

// ---------------------------------------------------------------------------
// helpers
// ---------------------------------------------------------------------------
__device__ __forceinline__ void cp16(uint32_t s, const void* g) {
    asm volatile("cp.async.cg.shared.global [%0], [%1], 16;" :: "r"(s), "l"(g));
}
__device__ __forceinline__ uint32_t smem_u32(const void* p) {
    uint32_t a;
    asm("{ .reg .u64 t; cvta.to.shared.u64 t, %1; cvt.u32.u64 %0, t; }"
        : "=r"(a) : "l"(p));
    return a;
}
__device__ __forceinline__ uint32_t pack4h(__half a, __half b) {
    __half2 h2 = {a, b};
    return *reinterpret_cast<unsigned*>(&h2);
}

// ---------------------------------------------------------------------------
// Converters
// ---------------------------------------------------------------------------
__global__ __launch_bounds__(256) void cvt_hi16_kernel(
    const float4* __restrict__ in, uint2* __restrict__ hi, size_t n4)
{
    size_t i = (size_t)blockIdx.x * 256 + threadIdx.x;
    if (i >= n4) return;
    float4 v = in[i];
    hi[i] = make_uint2(pack4h(__float2half_rn(v.x), __float2half_rn(v.y)),
                       pack4h(__float2half_rn(v.z), __float2half_rn(v.w)));
}

// Pack gate weights: wg2[nb][k][c] = c<128 ? Wgx[nb][k][c] : Wga[nb][k][c-128]
__global__ __launch_bounds__(256) void cvt_gatew_kernel(
    const float* __restrict__ Wgx, const float* __restrict__ Wga,
    __half* __restrict__ out)
{
    int i = blockIdx.x * 256 + threadIdx.x;
    int c  = i & 255;
    int k  = (i >> 8) & 255;
    int nb = i >> 16;
    float v = (c < 128) ? Wgx[nb * 32768 + k * 128 + c]
                        : Wga[nb * 32768 + k * 128 + (c - 128)];
    out[i] = __float2half_rn(v);
}

// ---------------------------------------------------------------------------
// Shared mainloop: CTA tile 128x256, BK=64, NSTAGE-deep cp.async pipeline.
// ---------------------------------------------------------------------------
__device__ __forceinline__ void load_stage(
    const __half* __restrict__ A, int lda,
    const __half* __restrict__ B, int ldb,
    int kt, uint32_t base, int tid)
{
#pragma unroll
    for (int i = 0; i < 4; i++) {            // A: 128 rows x 128B
        int u = tid + (i << 8);
        int r = u >> 3;
        int ch = u & 7;
        cp16(base + (uint32_t)(r * 144 + ch * 16),
             A + (size_t)r * lda + kt + ch * 8);
    }
#pragma unroll
    for (int i = 0; i < 8; i++) {            // B: 64 rows x 512B
        int u = tid + (i << 8);
        int r = u >> 5;
        int ch = u & 31;
        cp16(base + A_BYTES + (uint32_t)(r * 528 + ch * 16),
             B + (size_t)(kt + r) * ldb + ch * 8);
    }
}

template<int NSTAGE>
__device__ __forceinline__ void gemm_mainloop(
    const __half* __restrict__ A, int lda,
    const __half* __restrict__ B, int ldb, int K,
    wmma::fragment<wmma::accumulator, 16, 16, 16, float> (&acc)[4][4],
    char* smem, uint32_t sb, int tid, int warp_m, int warp_n)
{
#pragma unroll
    for (int m = 0; m < 4; m++)
#pragma unroll
        for (int n = 0; n < 4; n++) wmma::fill_fragment(acc[m][n], 0.0f);

    const int nIter = K / 64;
#pragma unroll
    for (int s = 0; s < NSTAGE - 1; s++) {
        load_stage(A, lda, B, ldb, s * 64, sb + (uint32_t)s * STAGE, tid);
        asm volatile("cp.async.commit_group;");
    }

    for (int it = 0; it < nIter; ++it) {
        if (it + NSTAGE - 2 < nIter)
            asm volatile("cp.async.wait_group %0;" :: "n"(NSTAGE - 2));
        else
            asm volatile("cp.async.wait_group 0;");
        __syncthreads();
        if (it + NSTAGE - 1 < nIter) {
            load_stage(A, lda, B, ldb, (it + NSTAGE - 1) * 64,
                       sb + (uint32_t)((it + NSTAGE - 1) % NSTAGE) * STAGE, tid);
            asm volatile("cp.async.commit_group;");
        }

        char* stg = smem + (it % NSTAGE) * STAGE;
        const __half* As = reinterpret_cast<const __half*>(stg);
        const __half* Bs = reinterpret_cast<const __half*>(stg + A_BYTES);

#pragma unroll
        for (int kk = 0; kk < 64; kk += 16) {
            wmma::fragment<wmma::matrix_a, 16, 16, 16, __half, wmma::row_major> a[4];
            wmma::fragment<wmma::matrix_b, 16, 16, 16, __half, wmma::row_major> b[4];
#pragma unroll
            for (int m = 0; m < 4; m++)
                wmma::load_matrix_sync(a[m], As + (warp_m * 64 + m * 16) * TLDA + kk, TLDA);
#pragma unroll
            for (int n = 0; n < 4; n++)
                wmma::load_matrix_sync(b[n], Bs + kk * TLDB + warp_n * 64 + n * 16, TLDB);
#pragma unroll
            for (int m = 0; m < 4; m++)
#pragma unroll
                for (int n = 0; n < 4; n++)
                    wmma::mma_sync(acc[m][n], a[m], b[n], acc[m][n]);
        }
    }
    __syncthreads();
}

// ---------------------------------------------------------------------------
// Fused GEMM1 + gate GEMM.
//   Grid (NB=8, MROWS/128): CTA computes xh tile [128 x 256] (= gate block nb
//   A operand), writes xh hi to global AND fp16 tile to smem, then computes
//   gate logits [128 x 256] = xh_tile @ wg2[nb] (+bias) -> gx/ga fp16.
// ---------------------------------------------------------------------------
__global__ __launch_bounds__(256, 1) void gemm1_fused_kernel(
    const __half* __restrict__ Ahi, const __half* __restrict__ Bhi,
    const float* __restrict__ bias,
    const __half* __restrict__ wg2,
    const float* __restrict__ bgx, const float* __restrict__ bga,
    __half* __restrict__ Chi,
    __half* __restrict__ gx, __half* __restrict__ ga)
{
    extern __shared__ __align__(256) char smem[];
    const uint32_t sb = smem_u32(smem);
    const int tid = threadIdx.x, wid = tid >> 5, lane = tid & 31;
    const int warp_m = wid >> 2, warp_n = wid & 3;
    const int nb   = blockIdx.x;          // 0..7
    const int bn   = nb * 256;
    const int row0 = blockIdx.y * 128;

    wmma::fragment<wmma::accumulator, 16, 16, 16, float> acc[4][4];
    gemm_mainloop<4>(Ahi + (size_t)row0 * GK, GK, Bhi + bn, GK, GK,
                     acc, smem, sb, tid, warp_m, warp_n);

    // ---- epilogue 1: bias add; write xh hi to global and fp16 tile to smem
    __half* xhs = reinterpret_cast<__half*>(smem);              // [128][264]
    float* st = reinterpret_cast<float*>(smem + ST_OFF) + wid * (16 * 64);
#pragma unroll
    for (int m = 0; m < 4; m++) {
#pragma unroll
        for (int n = 0; n < 4; n++)
            wmma::store_matrix_sync(st + n * 16, acc[m][n], 64, wmma::mem_row_major);
        __syncwarp();
        int r = lane >> 1, cs = (lane & 1) * 32;
        int lrow = warp_m * 64 + m * 16 + r;
        int lcol = warp_n * 64 + cs;
#pragma unroll
        for (int c = 0; c < 32; c += 4) {
            float4 v = *reinterpret_cast<float4*>(st + r * 64 + cs + c);
            v.x += bias[bn + lcol + c + 0];
            v.y += bias[bn + lcol + c + 1];
            v.z += bias[bn + lcol + c + 2];
            v.w += bias[bn + lcol + c + 3];
            uint2 u = make_uint2(pack4h(__float2half_rn(v.x), __float2half_rn(v.y)),
                                 pack4h(__float2half_rn(v.z), __float2half_rn(v.w)));
            *reinterpret_cast<uint2*>(Chi + (size_t)(row0 + lrow) * GK + bn + lcol + c) = u;
            *reinterpret_cast<uint2*>(xhs + lrow * TLDB + lcol + c) = u;
        }
        __syncwarp();
    }
    __syncthreads();

    // ---- gate GEMM: [128 x 256] @ wg2[nb] (256 x 256), K streamed in 4 chunks
    const __half* wgb = wg2 + (size_t)nb * 65536;
    char* gb = smem + GB_OFF;   // double buffer, 2 x B_BYTES

    // prefetch chunk 0
#pragma unroll
    for (int i = 0; i < 8; i++) {
        int u = tid + (i << 8);
        int r = u >> 5;
        int ch = u & 31;
        cp16(sb + GB_OFF + (uint32_t)(r * 528 + ch * 16),
             wgb + (size_t)r * 256 + ch * 8);
    }
    asm volatile("cp.async.commit_group;");

    wmma::fragment<wmma::accumulator, 16, 16, 16, float> acc2[4][4];
#pragma unroll
    for (int m = 0; m < 4; m++)
#pragma unroll
        for (int n = 0; n < 4; n++) wmma::fill_fragment(acc2[m][n], 0.0f);

    for (int chunk = 0; chunk < 4; ++chunk) {
        if (chunk < 3) {
            uint32_t dst = sb + GB_OFF + (uint32_t)((chunk + 1) & 1) * B_BYTES;
#pragma unroll
            for (int i = 0; i < 8; i++) {
                int u = tid + (i << 8);
                int r = u >> 5;
                int ch = u & 31;
                cp16(dst + (uint32_t)(r * 528 + ch * 16),
                     wgb + (size_t)((chunk + 1) * 64 + r) * 256 + ch * 8);
            }
            asm volatile("cp.async.commit_group;");
            asm volatile("cp.async.wait_group 1;");
        } else {
            asm volatile("cp.async.wait_group 0;");
        }
        __syncthreads();

        const __half* Bs = reinterpret_cast<const __half*>(gb + (chunk & 1) * B_BYTES);
#pragma unroll
        for (int kk = 0; kk < 64; kk += 16) {
            int kabs = chunk * 64 + kk;
            wmma::fragment<wmma::matrix_a, 16, 16, 16, __half, wmma::row_major> a[4];
            wmma::fragment<wmma::matrix_b, 16, 16, 16, __half, wmma::row_major> b[4];
#pragma unroll
            for (int m = 0; m < 4; m++)
                wmma::load_matrix_sync(a[m], xhs + (warp_m * 64 + m * 16) * TLDB + kabs, TLDB);
#pragma unroll
            for (int n = 0; n < 4; n++)
                wmma::load_matrix_sync(b[n], Bs + kk * TLDB + warp_n * 64 + n * 16, TLDB);
#pragma unroll
            for (int m = 0; m < 4; m++)
#pragma unroll
                for (int n = 0; n < 4; n++)
                    wmma::mma_sync(acc2[m][n], a[m], b[n], acc2[m][n]);
        }
        __syncthreads();
    }

    // ---- epilogue 2: gate bias + fp16 logits
#pragma unroll
    for (int m = 0; m < 4; m++) {
#pragma unroll
        for (int n = 0; n < 4; n++)
            wmma::store_matrix_sync(st + n * 16, acc2[m][n], 64, wmma::mem_row_major);
        __syncwarp();
        int r = lane >> 1, cs = (lane & 1) * 32;
        int lrow = warp_m * 64 + m * 16 + r;
        int gcol = warp_n * 64 + cs;     // 0..255
        bool isx = gcol < 128;
        int col = isx ? gcol : gcol - 128;
        const float* bp = (isx ? bgx : bga) + nb * 128 + col;
        __half* op = (isx ? gx : ga) + (size_t)(row0 + lrow) * DH + nb * 128 + col;
#pragma unroll
        for (int c = 0; c < 32; c += 4) {
            float4 v = *reinterpret_cast<float4*>(st + r * 64 + cs + c);
            v.x += bp[c + 0];
            v.y += bp[c + 1];
            v.z += bp[c + 2];
            v.w += bp[c + 3];
            *reinterpret_cast<uint2*>(op + c) =
                make_uint2(pack4h(__float2half_rn(v.x), __float2half_rn(v.y)),
                           pack4h(__float2half_rn(v.z), __float2half_rn(v.w)));
        }
        __syncwarp();
    }
}

// ---------------------------------------------------------------------------
// GEMM2: y = h @ W_out + b_out -> fp32. Grid (GK/256, MROWS/128).
// ---------------------------------------------------------------------------
__global__ __launch_bounds__(256, 1) void gemm_f32out_kernel(
    const __half* __restrict__ Ahi, const __half* __restrict__ Bhi,
    const float* __restrict__ bias, float* __restrict__ C)
{
    extern __shared__ __align__(256) char smem[];
    const uint32_t sb = smem_u32(smem);
    const int tid = threadIdx.x, wid = tid >> 5, lane = tid & 31;
    const int warp_m = wid >> 2, warp_n = wid & 3;
    const int row0 = blockIdx.y * 128;
    const int bn   = blockIdx.x * 256;

    wmma::fragment<wmma::accumulator, 16, 16, 16, float> acc[4][4];
    gemm_mainloop<4>(Ahi + (size_t)row0 * GK, GK, Bhi + bn, GK, GK,
                     acc, smem, sb, tid, warp_m, warp_n);

    float* st = reinterpret_cast<float*>(smem) + wid * (16 * 64);
#pragma unroll
    for (int m = 0; m < 4; m++) {
#pragma unroll
        for (int n = 0; n < 4; n++)
            wmma::store_matrix_sync(st + n * 16, acc[m][n], 64, wmma::mem_row_major);
        __syncwarp();
        int r = lane >> 1, cs = (lane & 1) * 32;
        int grow = row0 + warp_m * 64 + m * 16 + r;
        int gcol = bn + warp_n * 64 + cs;
#pragma unroll
        for (int c = 0; c < 32; c += 4) {
            float4 v = *reinterpret_cast<float4*>(st + r * 64 + cs + c);
            v.x += bias[gcol + c + 0];
            v.y += bias[gcol + c + 1];
            v.z += bias[gcol + c + 2];
            v.w += bias[gcol + c + 3];
            *reinterpret_cast<float4*>(C + (size_t)grow * GK + gcol + c) = v;
        }
        __syncwarp();
    }
}

// ---------------------------------------------------------------------------
// Fused pointwise + warp-parallel complex scan (fp16 in, h fp16 out).
// ---------------------------------------------------------------------------
__global__ __launch_bounds__(1024) void scanfused_kernel(
    const __half* __restrict__ xhhi,
    const __half* __restrict__ gxl, const __half* __restrict__ gal,
    const float* __restrict__ arp, const float* __restrict__ aip,
    __half* __restrict__ hout, float* __restrict__ h_last)
{
    __shared__ float sGx[32][33], sGa[32][33], sXr[32][33], sXi[32][33];
    __shared__ float sHr[32][33], sHi[32][33];

    const int b  = blockIdx.x >> 5;
    const int db = (blockIdx.x & 31) * 32;
    const int tid = threadIdx.x;
    const int w = tid >> 5;
    const int j = tid & 31;
    const int d = db + w;

    float av = arp[d];
    float sp = fmaxf(av, 0.f) + log1pf(expf(-fabsf(av)));   // softplus
    float aipd = aip[d];

    float cr = 0.f, ci = 0.f;

    for (int s0 = 0; s0 < S_SZ; s0 += 32) {
        size_t grow = (size_t)(b * S_SZ + s0 + w);
        sGx[w][j] = __half2float(gxl[grow * DH + db + j]);
        sGa[w][j] = __half2float(gal[grow * DH + db + j]);
        size_t xb = grow * DHID + db + j;
        sXr[w][j] = __half2float(xhhi[xb]);
        sXi[w][j] = __half2float(xhhi[xb + DH]);
        __syncthreads();

        float gx_s = 1.f / (1.f + expf(-sGx[j][w]));
        float ga_s = 1.f / (1.f + expf(-sGa[j][w]));
        float log_a = -8.f * ga_s * sp;
        float mag = expf(log_a);
        float sn, cs;
        sincosf(aipd * ga_s, &sn, &cs);
        float ar = mag * cs;
        float ai = mag * sn;
        float nrm = sqrtf(fmaxf(1.f - mag * mag, 0.f));
        float scale = gx_s * nrm;
        float xr = scale * sXr[j][w];
        float xi = scale * sXi[j][w];

#pragma unroll
        for (int off = 1; off < 32; off <<= 1) {
            float p_ar = __shfl_up_sync(0xffffffffu, ar, off);
            float p_ai = __shfl_up_sync(0xffffffffu, ai, off);
            float p_xr = __shfl_up_sync(0xffffffffu, xr, off);
            float p_xi = __shfl_up_sync(0xffffffffu, xi, off);
            if (j >= off) {
                float nar = ar * p_ar - ai * p_ai;
                float nai = ar * p_ai + ai * p_ar;
                float nxr = ar * p_xr - ai * p_xi + xr;
                float nxi = ar * p_xi + ai * p_xr + xi;
                ar = nar; ai = nai; xr = nxr; xi = nxi;
            }
        }

        float hr  = fmaf(ar, cr, fmaf(-ai, ci, xr));
        float hi_ = fmaf(ar, ci, fmaf(ai, cr, xi));
        cr = __shfl_sync(0xffffffffu, hr, 31);
        ci = __shfl_sync(0xffffffffu, hi_, 31);

        sHr[j][w] = hr;
        sHi[j][w] = hi_;
        __syncthreads();

        size_t orow = grow * (size_t)DHID;
        hout[orow + db + j]      = __float2half_rn(sHr[w][j]);
        hout[orow + DH + db + j] = __float2half_rn(sHi[w][j]);
    }

    if (j == 0) {
        h_last[(size_t)b * DHID + d]      = cr;
        h_last[(size_t)b * DHID + DH + d] = ci;
    }
}

// ---------------------------------------------------------------------------
// Launch
// ---------------------------------------------------------------------------
extern "C" void kernel_launch(void* const* d_in, const int* in_sizes, int n_in,
                              void* d_out, int out_size)
{
    const float* x     = (const float*)d_in[0];
    const float* arp   = (const float*)d_in[1];
    const float* aip   = (const float*)d_in[2];
    const float* W_in  = (const float*)d_in[3];
    const float* b_in  = (const float*)d_in[4];
    const float* Wgx   = (const float*)d_in[5];
    const float* bgx   = (const float*)d_in[6];
    const float* Wga   = (const float*)d_in[7];
    const float* bga   = (const float*)d_in[8];
    const float* W_out = (const float*)d_in[9];
    const float* b_out = (const float*)d_in[10];

    float* y = (float*)d_out;
    float* h_last = (float*)d_out + ((size_t)out_size - (size_t)B_SZ * DHID);

    __half *gx, *ga, *xsp, *h, *xhhi, *win, *wout, *wg2;
    cudaGetSymbolAddress((void**)&gx,   g_gx);
    cudaGetSymbolAddress((void**)&ga,   g_ga);
    cudaGetSymbolAddress((void**)&xsp,  g_xsp);
    cudaGetSymbolAddress((void**)&h,    g_h);
    cudaGetSymbolAddress((void**)&xhhi, g_xhhi);
    cudaGetSymbolAddress((void**)&win,  g_win);
    cudaGetSymbolAddress((void**)&wout, g_wout);
    cudaGetSymbolAddress((void**)&wg2,  g_wg2);

    cudaFuncSetAttribute(gemm1_fused_kernel,
                         cudaFuncAttributeMaxDynamicSharedMemorySize, SMEM_BIG);
    cudaFuncSetAttribute(gemm_f32out_kernel,
                         cudaFuncAttributeMaxDynamicSharedMemorySize, SMEM_BIG);

    const size_t nx4 = (size_t)MROWS * GK / 4;
    const size_t nw4 = (size_t)GK * GK / 4;

    // 0) conversions (independent)
    cvt_hi16_kernel<<<(unsigned)((nx4 + 255) / 256), 256>>>(
        (const float4*)x, (uint2*)xsp, nx4);
    cvt_hi16_kernel<<<(unsigned)((nw4 + 255) / 256), 256>>>(
        (const float4*)W_in, (uint2*)win, nw4);
    cvt_hi16_kernel<<<(unsigned)((nw4 + 255) / 256), 256>>>(
        (const float4*)W_out, (uint2*)wout, nw4);
    cvt_gatew_kernel<<<(NB * 256 * 256) / 256, 256>>>(Wgx, Wga, wg2);

    // 1+2) fused: xh = x @ W_in + b_in (hi out) AND gate logits
    gemm1_fused_kernel<<<dim3(NB, MROWS / 128), 256, SMEM_BIG>>>(
        xsp, win, b_in, wg2, bgx, bga, xhhi, gx, ga);

    // 3+4) fused pointwise + warp scan; writes h as fp16 hi
    scanfused_kernel<<<B_SZ * (DH / 32), 1024>>>(
        xhhi, gx, ga, arp, aip, h, h_last);

    // 5) y = h @ W_out + b_out
    gemm_f32out_kernel<<<dim3(GK / 256, MROWS / 128), 256, SMEM_BIG>>>(
        h, wout, b_out, y);
}

// round 12
// speedup vs baseline: 6.4133x; 1.0086x over previous
#include <cuda_runtime.h>
#include <cuda_fp16.h>
#include <mma.h>
#include <math.h>
#include <stdint.h>

using namespace nvcuda;

// Problem dims (fixed by the dataset)
#define NB     8
#define B_SZ   4
#define S_SZ   4096
#define DIN    2048
#define DHID   2048
#define DH     1024
#define MROWS  (B_SZ * S_SZ)   // 16384
#define GK     2048            // K (and N) for both big GEMMs

// wmma GEMM tiling: CTA 128x256, BK=64, warp tile 64x64 (8 warps: 2m x 4n)
#define TLDA 72      // A smem stride (halves): 144B
#define TLDB 264     // B smem stride (halves): 528B (256 cols + 8 pad)
#define A_BYTES (128 * TLDA * 2)     // 18432
#define B_BYTES (64 * TLDB * 2)      // 33792
#define STAGE   (A_BYTES + B_BYTES)  // 52224
#define SMEM_BIG (4 * STAGE)         // 208896

// post-mainloop layout inside smem (fused GEMM1):
#define XHS_BYTES (128 * TLDB * 2)        // 67584: xh tile fp16 [128][264]
#define ST_OFF    XHS_BYTES               // fp32 staging (8 warps * 16*64*4 = 32KB)
#define GB_OFF    (XHS_BYTES + 32768)     // gate B double buffer (2 * 33792)

// ---------------------------------------------------------------------------
// Scratch (device globals -- no allocation allowed in kernel_launch)
// ---------------------------------------------------------------------------
__device__ __align__(256) __half g_gx  [(size_t)MROWS * DH];    // gate_x logits
__device__ __align__(256) __half g_ga  [(size_t)MROWS * DH];    // gate_a logits
__device__ __align__(256) __half g_xsp [(size_t)MROWS * DIN];   // x hi
__device__ __align__(256) __half g_h   [(size_t)MROWS * DHID];  // h hi
__device__ __align__(256) __half g_xhhi[(size_t)MROWS * DHID];  // xh hi
__device__ __align__(256) __half g_win [(size_t)GK * GK];       // W_in hi
__device__ __align__(256) __half g_wout[(size_t)GK * GK];       // W_out hi
__device__ __align__(256) __half g_wg2 [(size_t)NB * 256 * 256]; // [Wgx|Wga]

// ---------------------------------------------------------------------------
// helpers
// ---------------------------------------------------------------------------
__device__ __forceinline__ void cp16(uint32_t s, const void* g) {
    asm volatile("cp.async.cg.shared.global [%0], [%1], 16;" :: "r"(s), "l"(g));
}
__device__ __forceinline__ uint32_t smem_u32(const void* p) {
    uint32_t a;
    asm("{ .reg .u64 t; cvta.to.shared.u64 t, %1; cvt.u32.u64 %0, t; }"
        : "=r"(a) : "l"(p));
    return a;
}
__device__ __forceinline__ uint32_t pack4h(__half a, __half b) {
    __half2 h2 = {a, b};
    return *reinterpret_cast<unsigned*>(&h2);
}

// ---------------------------------------------------------------------------
// Converters
// ---------------------------------------------------------------------------
__global__ __launch_bounds__(256) void cvt_hi16_kernel(
    const float4* __restrict__ in, uint2* __restrict__ hi, size_t n4)
{
    size_t i = (size_t)blockIdx.x * 256 + threadIdx.x;
    if (i >= n4) return;
    float4 v = in[i];
    hi[i] = make_uint2(pack4h(__float2half_rn(v.x), __float2half_rn(v.y)),
                       pack4h(__float2half_rn(v.z), __float2half_rn(v.w)));
}

// Pack gate weights: wg2[nb][k][c] = c<128 ? Wgx[nb][k][c] : Wga[nb][k][c-128]
__global__ __launch_bounds__(256) void cvt_gatew_kernel(
    const float* __restrict__ Wgx, const float* __restrict__ Wga,
    __half* __restrict__ out)
{
    int i = blockIdx.x * 256 + threadIdx.x;
    int c  = i & 255;
    int k  = (i >> 8) & 255;
    int nb = i >> 16;
    float v = (c < 128) ? Wgx[nb * 32768 + k * 128 + c]
                        : Wga[nb * 32768 + k * 128 + (c - 128)];
    out[i] = __float2half_rn(v);
}

// ---------------------------------------------------------------------------
// Shared mainloop: CTA tile 128x256, BK=64, NSTAGE-deep cp.async pipeline.
// ---------------------------------------------------------------------------
__device__ __forceinline__ void load_stage(
    const __half* __restrict__ A, int lda,
    const __half* __restrict__ B, int ldb,
    int kt, uint32_t base, int tid)
{
#pragma unroll
    for (int i = 0; i < 4; i++) {            // A: 128 rows x 128B
        int u = tid + (i << 8);
        int r = u >> 3;
        int ch = u & 7;
        cp16(base + (uint32_t)(r * 144 + ch * 16),
             A + (size_t)r * lda + kt + ch * 8);
    }
#pragma unroll
    for (int i = 0; i < 8; i++) {            // B: 64 rows x 512B
        int u = tid + (i << 8);
        int r = u >> 5;
        int ch = u & 31;
        cp16(base + A_BYTES + (uint32_t)(r * 528 + ch * 16),
             B + (size_t)(kt + r) * ldb + ch * 8);
    }
}

template<int NSTAGE>
__device__ __forceinline__ void gemm_mainloop(
    const __half* __restrict__ A, int lda,
    const __half* __restrict__ B, int ldb, int K,
    wmma::fragment<wmma::accumulator, 16, 16, 16, float> (&acc)[4][4],
    char* smem, uint32_t sb, int tid, int warp_m, int warp_n)
{
#pragma unroll
    for (int m = 0; m < 4; m++)
#pragma unroll
        for (int n = 0; n < 4; n++) wmma::fill_fragment(acc[m][n], 0.0f);

    const int nIter = K / 64;
#pragma unroll
    for (int s = 0; s < NSTAGE - 1; s++) {
        load_stage(A, lda, B, ldb, s * 64, sb + (uint32_t)s * STAGE, tid);
        asm volatile("cp.async.commit_group;");
    }

    for (int it = 0; it < nIter; ++it) {
        if (it + NSTAGE - 2 < nIter)
            asm volatile("cp.async.wait_group %0;" :: "n"(NSTAGE - 2));
        else
            asm volatile("cp.async.wait_group 0;");
        __syncthreads();
        if (it + NSTAGE - 1 < nIter) {
            load_stage(A, lda, B, ldb, (it + NSTAGE - 1) * 64,
                       sb + (uint32_t)((it + NSTAGE - 1) % NSTAGE) * STAGE, tid);
            asm volatile("cp.async.commit_group;");
        }

        char* stg = smem + (it % NSTAGE) * STAGE;
        const __half* As = reinterpret_cast<const __half*>(stg);
        const __half* Bs = reinterpret_cast<const __half*>(stg + A_BYTES);

#pragma unroll
        for (int kk = 0; kk < 64; kk += 16) {
            wmma::fragment<wmma::matrix_a, 16, 16, 16, __half, wmma::row_major> a[4];
            wmma::fragment<wmma::matrix_b, 16, 16, 16, __half, wmma::row_major> b[4];
#pragma unroll
            for (int m = 0; m < 4; m++)
                wmma::load_matrix_sync(a[m], As + (warp_m * 64 + m * 16) * TLDA + kk, TLDA);
#pragma unroll
            for (int n = 0; n < 4; n++)
                wmma::load_matrix_sync(b[n], Bs + kk * TLDB + warp_n * 64 + n * 16, TLDB);
#pragma unroll
            for (int m = 0; m < 4; m++)
#pragma unroll
                for (int n = 0; n < 4; n++)
                    wmma::mma_sync(acc[m][n], a[m], b[n], acc[m][n]);
        }
    }
    __syncthreads();
}

// ---------------------------------------------------------------------------
// Fused GEMM1 + gate GEMM.
// ---------------------------------------------------------------------------
__global__ __launch_bounds__(256, 1) void gemm1_fused_kernel(
    const __half* __restrict__ Ahi, const __half* __restrict__ Bhi,
    const float* __restrict__ bias,
    const __half* __restrict__ wg2,
    const float* __restrict__ bgx, const float* __restrict__ bga,
    __half* __restrict__ Chi,
    __half* __restrict__ gx, __half* __restrict__ ga)
{
    extern __shared__ __align__(256) char smem[];
    const uint32_t sb = smem_u32(smem);
    const int tid = threadIdx.x, wid = tid >> 5, lane = tid & 31;
    const int warp_m = wid >> 2, warp_n = wid & 3;
    const int nb   = blockIdx.x;          // 0..7
    const int bn   = nb * 256;
    const int row0 = blockIdx.y * 128;

    wmma::fragment<wmma::accumulator, 16, 16, 16, float> acc[4][4];
    gemm_mainloop<4>(Ahi + (size_t)row0 * GK, GK, Bhi + bn, GK, GK,
                     acc, smem, sb, tid, warp_m, warp_n);

    // ---- epilogue 1: bias add; write xh hi to global and fp16 tile to smem
    __half* xhs = reinterpret_cast<__half*>(smem);              // [128][264]
    float* st = reinterpret_cast<float*>(smem + ST_OFF) + wid * (16 * 64);
#pragma unroll
    for (int m = 0; m < 4; m++) {
#pragma unroll
        for (int n = 0; n < 4; n++)
            wmma::store_matrix_sync(st + n * 16, acc[m][n], 64, wmma::mem_row_major);
        __syncwarp();
        int r = lane >> 1, cs = (lane & 1) * 32;
        int lrow = warp_m * 64 + m * 16 + r;
        int lcol = warp_n * 64 + cs;
#pragma unroll
        for (int c = 0; c < 32; c += 4) {
            float4 v = *reinterpret_cast<float4*>(st + r * 64 + cs + c);
            v.x += bias[bn + lcol + c + 0];
            v.y += bias[bn + lcol + c + 1];
            v.z += bias[bn + lcol + c + 2];
            v.w += bias[bn + lcol + c + 3];
            uint2 u = make_uint2(pack4h(__float2half_rn(v.x), __float2half_rn(v.y)),
                                 pack4h(__float2half_rn(v.z), __float2half_rn(v.w)));
            *reinterpret_cast<uint2*>(Chi + (size_t)(row0 + lrow) * GK + bn + lcol + c) = u;
            *reinterpret_cast<uint2*>(xhs + lrow * TLDB + lcol + c) = u;
        }
        __syncwarp();
    }
    __syncthreads();

    // ---- gate GEMM: [128 x 256] @ wg2[nb] (256 x 256), K streamed in 4 chunks
    const __half* wgb = wg2 + (size_t)nb * 65536;
    char* gb = smem + GB_OFF;   // double buffer, 2 x B_BYTES

#pragma unroll
    for (int i = 0; i < 8; i++) {
        int u = tid + (i << 8);
        int r = u >> 5;
        int ch = u & 31;
        cp16(sb + GB_OFF + (uint32_t)(r * 528 + ch * 16),
             wgb + (size_t)r * 256 + ch * 8);
    }
    asm volatile("cp.async.commit_group;");

    wmma::fragment<wmma::accumulator, 16, 16, 16, float> acc2[4][4];
#pragma unroll
    for (int m = 0; m < 4; m++)
#pragma unroll
        for (int n = 0; n < 4; n++) wmma::fill_fragment(acc2[m][n], 0.0f);

    for (int chunk = 0; chunk < 4; ++chunk) {
        if (chunk < 3) {
            uint32_t dst = sb + GB_OFF + (uint32_t)((chunk + 1) & 1) * B_BYTES;
#pragma unroll
            for (int i = 0; i < 8; i++) {
                int u = tid + (i << 8);
                int r = u >> 5;
                int ch = u & 31;
                cp16(dst + (uint32_t)(r * 528 + ch * 16),
                     wgb + (size_t)((chunk + 1) * 64 + r) * 256 + ch * 8);
            }
            asm volatile("cp.async.commit_group;");
            asm volatile("cp.async.wait_group 1;");
        } else {
            asm volatile("cp.async.wait_group 0;");
        }
        __syncthreads();

        const __half* Bs = reinterpret_cast<const __half*>(gb + (chunk & 1) * B_BYTES);
#pragma unroll
        for (int kk = 0; kk < 64; kk += 16) {
            int kabs = chunk * 64 + kk;
            wmma::fragment<wmma::matrix_a, 16, 16, 16, __half, wmma::row_major> a[4];
            wmma::fragment<wmma::matrix_b, 16, 16, 16, __half, wmma::row_major> b[4];
#pragma unroll
            for (int m = 0; m < 4; m++)
                wmma::load_matrix_sync(a[m], xhs + (warp_m * 64 + m * 16) * TLDB + kabs, TLDB);
#pragma unroll
            for (int n = 0; n < 4; n++)
                wmma::load_matrix_sync(b[n], Bs + kk * TLDB + warp_n * 64 + n * 16, TLDB);
#pragma unroll
            for (int m = 0; m < 4; m++)
#pragma unroll
                for (int n = 0; n < 4; n++)
                    wmma::mma_sync(acc2[m][n], a[m], b[n], acc2[m][n]);
        }
        __syncthreads();
    }

    // ---- epilogue 2: gate bias + fp16 logits
#pragma unroll
    for (int m = 0; m < 4; m++) {
#pragma unroll
        for (int n = 0; n < 4; n++)
            wmma::store_matrix_sync(st + n * 16, acc2[m][n], 64, wmma::mem_row_major);
        __syncwarp();
        int r = lane >> 1, cs = (lane & 1) * 32;
        int lrow = warp_m * 64 + m * 16 + r;
        int gcol = warp_n * 64 + cs;     // 0..255
        bool isx = gcol < 128;
        int col = isx ? gcol : gcol - 128;
        const float* bp = (isx ? bgx : bga) + nb * 128 + col;
        __half* op = (isx ? gx : ga) + (size_t)(row0 + lrow) * DH + nb * 128 + col;
#pragma unroll
        for (int c = 0; c < 32; c += 4) {
            float4 v = *reinterpret_cast<float4*>(st + r * 64 + cs + c);
            v.x += bp[c + 0];
            v.y += bp[c + 1];
            v.z += bp[c + 2];
            v.w += bp[c + 3];
            *reinterpret_cast<uint2*>(op + c) =
                make_uint2(pack4h(__float2half_rn(v.x), __float2half_rn(v.y)),
                           pack4h(__float2half_rn(v.z), __float2half_rn(v.w)));
        }
        __syncwarp();
    }
}

// ---------------------------------------------------------------------------
// GEMM2: y = h @ W_out + b_out -> fp32. Grid (GK/256, MROWS/128).
// ---------------------------------------------------------------------------
__global__ __launch_bounds__(256, 1) void gemm_f32out_kernel(
    const __half* __restrict__ Ahi, const __half* __restrict__ Bhi,
    const float* __restrict__ bias, float* __restrict__ C)
{
    extern __shared__ __align__(256) char smem[];
    const uint32_t sb = smem_u32(smem);
    const int tid = threadIdx.x, wid = tid >> 5, lane = tid & 31;
    const int warp_m = wid >> 2, warp_n = wid & 3;
    const int row0 = blockIdx.y * 128;
    const int bn   = blockIdx.x * 256;

    wmma::fragment<wmma::accumulator, 16, 16, 16, float> acc[4][4];
    gemm_mainloop<4>(Ahi + (size_t)row0 * GK, GK, Bhi + bn, GK, GK,
                     acc, smem, sb, tid, warp_m, warp_n);

    float* st = reinterpret_cast<float*>(smem) + wid * (16 * 64);
#pragma unroll
    for (int m = 0; m < 4; m++) {
#pragma unroll
        for (int n = 0; n < 4; n++)
            wmma::store_matrix_sync(st + n * 16, acc[m][n], 64, wmma::mem_row_major);
        __syncwarp();
        int r = lane >> 1, cs = (lane & 1) * 32;
        int grow = row0 + warp_m * 64 + m * 16 + r;
        int gcol = bn + warp_n * 64 + cs;
#pragma unroll
        for (int c = 0; c < 32; c += 4) {
            float4 v = *reinterpret_cast<float4*>(st + r * 64 + cs + c);
            v.x += bias[gcol + c + 0];
            v.y += bias[gcol + c + 1];
            v.z += bias[gcol + c + 2];
            v.w += bias[gcol + c + 3];
            *reinterpret_cast<float4*>(C + (size_t)grow * GK + gcol + c) = v;
        }
        __syncwarp();
    }
}

// ---------------------------------------------------------------------------
// Fused pointwise + warp-parallel complex scan (fp16 in, h fp16 out).
// Pointwise uses MUFU intrinsics explicitly (independent of -use_fast_math).
// ---------------------------------------------------------------------------
__global__ __launch_bounds__(1024) void scanfused_kernel(
    const __half* __restrict__ xhhi,
    const __half* __restrict__ gxl, const __half* __restrict__ gal,
    const float* __restrict__ arp, const float* __restrict__ aip,
    __half* __restrict__ hout, float* __restrict__ h_last)
{
    __shared__ float sGx[32][33], sGa[32][33], sXr[32][33], sXi[32][33];
    __shared__ float sHr[32][33], sHi[32][33];

    const int b  = blockIdx.x >> 5;
    const int db = (blockIdx.x & 31) * 32;
    const int tid = threadIdx.x;
    const int w = tid >> 5;
    const int j = tid & 31;
    const int d = db + w;

    float av = arp[d];
    float sp = fmaxf(av, 0.f) + log1pf(__expf(-fabsf(av)));   // softplus
    float aipd = aip[d];

    float cr = 0.f, ci = 0.f;

    for (int s0 = 0; s0 < S_SZ; s0 += 32) {
        size_t grow = (size_t)(b * S_SZ + s0 + w);
        sGx[w][j] = __half2float(gxl[grow * DH + db + j]);
        sGa[w][j] = __half2float(gal[grow * DH + db + j]);
        size_t xb = grow * DHID + db + j;
        sXr[w][j] = __half2float(xhhi[xb]);
        sXi[w][j] = __half2float(xhhi[xb + DH]);
        __syncthreads();

        // MUFU-intrinsic pointwise math
        float gx_s = __fdividef(1.f, 1.f + __expf(-sGx[j][w]));
        float ga_s = __fdividef(1.f, 1.f + __expf(-sGa[j][w]));
        float log_a = -8.f * ga_s * sp;
        float mag = __expf(log_a);
        float th = aipd * ga_s;
        float sn = __sinf(th);
        float cs = __cosf(th);
        float ar = mag * cs;
        float ai = mag * sn;
        float nrm = sqrtf(fmaxf(1.f - mag * mag, 0.f));
        float scale = gx_s * nrm;
        float xr = scale * sXr[j][w];
        float xi = scale * sXi[j][w];

#pragma unroll
        for (int off = 1; off < 32; off <<= 1) {
            float p_ar = __shfl_up_sync(0xffffffffu, ar, off);
            float p_ai = __shfl_up_sync(0xffffffffu, ai, off);
            float p_xr = __shfl_up_sync(0xffffffffu, xr, off);
            float p_xi = __shfl_up_sync(0xffffffffu, xi, off);
            if (j >= off) {
                float nar = ar * p_ar - ai * p_ai;
                float nai = ar * p_ai + ai * p_ar;
                float nxr = ar * p_xr - ai * p_xi + xr;
                float nxi = ar * p_xi + ai * p_xr + xi;
                ar = nar; ai = nai; xr = nxr; xi = nxi;
            }
        }

        float hr  = fmaf(ar, cr, fmaf(-ai, ci, xr));
        float hi_ = fmaf(ar, ci, fmaf(ai, cr, xi));
        cr = __shfl_sync(0xffffffffu, hr, 31);
        ci = __shfl_sync(0xffffffffu, hi_, 31);

        sHr[j][w] = hr;
        sHi[j][w] = hi_;
        __syncthreads();

        size_t orow = grow * (size_t)DHID;
        hout[orow + db + j]      = __float2half_rn(sHr[w][j]);
        hout[orow + DH + db + j] = __float2half_rn(sHi[w][j]);
    }

    if (j == 0) {
        h_last[(size_t)b * DHID + d]      = cr;
        h_last[(size_t)b * DHID + DH + d] = ci;
    }
}

// ---------------------------------------------------------------------------
// Launch
// ---------------------------------------------------------------------------
extern "C" void kernel_launch(void* const* d_in, const int* in_sizes, int n_in,
                              void* d_out, int out_size)
{
    const float* x     = (const float*)d_in[0];
    const float* arp   = (const float*)d_in[1];
    const float* aip   = (const float*)d_in[2];
    const float* W_in  = (const float*)d_in[3];
    const float* b_in  = (const float*)d_in[4];
    const float* Wgx   = (const float*)d_in[5];
    const float* bgx   = (const float*)d_in[6];
    const float* Wga   = (const float*)d_in[7];
    const float* bga   = (const float*)d_in[8];
    const float* W_out = (const float*)d_in[9];
    const float* b_out = (const float*)d_in[10];

    float* y = (float*)d_out;
    float* h_last = (float*)d_out + ((size_t)out_size - (size_t)B_SZ * DHID);

    __half *gx, *ga, *xsp, *h, *xhhi, *win, *wout, *wg2;
    cudaGetSymbolAddress((void**)&gx,   g_gx);
    cudaGetSymbolAddress((void**)&ga,   g_ga);
    cudaGetSymbolAddress((void**)&xsp,  g_xsp);
    cudaGetSymbolAddress((void**)&h,    g_h);
    cudaGetSymbolAddress((void**)&xhhi, g_xhhi);
    cudaGetSymbolAddress((void**)&win,  g_win);
    cudaGetSymbolAddress((void**)&wout, g_wout);
    cudaGetSymbolAddress((void**)&wg2,  g_wg2);

    cudaFuncSetAttribute(gemm1_fused_kernel,
                         cudaFuncAttributeMaxDynamicSharedMemorySize, SMEM_BIG);
    cudaFuncSetAttribute(gemm_f32out_kernel,
                         cudaFuncAttributeMaxDynamicSharedMemorySize, SMEM_BIG);

    const size_t nx4 = (size_t)MROWS * GK / 4;
    const size_t nw4 = (size_t)GK * GK / 4;

    // 0) conversions (independent)
    cvt_hi16_kernel<<<(unsigned)((nx4 + 255) / 256), 256>>>(
        (const float4*)x, (uint2*)xsp, nx4);
    cvt_hi16_kernel<<<(unsigned)((nw4 + 255) / 256), 256>>>(
        (const float4*)W_in, (uint2*)win, nw4);
    cvt_hi16_kernel<<<(unsigned)((nw4 + 255) / 256), 256>>>(
        (const float4*)W_out, (uint2*)wout, nw4);
    cvt_gatew_kernel<<<(NB * 256 * 256) / 256, 256>>>(Wgx, Wga, wg2);

    // 1+2) fused: xh = x @ W_in + b_in (hi out) AND gate logits
    gemm1_fused_kernel<<<dim3(NB, MROWS / 128), 256, SMEM_BIG>>>(
        xsp, win, b_in, wg2, bgx, bga, xhhi, gx, ga);

    // 3+4) fused pointwise + warp scan; writes h as fp16 hi
    scanfused_kernel<<<B_SZ * (DH / 32), 1024>>>(
        xhhi, gx, ga, arp, aip, h, h_last);

    // 5) y = h @ W_out + b_out
    gemm_f32out_kernel<<<dim3(GK / 256, MROWS / 128), 256, SMEM_BIG>>>(
        h, wout, b_out, y);
}

// round 13
// speedup vs baseline: 6.6591x; 1.0383x over previous
#include <cuda_runtime.h>
#include <cuda_fp16.h>
#include <mma.h>
#include <math.h>
#include <stdint.h>

using namespace nvcuda;

// Problem dims (fixed by the dataset)
#define NB     8
#define B_SZ   4
#define S_SZ   4096
#define DIN    2048
#define DHID   2048
#define DH     1024
#define MROWS  (B_SZ * S_SZ)   // 16384
#define GK     2048            // K (and N) for both big GEMMs

// GEMM1 tiling: CTA 128x256, BK=64, warp tile 64x64 (8 warps: 2m x 4n)
#define TLDA 72      // A smem stride (halves): 144B
#define TLDB 264     // B smem stride (halves): 528B (256 cols + 8 pad)
#define A_BYTES (128 * TLDA * 2)     // 18432
#define B_BYTES (64 * TLDB * 2)      // 33792
#define STAGE   (A_BYTES + B_BYTES)  // 52224
#define SMEM_BIG (4 * STAGE)         // 208896

// post-mainloop layout inside smem (fused GEMM1):
#define XHS_BYTES (128 * TLDB * 2)        // 67584: xh tile fp16 [128][264]
#define ST_OFF    XHS_BYTES               // fp32 staging (8 warps * 16*64*4 = 32KB)
#define GB_OFF    (XHS_BYTES + 32768)     // gate B double buffer (2 * 33792)

// GEMM2 tiling: CTA 128x128, BK=64, 2 CTAs/SM, warp tile 64x32 (2m x 4n)
#define T2LDB 136                      // B smem stride (halves): 272B
#define B2_BYTES (64 * T2LDB * 2)      // 17408
#define STAGE2   (A_BYTES + B2_BYTES)  // 35840
#define SMEM_G2  (3 * STAGE2)          // 107520

// ---------------------------------------------------------------------------
// Scratch (device globals -- no allocation allowed in kernel_launch)
// ---------------------------------------------------------------------------
__device__ __align__(256) __half g_gx  [(size_t)MROWS * DH];    // gate_x logits
__device__ __align__(256) __half g_ga  [(size_t)MROWS * DH];    // gate_a logits
__device__ __align__(256) __half g_xsp [(size_t)MROWS * DIN];   // x hi
__device__ __align__(256) __half g_h   [(size_t)MROWS * DHID];  // h hi
__device__ __align__(256) __half g_xhhi[(size_t)MROWS * DHID];  // xh hi
__device__ __align__(256) __half g_win [(size_t)GK * GK];       // W_in hi
__device__ __align__(256) __half g_wout[(size_t)GK * GK];       // W_out hi
__device__ __align__(256) __half g_wg2 [(size_t)NB * 256 * 256]; // [Wgx|Wga]

// ---------------------------------------------------------------------------
// helpers
// ---------------------------------------------------------------------------
__device__ __forceinline__ void cp16(uint32_t s, const void* g) {
    asm volatile("cp.async.cg.shared.global [%0], [%1], 16;" :: "r"(s), "l"(g));
}
__device__ __forceinline__ uint32_t smem_u32(const void* p) {
    uint32_t a;
    asm("{ .reg .u64 t; cvta.to.shared.u64 t, %1; cvt.u32.u64 %0, t; }"
        : "=r"(a) : "l"(p));
    return a;
}
__device__ __forceinline__ uint32_t pack4h(__half a, __half b) {
    __half2 h2 = {a, b};
    return *reinterpret_cast<unsigned*>(&h2);
}

// ---------------------------------------------------------------------------
// Converters
// ---------------------------------------------------------------------------
__global__ __launch_bounds__(256) void cvt_hi16_kernel(
    const float4* __restrict__ in, uint2* __restrict__ hi, size_t n4)
{
    size_t i = (size_t)blockIdx.x * 256 + threadIdx.x;
    if (i >= n4) return;
    float4 v = in[i];
    hi[i] = make_uint2(pack4h(__float2half_rn(v.x), __float2half_rn(v.y)),
                       pack4h(__float2half_rn(v.z), __float2half_rn(v.w)));
}

// Pack gate weights: wg2[nb][k][c] = c<128 ? Wgx[nb][k][c] : Wga[nb][k][c-128]
__global__ __launch_bounds__(256) void cvt_gatew_kernel(
    const float* __restrict__ Wgx, const float* __restrict__ Wga,
    __half* __restrict__ out)
{
    int i = blockIdx.x * 256 + threadIdx.x;
    int c  = i & 255;
    int k  = (i >> 8) & 255;
    int nb = i >> 16;
    float v = (c < 128) ? Wgx[nb * 32768 + k * 128 + c]
                        : Wga[nb * 32768 + k * 128 + (c - 128)];
    out[i] = __float2half_rn(v);
}

// ---------------------------------------------------------------------------
// GEMM1 mainloop (CTA tile 128x256, NSTAGE-deep cp.async pipeline).
// ---------------------------------------------------------------------------
__device__ __forceinline__ void load_stage(
    const __half* __restrict__ A, int lda,
    const __half* __restrict__ B, int ldb,
    int kt, uint32_t base, int tid)
{
#pragma unroll
    for (int i = 0; i < 4; i++) {            // A: 128 rows x 128B
        int u = tid + (i << 8);
        int r = u >> 3;
        int ch = u & 7;
        cp16(base + (uint32_t)(r * 144 + ch * 16),
             A + (size_t)r * lda + kt + ch * 8);
    }
#pragma unroll
    for (int i = 0; i < 8; i++) {            // B: 64 rows x 512B
        int u = tid + (i << 8);
        int r = u >> 5;
        int ch = u & 31;
        cp16(base + A_BYTES + (uint32_t)(r * 528 + ch * 16),
             B + (size_t)(kt + r) * ldb + ch * 8);
    }
}

template<int NSTAGE>
__device__ __forceinline__ void gemm_mainloop(
    const __half* __restrict__ A, int lda,
    const __half* __restrict__ B, int ldb, int K,
    wmma::fragment<wmma::accumulator, 16, 16, 16, float> (&acc)[4][4],
    char* smem, uint32_t sb, int tid, int warp_m, int warp_n)
{
#pragma unroll
    for (int m = 0; m < 4; m++)
#pragma unroll
        for (int n = 0; n < 4; n++) wmma::fill_fragment(acc[m][n], 0.0f);

    const int nIter = K / 64;
#pragma unroll
    for (int s = 0; s < NSTAGE - 1; s++) {
        load_stage(A, lda, B, ldb, s * 64, sb + (uint32_t)s * STAGE, tid);
        asm volatile("cp.async.commit_group;");
    }

    for (int it = 0; it < nIter; ++it) {
        if (it + NSTAGE - 2 < nIter)
            asm volatile("cp.async.wait_group %0;" :: "n"(NSTAGE - 2));
        else
            asm volatile("cp.async.wait_group 0;");
        __syncthreads();
        if (it + NSTAGE - 1 < nIter) {
            load_stage(A, lda, B, ldb, (it + NSTAGE - 1) * 64,
                       sb + (uint32_t)((it + NSTAGE - 1) % NSTAGE) * STAGE, tid);
            asm volatile("cp.async.commit_group;");
        }

        char* stg = smem + (it % NSTAGE) * STAGE;
        const __half* As = reinterpret_cast<const __half*>(stg);
        const __half* Bs = reinterpret_cast<const __half*>(stg + A_BYTES);

#pragma unroll
        for (int kk = 0; kk < 64; kk += 16) {
            wmma::fragment<wmma::matrix_a, 16, 16, 16, __half, wmma::row_major> a[4];
            wmma::fragment<wmma::matrix_b, 16, 16, 16, __half, wmma::row_major> b[4];
#pragma unroll
            for (int m = 0; m < 4; m++)
                wmma::load_matrix_sync(a[m], As + (warp_m * 64 + m * 16) * TLDA + kk, TLDA);
#pragma unroll
            for (int n = 0; n < 4; n++)
                wmma::load_matrix_sync(b[n], Bs + kk * TLDB + warp_n * 64 + n * 16, TLDB);
#pragma unroll
            for (int m = 0; m < 4; m++)
#pragma unroll
                for (int n = 0; n < 4; n++)
                    wmma::mma_sync(acc[m][n], a[m], b[n], acc[m][n]);
        }
    }
    __syncthreads();
}

// ---------------------------------------------------------------------------
// Fused GEMM1 + gate GEMM. Grid (NB, MROWS/128), 1 CTA/SM.
// ---------------------------------------------------------------------------
__global__ __launch_bounds__(256, 1) void gemm1_fused_kernel(
    const __half* __restrict__ Ahi, const __half* __restrict__ Bhi,
    const float* __restrict__ bias,
    const __half* __restrict__ wg2,
    const float* __restrict__ bgx, const float* __restrict__ bga,
    __half* __restrict__ Chi,
    __half* __restrict__ gx, __half* __restrict__ ga)
{
    extern __shared__ __align__(256) char smem[];
    const uint32_t sb = smem_u32(smem);
    const int tid = threadIdx.x, wid = tid >> 5, lane = tid & 31;
    const int warp_m = wid >> 2, warp_n = wid & 3;
    const int nb   = blockIdx.x;          // 0..7
    const int bn   = nb * 256;
    const int row0 = blockIdx.y * 128;

    wmma::fragment<wmma::accumulator, 16, 16, 16, float> acc[4][4];
    gemm_mainloop<4>(Ahi + (size_t)row0 * GK, GK, Bhi + bn, GK, GK,
                     acc, smem, sb, tid, warp_m, warp_n);

    // ---- epilogue 1: bias add; write xh hi to global and fp16 tile to smem
    __half* xhs = reinterpret_cast<__half*>(smem);              // [128][264]
    float* st = reinterpret_cast<float*>(smem + ST_OFF) + wid * (16 * 64);
#pragma unroll
    for (int m = 0; m < 4; m++) {
#pragma unroll
        for (int n = 0; n < 4; n++)
            wmma::store_matrix_sync(st + n * 16, acc[m][n], 64, wmma::mem_row_major);
        __syncwarp();
        int r = lane >> 1, cs = (lane & 1) * 32;
        int lrow = warp_m * 64 + m * 16 + r;
        int lcol = warp_n * 64 + cs;
#pragma unroll
        for (int c = 0; c < 32; c += 4) {
            float4 v = *reinterpret_cast<float4*>(st + r * 64 + cs + c);
            v.x += bias[bn + lcol + c + 0];
            v.y += bias[bn + lcol + c + 1];
            v.z += bias[bn + lcol + c + 2];
            v.w += bias[bn + lcol + c + 3];
            uint2 u = make_uint2(pack4h(__float2half_rn(v.x), __float2half_rn(v.y)),
                                 pack4h(__float2half_rn(v.z), __float2half_rn(v.w)));
            *reinterpret_cast<uint2*>(Chi + (size_t)(row0 + lrow) * GK + bn + lcol + c) = u;
            *reinterpret_cast<uint2*>(xhs + lrow * TLDB + lcol + c) = u;
        }
        __syncwarp();
    }
    __syncthreads();

    // ---- gate GEMM: [128 x 256] @ wg2[nb] (256 x 256), K streamed in 4 chunks
    const __half* wgb = wg2 + (size_t)nb * 65536;
    char* gb = smem + GB_OFF;   // double buffer, 2 x B_BYTES

#pragma unroll
    for (int i = 0; i < 8; i++) {
        int u = tid + (i << 8);
        int r = u >> 5;
        int ch = u & 31;
        cp16(sb + GB_OFF + (uint32_t)(r * 528 + ch * 16),
             wgb + (size_t)r * 256 + ch * 8);
    }
    asm volatile("cp.async.commit_group;");

    wmma::fragment<wmma::accumulator, 16, 16, 16, float> acc2[4][4];
#pragma unroll
    for (int m = 0; m < 4; m++)
#pragma unroll
        for (int n = 0; n < 4; n++) wmma::fill_fragment(acc2[m][n], 0.0f);

    for (int chunk = 0; chunk < 4; ++chunk) {
        if (chunk < 3) {
            uint32_t dst = sb + GB_OFF + (uint32_t)((chunk + 1) & 1) * B_BYTES;
#pragma unroll
            for (int i = 0; i < 8; i++) {
                int u = tid + (i << 8);
                int r = u >> 5;
                int ch = u & 31;
                cp16(dst + (uint32_t)(r * 528 + ch * 16),
                     wgb + (size_t)((chunk + 1) * 64 + r) * 256 + ch * 8);
            }
            asm volatile("cp.async.commit_group;");
            asm volatile("cp.async.wait_group 1;");
        } else {
            asm volatile("cp.async.wait_group 0;");
        }
        __syncthreads();

        const __half* Bs = reinterpret_cast<const __half*>(gb + (chunk & 1) * B_BYTES);
#pragma unroll
        for (int kk = 0; kk < 64; kk += 16) {
            int kabs = chunk * 64 + kk;
            wmma::fragment<wmma::matrix_a, 16, 16, 16, __half, wmma::row_major> a[4];
            wmma::fragment<wmma::matrix_b, 16, 16, 16, __half, wmma::row_major> b[4];
#pragma unroll
            for (int m = 0; m < 4; m++)
                wmma::load_matrix_sync(a[m], xhs + (warp_m * 64 + m * 16) * TLDB + kabs, TLDB);
#pragma unroll
            for (int n = 0; n < 4; n++)
                wmma::load_matrix_sync(b[n], Bs + kk * TLDB + warp_n * 64 + n * 16, TLDB);
#pragma unroll
            for (int m = 0; m < 4; m++)
#pragma unroll
                for (int n = 0; n < 4; n++)
                    wmma::mma_sync(acc2[m][n], a[m], b[n], acc2[m][n]);
        }
        __syncthreads();
    }

    // ---- epilogue 2: gate bias + fp16 logits
#pragma unroll
    for (int m = 0; m < 4; m++) {
#pragma unroll
        for (int n = 0; n < 4; n++)
            wmma::store_matrix_sync(st + n * 16, acc2[m][n], 64, wmma::mem_row_major);
        __syncwarp();
        int r = lane >> 1, cs = (lane & 1) * 32;
        int lrow = warp_m * 64 + m * 16 + r;
        int gcol = warp_n * 64 + cs;     // 0..255
        bool isx = gcol < 128;
        int col = isx ? gcol : gcol - 128;
        const float* bp = (isx ? bgx : bga) + nb * 128 + col;
        __half* op = (isx ? gx : ga) + (size_t)(row0 + lrow) * DH + nb * 128 + col;
#pragma unroll
        for (int c = 0; c < 32; c += 4) {
            float4 v = *reinterpret_cast<float4*>(st + r * 64 + cs + c);
            v.x += bp[c + 0];
            v.y += bp[c + 1];
            v.z += bp[c + 2];
            v.w += bp[c + 3];
            *reinterpret_cast<uint2*>(op + c) =
                make_uint2(pack4h(__float2half_rn(v.x), __float2half_rn(v.y)),
                           pack4h(__float2half_rn(v.z), __float2half_rn(v.w)));
        }
        __syncwarp();
    }
}

// ---------------------------------------------------------------------------
// GEMM2: y = h @ W_out + b_out -> fp32.
// CTA tile 128x128, NSTAGE=3, 2 CTAs/SM, warp tile 64x32 (2m x 4n).
// Grid (GK/128, MROWS/128) = (16, 128).
// ---------------------------------------------------------------------------
__global__ __launch_bounds__(256, 2) void gemm2_kernel(
    const __half* __restrict__ Ahi, const __half* __restrict__ Bhi,
    const float* __restrict__ bias, float* __restrict__ C)
{
    extern __shared__ __align__(256) char smem[];
    const uint32_t sb = smem_u32(smem);
    const int tid = threadIdx.x, wid = tid >> 5, lane = tid & 31;
    const int warp_m = wid >> 2;   // 0..1 (64-row slab)
    const int warp_n = wid & 3;    // 0..3 (32-col slab)
    const int row0 = blockIdx.y * 128;
    const int bn   = blockIdx.x * 128;

    const __half* A = Ahi + (size_t)row0 * GK;
    const __half* B = Bhi + bn;

    wmma::fragment<wmma::accumulator, 16, 16, 16, float> acc[4][2];
#pragma unroll
    for (int m = 0; m < 4; m++)
#pragma unroll
        for (int n = 0; n < 2; n++) wmma::fill_fragment(acc[m][n], 0.0f);

    // stage loader: A 128x128B (1024 chunks), B 64x256B (1024 chunks)
    auto load2 = [&](int kt, uint32_t base) {
#pragma unroll
        for (int i = 0; i < 4; i++) {
            int u = tid + (i << 8);
            int r = u >> 3;
            int ch = u & 7;
            cp16(base + (uint32_t)(r * 144 + ch * 16),
                 A + (size_t)r * GK + kt + ch * 8);
        }
#pragma unroll
        for (int i = 0; i < 4; i++) {
            int u = tid + (i << 8);
            int r = u >> 4;
            int ch = u & 15;
            cp16(base + A_BYTES + (uint32_t)(r * 272 + ch * 16),
                 B + (size_t)(kt + r) * GK + ch * 8);
        }
    };

    const int nIter = GK / 64;   // 32
#pragma unroll
    for (int s = 0; s < 2; s++) {
        load2(s * 64, sb + (uint32_t)s * STAGE2);
        asm volatile("cp.async.commit_group;");
    }

    for (int it = 0; it < nIter; ++it) {
        if (it + 1 < nIter) asm volatile("cp.async.wait_group 1;");
        else                asm volatile("cp.async.wait_group 0;");
        __syncthreads();
        if (it + 2 < nIter) {
            load2((it + 2) * 64, sb + (uint32_t)((it + 2) % 3) * STAGE2);
            asm volatile("cp.async.commit_group;");
        }

        char* stg = smem + (it % 3) * STAGE2;
        const __half* As = reinterpret_cast<const __half*>(stg);
        const __half* Bs = reinterpret_cast<const __half*>(stg + A_BYTES);

#pragma unroll
        for (int kk = 0; kk < 64; kk += 16) {
            wmma::fragment<wmma::matrix_a, 16, 16, 16, __half, wmma::row_major> a[4];
            wmma::fragment<wmma::matrix_b, 16, 16, 16, __half, wmma::row_major> b[2];
#pragma unroll
            for (int m = 0; m < 4; m++)
                wmma::load_matrix_sync(a[m], As + (warp_m * 64 + m * 16) * TLDA + kk, TLDA);
#pragma unroll
            for (int n = 0; n < 2; n++)
                wmma::load_matrix_sync(b[n], Bs + kk * T2LDB + warp_n * 32 + n * 16, T2LDB);
#pragma unroll
            for (int m = 0; m < 4; m++)
#pragma unroll
                for (int n = 0; n < 2; n++)
                    wmma::mma_sync(acc[m][n], a[m], b[n], acc[m][n]);
        }
    }
    __syncthreads();

    // Epilogue: per-warp smem stage (16x32 fp32), fp32 bias add.
    float* st = reinterpret_cast<float*>(smem) + wid * (16 * 32);
#pragma unroll
    for (int m = 0; m < 4; m++) {
        wmma::store_matrix_sync(st,      acc[m][0], 32, wmma::mem_row_major);
        wmma::store_matrix_sync(st + 16, acc[m][1], 32, wmma::mem_row_major);
        __syncwarp();
        int r  = lane >> 1;
        int cs = (lane & 1) * 16;
        int grow = row0 + warp_m * 64 + m * 16 + r;
        int gcol = bn + warp_n * 32 + cs;
#pragma unroll
        for (int c = 0; c < 16; c += 4) {
            float4 v = *reinterpret_cast<float4*>(st + r * 32 + cs + c);
            v.x += bias[gcol + c + 0];
            v.y += bias[gcol + c + 1];
            v.z += bias[gcol + c + 2];
            v.w += bias[gcol + c + 3];
            *reinterpret_cast<float4*>(C + (size_t)grow * GK + gcol + c) = v;
        }
        __syncwarp();
    }
}

// ---------------------------------------------------------------------------
// Fused pointwise + warp-parallel complex scan (fp16 in, h fp16 out).
// ---------------------------------------------------------------------------
__global__ __launch_bounds__(1024) void scanfused_kernel(
    const __half* __restrict__ xhhi,
    const __half* __restrict__ gxl, const __half* __restrict__ gal,
    const float* __restrict__ arp, const float* __restrict__ aip,
    __half* __restrict__ hout, float* __restrict__ h_last)
{
    __shared__ float sGx[32][33], sGa[32][33], sXr[32][33], sXi[32][33];
    __shared__ float sHr[32][33], sHi[32][33];

    const int b  = blockIdx.x >> 5;
    const int db = (blockIdx.x & 31) * 32;
    const int tid = threadIdx.x;
    const int w = tid >> 5;
    const int j = tid & 31;
    const int d = db + w;

    float av = arp[d];
    float sp = fmaxf(av, 0.f) + log1pf(__expf(-fabsf(av)));   // softplus
    float aipd = aip[d];

    float cr = 0.f, ci = 0.f;

    for (int s0 = 0; s0 < S_SZ; s0 += 32) {
        size_t grow = (size_t)(b * S_SZ + s0 + w);
        sGx[w][j] = __half2float(gxl[grow * DH + db + j]);
        sGa[w][j] = __half2float(gal[grow * DH + db + j]);
        size_t xb = grow * DHID + db + j;
        sXr[w][j] = __half2float(xhhi[xb]);
        sXi[w][j] = __half2float(xhhi[xb + DH]);
        __syncthreads();

        float gx_s = __fdividef(1.f, 1.f + __expf(-sGx[j][w]));
        float ga_s = __fdividef(1.f, 1.f + __expf(-sGa[j][w]));
        float log_a = -8.f * ga_s * sp;
        float mag = __expf(log_a);
        float th = aipd * ga_s;
        float sn = __sinf(th);
        float cs = __cosf(th);
        float ar = mag * cs;
        float ai = mag * sn;
        float nrm = sqrtf(fmaxf(1.f - mag * mag, 0.f));
        float scale = gx_s * nrm;
        float xr = scale * sXr[j][w];
        float xi = scale * sXi[j][w];

#pragma unroll
        for (int off = 1; off < 32; off <<= 1) {
            float p_ar = __shfl_up_sync(0xffffffffu, ar, off);
            float p_ai = __shfl_up_sync(0xffffffffu, ai, off);
            float p_xr = __shfl_up_sync(0xffffffffu, xr, off);
            float p_xi = __shfl_up_sync(0xffffffffu, xi, off);
            if (j >= off) {
                float nar = ar * p_ar - ai * p_ai;
                float nai = ar * p_ai + ai * p_ar;
                float nxr = ar * p_xr - ai * p_xi + xr;
                float nxi = ar * p_xi + ai * p_xr + xi;
                ar = nar; ai = nai; xr = nxr; xi = nxi;
            }
        }

        float hr  = fmaf(ar, cr, fmaf(-ai, ci, xr));
        float hi_ = fmaf(ar, ci, fmaf(ai, cr, xi));
        cr = __shfl_sync(0xffffffffu, hr, 31);
        ci = __shfl_sync(0xffffffffu, hi_, 31);

        sHr[j][w] = hr;
        sHi[j][w] = hi_;
        __syncthreads();

        size_t orow = grow * (size_t)DHID;
        hout[orow + db + j]      = __float2half_rn(sHr[w][j]);
        hout[orow + DH + db + j] = __float2half_rn(sHi[w][j]);
    }

    if (j == 0) {
        h_last[(size_t)b * DHID + d]      = cr;
        h_last[(size_t)b * DHID + DH + d] = ci;
    }
}

// ---------------------------------------------------------------------------
// Launch
// ---------------------------------------------------------------------------
extern "C" void kernel_launch(void* const* d_in, const int* in_sizes, int n_in,
                              void* d_out, int out_size)
{
    const float* x     = (const float*)d_in[0];
    const float* arp   = (const float*)d_in[1];
    const float* aip   = (const float*)d_in[2];
    const float* W_in  = (const float*)d_in[3];
    const float* b_in  = (const float*)d_in[4];
    const float* Wgx   = (const float*)d_in[5];
    const float* bgx   = (const float*)d_in[6];
    const float* Wga   = (const float*)d_in[7];
    const float* bga   = (const float*)d_in[8];
    const float* W_out = (const float*)d_in[9];
    const float* b_out = (const float*)d_in[10];

    float* y = (float*)d_out;
    float* h_last = (float*)d_out + ((size_t)out_size - (size_t)B_SZ * DHID);

    __half *gx, *ga, *xsp, *h, *xhhi, *win, *wout, *wg2;
    cudaGetSymbolAddress((void**)&gx,   g_gx);
    cudaGetSymbolAddress((void**)&ga,   g_ga);
    cudaGetSymbolAddress((void**)&xsp,  g_xsp);
    cudaGetSymbolAddress((void**)&h,    g_h);
    cudaGetSymbolAddress((void**)&xhhi, g_xhhi);
    cudaGetSymbolAddress((void**)&win,  g_win);
    cudaGetSymbolAddress((void**)&wout, g_wout);
    cudaGetSymbolAddress((void**)&wg2,  g_wg2);

    cudaFuncSetAttribute(gemm1_fused_kernel,
                         cudaFuncAttributeMaxDynamicSharedMemorySize, SMEM_BIG);
    cudaFuncSetAttribute(gemm2_kernel,
                         cudaFuncAttributeMaxDynamicSharedMemorySize, SMEM_G2);

    const size_t nx4 = (size_t)MROWS * GK / 4;
    const size_t nw4 = (size_t)GK * GK / 4;

    // 0) conversions (independent)
    cvt_hi16_kernel<<<(unsigned)((nx4 + 255) / 256), 256>>>(
        (const float4*)x, (uint2*)xsp, nx4);
    cvt_hi16_kernel<<<(unsigned)((nw4 + 255) / 256), 256>>>(
        (const float4*)W_in, (uint2*)win, nw4);
    cvt_hi16_kernel<<<(unsigned)((nw4 + 255) / 256), 256>>>(
        (const float4*)W_out, (uint2*)wout, nw4);
    cvt_gatew_kernel<<<(NB * 256 * 256) / 256, 256>>>(Wgx, Wga, wg2);

    // 1+2) fused: xh = x @ W_in + b_in (hi out) AND gate logits
    gemm1_fused_kernel<<<dim3(NB, MROWS / 128), 256, SMEM_BIG>>>(
        xsp, win, b_in, wg2, bgx, bga, xhhi, gx, ga);

    // 3+4) fused pointwise + warp scan; writes h as fp16 hi
    scanfused_kernel<<<B_SZ * (DH / 32), 1024>>>(
        xhhi, gx, ga, arp, aip, h, h_last);

    // 5) y = h @ W_out + b_out (128x128 tiles, 2 CTAs/SM)
    gemm2_kernel<<<dim3(GK / 128, MROWS / 128), 256, SMEM_G2>>>(
        h, wout, b_out, y);
}

// round 14
// speedup vs baseline: 7.0435x; 1.0577x over previous
#include <cuda_runtime.h>
#include <cuda_fp16.h>
#include <mma.h>
#include <math.h>
#include <stdint.h>

using namespace nvcuda;

// Problem dims (fixed by the dataset)
#define NB     8
#define B_SZ   4
#define S_SZ   4096
#define DIN    2048
#define DHID   2048
#define DH     1024
#define MROWS  (B_SZ * S_SZ)   // 16384
#define GK     2048            // K (and N) for both big GEMMs

// GEMM1 tiling: CTA 128x256, BK=64, warp tile 64x64 (8 warps: 2m x 4n)
#define TLDA 72      // A smem stride (halves): 144B
#define TLDB 264     // B smem stride (halves): 528B (256 cols + 8 pad)
#define A_BYTES (128 * TLDA * 2)     // 18432
#define B_BYTES (64 * TLDB * 2)      // 33792
#define STAGE   (A_BYTES + B_BYTES)  // 52224
#define SMEM_BIG (4 * STAGE)         // 208896

// post-mainloop layout inside smem (fused GEMM1):
#define XHS_BYTES (128 * TLDB * 2)        // 67584: xh tile fp16 [128][264]
#define ST_OFF    XHS_BYTES               // fp32 staging (8 warps * 16*64*4 = 32KB)
#define GB_OFF    (XHS_BYTES + 32768)     // gate B double buffer (2 * 33792)

// GEMM2 tiling: CTA 128x128, BK=64, 2 CTAs/SM, warp tile 64x32 (2m x 4n)
#define T2LDB 136                      // B smem stride (halves): 272B
#define B2_BYTES (64 * T2LDB * 2)      // 17408
#define STAGE2   (A_BYTES + B2_BYTES)  // 35840
#define SMEM_G2  (3 * STAGE2)          // 107520

// ---------------------------------------------------------------------------
// Scratch (device globals -- no allocation allowed in kernel_launch)
// ---------------------------------------------------------------------------
__device__ __align__(256) __half g_gx  [(size_t)MROWS * DH];    // gate_x logits
__device__ __align__(256) __half g_ga  [(size_t)MROWS * DH];    // gate_a logits
__device__ __align__(256) __half g_xsp [(size_t)MROWS * DIN];   // x hi
__device__ __align__(256) __half g_h   [(size_t)MROWS * DHID];  // h hi
__device__ __align__(256) __half g_xhhi[(size_t)MROWS * DHID];  // xh hi
__device__ __align__(256) __half g_win [(size_t)GK * GK];       // W_in hi
__device__ __align__(256) __half g_wout[(size_t)GK * GK];       // W_out hi
__device__ __align__(256) __half g_wg2 [(size_t)NB * 256 * 256]; // [Wgx|Wga]

// ---------------------------------------------------------------------------
// helpers
// ---------------------------------------------------------------------------
__device__ __forceinline__ void cp16(uint32_t s, const void* g) {
    asm volatile("cp.async.cg.shared.global [%0], [%1], 16;" :: "r"(s), "l"(g));
}
__device__ __forceinline__ void cp4(uint32_t s, const void* g) {
    asm volatile("cp.async.ca.shared.global [%0], [%1], 4;" :: "r"(s), "l"(g));
}
__device__ __forceinline__ uint32_t smem_u32(const void* p) {
    uint32_t a;
    asm("{ .reg .u64 t; cvta.to.shared.u64 t, %1; cvt.u32.u64 %0, t; }"
        : "=r"(a) : "l"(p));
    return a;
}
__device__ __forceinline__ uint32_t pack4h(__half a, __half b) {
    __half2 h2 = {a, b};
    return *reinterpret_cast<unsigned*>(&h2);
}

// ---------------------------------------------------------------------------
// Converters
// ---------------------------------------------------------------------------
__global__ __launch_bounds__(256) void cvt_hi16_kernel(
    const float4* __restrict__ in, uint2* __restrict__ hi, size_t n4)
{
    size_t i = (size_t)blockIdx.x * 256 + threadIdx.x;
    if (i >= n4) return;
    float4 v = in[i];
    hi[i] = make_uint2(pack4h(__float2half_rn(v.x), __float2half_rn(v.y)),
                       pack4h(__float2half_rn(v.z), __float2half_rn(v.w)));
}

// Pack gate weights: wg2[nb][k][c] = c<128 ? Wgx[nb][k][c] : Wga[nb][k][c-128]
__global__ __launch_bounds__(256) void cvt_gatew_kernel(
    const float* __restrict__ Wgx, const float* __restrict__ Wga,
    __half* __restrict__ out)
{
    int i = blockIdx.x * 256 + threadIdx.x;
    int c  = i & 255;
    int k  = (i >> 8) & 255;
    int nb = i >> 16;
    float v = (c < 128) ? Wgx[nb * 32768 + k * 128 + c]
                        : Wga[nb * 32768 + k * 128 + (c - 128)];
    out[i] = __float2half_rn(v);
}

// ---------------------------------------------------------------------------
// GEMM1 mainloop (CTA tile 128x256, NSTAGE-deep cp.async pipeline).
// ---------------------------------------------------------------------------
__device__ __forceinline__ void load_stage(
    const __half* __restrict__ A, int lda,
    const __half* __restrict__ B, int ldb,
    int kt, uint32_t base, int tid)
{
#pragma unroll
    for (int i = 0; i < 4; i++) {            // A: 128 rows x 128B
        int u = tid + (i << 8);
        int r = u >> 3;
        int ch = u & 7;
        cp16(base + (uint32_t)(r * 144 + ch * 16),
             A + (size_t)r * lda + kt + ch * 8);
    }
#pragma unroll
    for (int i = 0; i < 8; i++) {            // B: 64 rows x 512B
        int u = tid + (i << 8);
        int r = u >> 5;
        int ch = u & 31;
        cp16(base + A_BYTES + (uint32_t)(r * 528 + ch * 16),
             B + (size_t)(kt + r) * ldb + ch * 8);
    }
}

template<int NSTAGE>
__device__ __forceinline__ void gemm_mainloop(
    const __half* __restrict__ A, int lda,
    const __half* __restrict__ B, int ldb, int K,
    wmma::fragment<wmma::accumulator, 16, 16, 16, float> (&acc)[4][4],
    char* smem, uint32_t sb, int tid, int warp_m, int warp_n)
{
#pragma unroll
    for (int m = 0; m < 4; m++)
#pragma unroll
        for (int n = 0; n < 4; n++) wmma::fill_fragment(acc[m][n], 0.0f);

    const int nIter = K / 64;
#pragma unroll
    for (int s = 0; s < NSTAGE - 1; s++) {
        load_stage(A, lda, B, ldb, s * 64, sb + (uint32_t)s * STAGE, tid);
        asm volatile("cp.async.commit_group;");
    }

    for (int it = 0; it < nIter; ++it) {
        if (it + NSTAGE - 2 < nIter)
            asm volatile("cp.async.wait_group %0;" :: "n"(NSTAGE - 2));
        else
            asm volatile("cp.async.wait_group 0;");
        __syncthreads();
        if (it + NSTAGE - 1 < nIter) {
            load_stage(A, lda, B, ldb, (it + NSTAGE - 1) * 64,
                       sb + (uint32_t)((it + NSTAGE - 1) % NSTAGE) * STAGE, tid);
            asm volatile("cp.async.commit_group;");
        }

        char* stg = smem + (it % NSTAGE) * STAGE;
        const __half* As = reinterpret_cast<const __half*>(stg);
        const __half* Bs = reinterpret_cast<const __half*>(stg + A_BYTES);

#pragma unroll
        for (int kk = 0; kk < 64; kk += 16) {
            wmma::fragment<wmma::matrix_a, 16, 16, 16, __half, wmma::row_major> a[4];
            wmma::fragment<wmma::matrix_b, 16, 16, 16, __half, wmma::row_major> b[4];
#pragma unroll
            for (int m = 0; m < 4; m++)
                wmma::load_matrix_sync(a[m], As + (warp_m * 64 + m * 16) * TLDA + kk, TLDA);
#pragma unroll
            for (int n = 0; n < 4; n++)
                wmma::load_matrix_sync(b[n], Bs + kk * TLDB + warp_n * 64 + n * 16, TLDB);
#pragma unroll
            for (int m = 0; m < 4; m++)
#pragma unroll
                for (int n = 0; n < 4; n++)
                    wmma::mma_sync(acc[m][n], a[m], b[n], acc[m][n]);
        }
    }
    __syncthreads();
}

// ---------------------------------------------------------------------------
// Fused GEMM1 + gate GEMM. Grid (NB, MROWS/128), 1 CTA/SM.
// ---------------------------------------------------------------------------
__global__ __launch_bounds__(256, 1) void gemm1_fused_kernel(
    const __half* __restrict__ Ahi, const __half* __restrict__ Bhi,
    const float* __restrict__ bias,
    const __half* __restrict__ wg2,
    const float* __restrict__ bgx, const float* __restrict__ bga,
    __half* __restrict__ Chi,
    __half* __restrict__ gx, __half* __restrict__ ga)
{
    extern __shared__ __align__(256) char smem[];
    const uint32_t sb = smem_u32(smem);
    const int tid = threadIdx.x, wid = tid >> 5, lane = tid & 31;
    const int warp_m = wid >> 2, warp_n = wid & 3;
    const int nb   = blockIdx.x;          // 0..7
    const int bn   = nb * 256;
    const int row0 = blockIdx.y * 128;

    wmma::fragment<wmma::accumulator, 16, 16, 16, float> acc[4][4];
    gemm_mainloop<4>(Ahi + (size_t)row0 * GK, GK, Bhi + bn, GK, GK,
                     acc, smem, sb, tid, warp_m, warp_n);

    // ---- epilogue 1: bias add; write xh hi to global and fp16 tile to smem
    __half* xhs = reinterpret_cast<__half*>(smem);              // [128][264]
    float* st = reinterpret_cast<float*>(smem + ST_OFF) + wid * (16 * 64);
#pragma unroll
    for (int m = 0; m < 4; m++) {
#pragma unroll
        for (int n = 0; n < 4; n++)
            wmma::store_matrix_sync(st + n * 16, acc[m][n], 64, wmma::mem_row_major);
        __syncwarp();
        int r = lane >> 1, cs = (lane & 1) * 32;
        int lrow = warp_m * 64 + m * 16 + r;
        int lcol = warp_n * 64 + cs;
#pragma unroll
        for (int c = 0; c < 32; c += 4) {
            float4 v = *reinterpret_cast<float4*>(st + r * 64 + cs + c);
            v.x += bias[bn + lcol + c + 0];
            v.y += bias[bn + lcol + c + 1];
            v.z += bias[bn + lcol + c + 2];
            v.w += bias[bn + lcol + c + 3];
            uint2 u = make_uint2(pack4h(__float2half_rn(v.x), __float2half_rn(v.y)),
                                 pack4h(__float2half_rn(v.z), __float2half_rn(v.w)));
            *reinterpret_cast<uint2*>(Chi + (size_t)(row0 + lrow) * GK + bn + lcol + c) = u;
            *reinterpret_cast<uint2*>(xhs + lrow * TLDB + lcol + c) = u;
        }
        __syncwarp();
    }
    __syncthreads();

    // ---- gate GEMM: [128 x 256] @ wg2[nb] (256 x 256), K streamed in 4 chunks
    const __half* wgb = wg2 + (size_t)nb * 65536;
    char* gb = smem + GB_OFF;   // double buffer, 2 x B_BYTES

#pragma unroll
    for (int i = 0; i < 8; i++) {
        int u = tid + (i << 8);
        int r = u >> 5;
        int ch = u & 31;
        cp16(sb + GB_OFF + (uint32_t)(r * 528 + ch * 16),
             wgb + (size_t)r * 256 + ch * 8);
    }
    asm volatile("cp.async.commit_group;");

    wmma::fragment<wmma::accumulator, 16, 16, 16, float> acc2[4][4];
#pragma unroll
    for (int m = 0; m < 4; m++)
#pragma unroll
        for (int n = 0; n < 4; n++) wmma::fill_fragment(acc2[m][n], 0.0f);

    for (int chunk = 0; chunk < 4; ++chunk) {
        if (chunk < 3) {
            uint32_t dst = sb + GB_OFF + (uint32_t)((chunk + 1) & 1) * B_BYTES;
#pragma unroll
            for (int i = 0; i < 8; i++) {
                int u = tid + (i << 8);
                int r = u >> 5;
                int ch = u & 31;
                cp16(dst + (uint32_t)(r * 528 + ch * 16),
                     wgb + (size_t)((chunk + 1) * 64 + r) * 256 + ch * 8);
            }
            asm volatile("cp.async.commit_group;");
            asm volatile("cp.async.wait_group 1;");
        } else {
            asm volatile("cp.async.wait_group 0;");
        }
        __syncthreads();

        const __half* Bs = reinterpret_cast<const __half*>(gb + (chunk & 1) * B_BYTES);
#pragma unroll
        for (int kk = 0; kk < 64; kk += 16) {
            int kabs = chunk * 64 + kk;
            wmma::fragment<wmma::matrix_a, 16, 16, 16, __half, wmma::row_major> a[4];
            wmma::fragment<wmma::matrix_b, 16, 16, 16, __half, wmma::row_major> b[4];
#pragma unroll
            for (int m = 0; m < 4; m++)
                wmma::load_matrix_sync(a[m], xhs + (warp_m * 64 + m * 16) * TLDB + kabs, TLDB);
#pragma unroll
            for (int n = 0; n < 4; n++)
                wmma::load_matrix_sync(b[n], Bs + kk * TLDB + warp_n * 64 + n * 16, TLDB);
#pragma unroll
            for (int m = 0; m < 4; m++)
#pragma unroll
                for (int n = 0; n < 4; n++)
                    wmma::mma_sync(acc2[m][n], a[m], b[n], acc2[m][n]);
        }
        __syncthreads();
    }

    // ---- epilogue 2: gate bias + fp16 logits
#pragma unroll
    for (int m = 0; m < 4; m++) {
#pragma unroll
        for (int n = 0; n < 4; n++)
            wmma::store_matrix_sync(st + n * 16, acc2[m][n], 64, wmma::mem_row_major);
        __syncwarp();
        int r = lane >> 1, cs = (lane & 1) * 32;
        int lrow = warp_m * 64 + m * 16 + r;
        int gcol = warp_n * 64 + cs;     // 0..255
        bool isx = gcol < 128;
        int col = isx ? gcol : gcol - 128;
        const float* bp = (isx ? bgx : bga) + nb * 128 + col;
        __half* op = (isx ? gx : ga) + (size_t)(row0 + lrow) * DH + nb * 128 + col;
#pragma unroll
        for (int c = 0; c < 32; c += 4) {
            float4 v = *reinterpret_cast<float4*>(st + r * 64 + cs + c);
            v.x += bp[c + 0];
            v.y += bp[c + 1];
            v.z += bp[c + 2];
            v.w += bp[c + 3];
            *reinterpret_cast<uint2*>(op + c) =
                make_uint2(pack4h(__float2half_rn(v.x), __float2half_rn(v.y)),
                           pack4h(__float2half_rn(v.z), __float2half_rn(v.w)));
        }
        __syncwarp();
    }
}

// ---------------------------------------------------------------------------
// GEMM2: y = h @ W_out + b_out -> fp32.
// CTA tile 128x128, NSTAGE=3, 2 CTAs/SM, warp tile 64x32 (2m x 4n).
// ---------------------------------------------------------------------------
__global__ __launch_bounds__(256, 2) void gemm2_kernel(
    const __half* __restrict__ Ahi, const __half* __restrict__ Bhi,
    const float* __restrict__ bias, float* __restrict__ C)
{
    extern __shared__ __align__(256) char smem[];
    const uint32_t sb = smem_u32(smem);
    const int tid = threadIdx.x, wid = tid >> 5, lane = tid & 31;
    const int warp_m = wid >> 2;   // 0..1 (64-row slab)
    const int warp_n = wid & 3;    // 0..3 (32-col slab)
    const int row0 = blockIdx.y * 128;
    const int bn   = blockIdx.x * 128;

    const __half* A = Ahi + (size_t)row0 * GK;
    const __half* B = Bhi + bn;

    wmma::fragment<wmma::accumulator, 16, 16, 16, float> acc[4][2];
#pragma unroll
    for (int m = 0; m < 4; m++)
#pragma unroll
        for (int n = 0; n < 2; n++) wmma::fill_fragment(acc[m][n], 0.0f);

    auto load2 = [&](int kt, uint32_t base) {
#pragma unroll
        for (int i = 0; i < 4; i++) {
            int u = tid + (i << 8);
            int r = u >> 3;
            int ch = u & 7;
            cp16(base + (uint32_t)(r * 144 + ch * 16),
                 A + (size_t)r * GK + kt + ch * 8);
        }
#pragma unroll
        for (int i = 0; i < 4; i++) {
            int u = tid + (i << 8);
            int r = u >> 4;
            int ch = u & 15;
            cp16(base + A_BYTES + (uint32_t)(r * 272 + ch * 16),
                 B + (size_t)(kt + r) * GK + ch * 8);
        }
    };

    const int nIter = GK / 64;   // 32
#pragma unroll
    for (int s = 0; s < 2; s++) {
        load2(s * 64, sb + (uint32_t)s * STAGE2);
        asm volatile("cp.async.commit_group;");
    }

    for (int it = 0; it < nIter; ++it) {
        if (it + 1 < nIter) asm volatile("cp.async.wait_group 1;");
        else                asm volatile("cp.async.wait_group 0;");
        __syncthreads();
        if (it + 2 < nIter) {
            load2((it + 2) * 64, sb + (uint32_t)((it + 2) % 3) * STAGE2);
            asm volatile("cp.async.commit_group;");
        }

        char* stg = smem + (it % 3) * STAGE2;
        const __half* As = reinterpret_cast<const __half*>(stg);
        const __half* Bs = reinterpret_cast<const __half*>(stg + A_BYTES);

#pragma unroll
        for (int kk = 0; kk < 64; kk += 16) {
            wmma::fragment<wmma::matrix_a, 16, 16, 16, __half, wmma::row_major> a[4];
            wmma::fragment<wmma::matrix_b, 16, 16, 16, __half, wmma::row_major> b[2];
#pragma unroll
            for (int m = 0; m < 4; m++)
                wmma::load_matrix_sync(a[m], As + (warp_m * 64 + m * 16) * TLDA + kk, TLDA);
#pragma unroll
            for (int n = 0; n < 2; n++)
                wmma::load_matrix_sync(b[n], Bs + kk * T2LDB + warp_n * 32 + n * 16, T2LDB);
#pragma unroll
            for (int m = 0; m < 4; m++)
#pragma unroll
                for (int n = 0; n < 2; n++)
                    wmma::mma_sync(acc[m][n], a[m], b[n], acc[m][n]);
        }
    }
    __syncthreads();

    float* st = reinterpret_cast<float*>(smem) + wid * (16 * 32);
#pragma unroll
    for (int m = 0; m < 4; m++) {
        wmma::store_matrix_sync(st,      acc[m][0], 32, wmma::mem_row_major);
        wmma::store_matrix_sync(st + 16, acc[m][1], 32, wmma::mem_row_major);
        __syncwarp();
        int r  = lane >> 1;
        int cs = (lane & 1) * 16;
        int grow = row0 + warp_m * 64 + m * 16 + r;
        int gcol = bn + warp_n * 32 + cs;
#pragma unroll
        for (int c = 0; c < 16; c += 4) {
            float4 v = *reinterpret_cast<float4*>(st + r * 32 + cs + c);
            v.x += bias[gcol + c + 0];
            v.y += bias[gcol + c + 1];
            v.z += bias[gcol + c + 2];
            v.w += bias[gcol + c + 3];
            *reinterpret_cast<float4*>(C + (size_t)grow * GK + gcol + c) = v;
        }
        __syncwarp();
    }
}

// ---------------------------------------------------------------------------
// Fused pointwise + warp-parallel complex scan, cp.async double-buffered.
// Grid: 128 CTAs (4 batches x 32 d-blocks), 1024 threads (32 warps).
// Inputs for tile i+1 stream into smem while tile i computes.
// ---------------------------------------------------------------------------
__global__ __launch_bounds__(1024) void scanfused_kernel(
    const __half* __restrict__ xhhi,
    const __half* __restrict__ gxl, const __half* __restrict__ gal,
    const float* __restrict__ arp, const float* __restrict__ aip,
    __half* __restrict__ hout, float* __restrict__ h_last)
{
    // sIn[buf][array][row s][col d], pad 34 -> transposed reads conflict-free
    __shared__ __half sIn[2][4][32][34];
    __shared__ float sHr[32][33], sHi[32][33];

    const int b  = blockIdx.x >> 5;
    const int db = (blockIdx.x & 31) * 32;
    const int tid = threadIdx.x;
    const int w = tid >> 5;
    const int j = tid & 31;
    const int d = db + w;
    const uint32_t sInb = smem_u32(sIn);

    float av = arp[d];
    float sp = fmaxf(av, 0.f) + log1pf(__expf(-fabsf(av)));   // softplus
    float aipd = aip[d];

    // issue one tile's inputs (4 arrays x 32 rows x 64B) via cp.async 4B
    auto issue_tile = [&](int s0, int buf) {
#pragma unroll
        for (int q = 0; q < 2; q++) {
            int e = tid + (q << 10);          // 0..2047
            int a = e >> 9;                   // array (uniform per warp)
            int r = (e >> 4) & 31;            // row within tile
            int c = (e & 15) << 1;            // half index (pairs)
            size_t row = (size_t)(b * S_SZ + s0 + r);
            const __half* src;
            if (a == 0)      src = gxl  + row * DH   + db + c;
            else if (a == 1) src = gal  + row * DH   + db + c;
            else if (a == 2) src = xhhi + row * DHID + db + c;
            else             src = xhhi + row * DHID + DH + db + c;
            uint32_t dst = sInb + (uint32_t)((((buf * 4 + a) * 32 + r) * 34 + c) * 2);
            cp4(dst, src);
        }
        asm volatile("cp.async.commit_group;");
    };

    float cr = 0.f, ci = 0.f;

    issue_tile(0, 0);

    const int nTiles = S_SZ / 32;   // 128
    for (int t = 0; t < nTiles; ++t) {
        asm volatile("cp.async.wait_group 0;");
        __syncthreads();
        if (t + 1 < nTiles) issue_tile((t + 1) * 32, (t + 1) & 1);

        const int cur = t & 1;
        // lane j = step s0+j of chain d (transposed read)
        float gx_s = __fdividef(1.f, 1.f + __expf(-__half2float(sIn[cur][0][j][w])));
        float ga_s = __fdividef(1.f, 1.f + __expf(-__half2float(sIn[cur][1][j][w])));
        float log_a = -8.f * ga_s * sp;
        float mag = __expf(log_a);
        float th = aipd * ga_s;
        float sn = __sinf(th);
        float cs = __cosf(th);
        float ar = mag * cs;
        float ai = mag * sn;
        float nrm = sqrtf(fmaxf(1.f - mag * mag, 0.f));
        float scale = gx_s * nrm;
        float xr = scale * __half2float(sIn[cur][2][j][w]);
        float xi = scale * __half2float(sIn[cur][3][j][w]);

#pragma unroll
        for (int off = 1; off < 32; off <<= 1) {
            float p_ar = __shfl_up_sync(0xffffffffu, ar, off);
            float p_ai = __shfl_up_sync(0xffffffffu, ai, off);
            float p_xr = __shfl_up_sync(0xffffffffu, xr, off);
            float p_xi = __shfl_up_sync(0xffffffffu, xi, off);
            if (j >= off) {
                float nar = ar * p_ar - ai * p_ai;
                float nai = ar * p_ai + ai * p_ar;
                float nxr = ar * p_xr - ai * p_xi + xr;
                float nxi = ar * p_xi + ai * p_xr + xi;
                ar = nar; ai = nai; xr = nxr; xi = nxi;
            }
        }

        float hr  = fmaf(ar, cr, fmaf(-ai, ci, xr));
        float hi_ = fmaf(ar, ci, fmaf(ai, cr, xi));
        cr = __shfl_sync(0xffffffffu, hr, 31);
        ci = __shfl_sync(0xffffffffu, hi_, 31);

        sHr[j][w] = hr;
        sHi[j][w] = hi_;
        __syncthreads();

        // coalesced store: thread (w = s-row, j = d-col)
        size_t orow = (size_t)(b * S_SZ + t * 32 + w) * DHID;
        hout[orow + db + j]      = __float2half_rn(sHr[w][j]);
        hout[orow + DH + db + j] = __float2half_rn(sHi[w][j]);
    }

    if (j == 0) {
        h_last[(size_t)b * DHID + d]      = cr;
        h_last[(size_t)b * DHID + DH + d] = ci;
    }
}

// ---------------------------------------------------------------------------
// Launch
// ---------------------------------------------------------------------------
extern "C" void kernel_launch(void* const* d_in, const int* in_sizes, int n_in,
                              void* d_out, int out_size)
{
    const float* x     = (const float*)d_in[0];
    const float* arp   = (const float*)d_in[1];
    const float* aip   = (const float*)d_in[2];
    const float* W_in  = (const float*)d_in[3];
    const float* b_in  = (const float*)d_in[4];
    const float* Wgx   = (const float*)d_in[5];
    const float* bgx   = (const float*)d_in[6];
    const float* Wga   = (const float*)d_in[7];
    const float* bga   = (const float*)d_in[8];
    const float* W_out = (const float*)d_in[9];
    const float* b_out = (const float*)d_in[10];

    float* y = (float*)d_out;
    float* h_last = (float*)d_out + ((size_t)out_size - (size_t)B_SZ * DHID);

    __half *gx, *ga, *xsp, *h, *xhhi, *win, *wout, *wg2;
    cudaGetSymbolAddress((void**)&gx,   g_gx);
    cudaGetSymbolAddress((void**)&ga,   g_ga);
    cudaGetSymbolAddress((void**)&xsp,  g_xsp);
    cudaGetSymbolAddress((void**)&h,    g_h);
    cudaGetSymbolAddress((void**)&xhhi, g_xhhi);
    cudaGetSymbolAddress((void**)&win,  g_win);
    cudaGetSymbolAddress((void**)&wout, g_wout);
    cudaGetSymbolAddress((void**)&wg2,  g_wg2);

    cudaFuncSetAttribute(gemm1_fused_kernel,
                         cudaFuncAttributeMaxDynamicSharedMemorySize, SMEM_BIG);
    cudaFuncSetAttribute(gemm2_kernel,
                         cudaFuncAttributeMaxDynamicSharedMemorySize, SMEM_G2);

    const size_t nx4 = (size_t)MROWS * GK / 4;
    const size_t nw4 = (size_t)GK * GK / 4;

    // 0) conversions (independent)
    cvt_hi16_kernel<<<(unsigned)((nx4 + 255) / 256), 256>>>(
        (const float4*)x, (uint2*)xsp, nx4);
    cvt_hi16_kernel<<<(unsigned)((nw4 + 255) / 256), 256>>>(
        (const float4*)W_in, (uint2*)win, nw4);
    cvt_hi16_kernel<<<(unsigned)((nw4 + 255) / 256), 256>>>(
        (const float4*)W_out, (uint2*)wout, nw4);
    cvt_gatew_kernel<<<(NB * 256 * 256) / 256, 256>>>(Wgx, Wga, wg2);

    // 1+2) fused: xh = x @ W_in + b_in (hi out) AND gate logits
    gemm1_fused_kernel<<<dim3(NB, MROWS / 128), 256, SMEM_BIG>>>(
        xsp, win, b_in, wg2, bgx, bga, xhhi, gx, ga);

    // 3+4) fused pointwise + warp scan (cp.async pipelined); h as fp16 hi
    scanfused_kernel<<<B_SZ * (DH / 32), 1024>>>(
        xhhi, gx, ga, arp, aip, h, h_last);

    // 5) y = h @ W_out + b_out (128x128 tiles, 2 CTAs/SM)
    gemm2_kernel<<<dim3(GK / 128, MROWS / 128), 256, SMEM_G2>>>(
        h, wout, b_out, y);
}

// round 16
// speedup vs baseline: 7.3598x; 1.0449x over previous
#include <cuda_runtime.h>
#include <cuda_fp16.h>
#include <mma.h>
#include <math.h>
#include <stdint.h>

using namespace nvcuda;

// Problem dims (fixed by the dataset)
#define NB     8
#define B_SZ   4
#define S_SZ   4096
#define DIN    2048
#define DHID   2048
#define DH     1024
#define MROWS  (B_SZ * S_SZ)   // 16384
#define GK     2048            // K (and N) for both big GEMMs

// GEMM1 tiling: CTA 128x256, BK=64, warp tile 64x64 (8 warps: 2m x 4n)
#define TLDA 72      // A smem stride (halves): 144B
#define TLDB 264     // B smem stride (halves): 528B (256 cols + 8 pad)
#define A_BYTES (128 * TLDA * 2)     // 18432
#define B_BYTES (64 * TLDB * 2)      // 33792
#define STAGE   (A_BYTES + B_BYTES)  // 52224
#define SMEM_BIG (4 * STAGE)         // 208896

// post-mainloop layout inside smem (fused GEMM1):
#define XHS_BYTES (128 * TLDB * 2)        // 67584: xh tile fp16 [128][264]
#define ST_OFF    XHS_BYTES               // fp32 staging (8 warps * 16*64*4 = 32KB)
#define GB_OFF    (XHS_BYTES + 32768)     // gate B double buffer (2 * 33792)

// GEMM2 tiling: CTA 128x128, BK=64, 2 CTAs/SM, warp tile 64x32 (2m x 4n)
#define T2LDB 136                      // B smem stride (halves): 272B
#define B2_BYTES (64 * T2LDB * 2)      // 17408
#define STAGE2   (A_BYTES + B2_BYTES)  // 35840
#define SMEM_G2  (3 * STAGE2)          // 107520

// Scan smem layout (dynamic): pad 38 halves -> 76B rows (4B aligned),
// transposed-read bank step 6 (2-way conflict, benign).
#define SPAD 38
#define SIN_BYTES  (2 * 4 * 64 * SPAD * 2)     // 77824
#define SHR_OFF    SIN_BYTES                   // 64*33 fp32 = 8448
#define SHI_OFF    (SIN_BYTES + 8448)
#define SMEM_SCAN  (SIN_BYTES + 2 * 8448)      // 94720

// ---------------------------------------------------------------------------
// Scratch (device globals -- no allocation allowed in kernel_launch)
// ---------------------------------------------------------------------------
__device__ __align__(256) __half g_gx  [(size_t)MROWS * DH];    // gate_x logits
__device__ __align__(256) __half g_ga  [(size_t)MROWS * DH];    // gate_a logits
__device__ __align__(256) __half g_xsp [(size_t)MROWS * DIN];   // x hi
__device__ __align__(256) __half g_h   [(size_t)MROWS * DHID];  // h hi
__device__ __align__(256) __half g_xhhi[(size_t)MROWS * DHID];  // xh hi
__device__ __align__(256) __half g_win [(size_t)GK * GK];       // W_in hi
__device__ __align__(256) __half g_wout[(size_t)GK * GK];       // W_out hi
__device__ __align__(256) __half g_wg2 [(size_t)NB * 256 * 256]; // [Wgx|Wga]

// ---------------------------------------------------------------------------
// helpers
// ---------------------------------------------------------------------------
__device__ __forceinline__ void cp16(uint32_t s, const void* g) {
    asm volatile("cp.async.cg.shared.global [%0], [%1], 16;" :: "r"(s), "l"(g));
}
__device__ __forceinline__ void cp4(uint32_t s, const void* g) {
    asm volatile("cp.async.ca.shared.global [%0], [%1], 4;" :: "r"(s), "l"(g));
}
__device__ __forceinline__ uint32_t smem_u32(const void* p) {
    uint32_t a;
    asm("{ .reg .u64 t; cvta.to.shared.u64 t, %1; cvt.u32.u64 %0, t; }"
        : "=r"(a) : "l"(p));
    return a;
}
__device__ __forceinline__ uint32_t pack4h(__half a, __half b) {
    __half2 h2 = {a, b};
    return *reinterpret_cast<unsigned*>(&h2);
}

// ---------------------------------------------------------------------------
// Converters
// ---------------------------------------------------------------------------
__global__ __launch_bounds__(256) void cvt_hi16_kernel(
    const float4* __restrict__ in, uint2* __restrict__ hi, size_t n4)
{
    size_t i = (size_t)blockIdx.x * 256 + threadIdx.x;
    if (i >= n4) return;
    float4 v = in[i];
    hi[i] = make_uint2(pack4h(__float2half_rn(v.x), __float2half_rn(v.y)),
                       pack4h(__float2half_rn(v.z), __float2half_rn(v.w)));
}

// Pack gate weights: wg2[nb][k][c] = c<128 ? Wgx[nb][k][c] : Wga[nb][k][c-128]
__global__ __launch_bounds__(256) void cvt_gatew_kernel(
    const float* __restrict__ Wgx, const float* __restrict__ Wga,
    __half* __restrict__ out)
{
    int i = blockIdx.x * 256 + threadIdx.x;
    int c  = i & 255;
    int k  = (i >> 8) & 255;
    int nb = i >> 16;
    float v = (c < 128) ? Wgx[nb * 32768 + k * 128 + c]
                        : Wga[nb * 32768 + k * 128 + (c - 128)];
    out[i] = __float2half_rn(v);
}

// ---------------------------------------------------------------------------
// GEMM1 mainloop (CTA tile 128x256, NSTAGE-deep cp.async pipeline).
// ---------------------------------------------------------------------------
__device__ __forceinline__ void load_stage(
    const __half* __restrict__ A, int lda,
    const __half* __restrict__ B, int ldb,
    int kt, uint32_t base, int tid)
{
#pragma unroll
    for (int i = 0; i < 4; i++) {            // A: 128 rows x 128B
        int u = tid + (i << 8);
        int r = u >> 3;
        int ch = u & 7;
        cp16(base + (uint32_t)(r * 144 + ch * 16),
             A + (size_t)r * lda + kt + ch * 8);
    }
#pragma unroll
    for (int i = 0; i < 8; i++) {            // B: 64 rows x 512B
        int u = tid + (i << 8);
        int r = u >> 5;
        int ch = u & 31;
        cp16(base + A_BYTES + (uint32_t)(r * 528 + ch * 16),
             B + (size_t)(kt + r) * ldb + ch * 8);
    }
}

template<int NSTAGE>
__device__ __forceinline__ void gemm_mainloop(
    const __half* __restrict__ A, int lda,
    const __half* __restrict__ B, int ldb, int K,
    wmma::fragment<wmma::accumulator, 16, 16, 16, float> (&acc)[4][4],
    char* smem, uint32_t sb, int tid, int warp_m, int warp_n)
{
#pragma unroll
    for (int m = 0; m < 4; m++)
#pragma unroll
        for (int n = 0; n < 4; n++) wmma::fill_fragment(acc[m][n], 0.0f);

    const int nIter = K / 64;
#pragma unroll
    for (int s = 0; s < NSTAGE - 1; s++) {
        load_stage(A, lda, B, ldb, s * 64, sb + (uint32_t)s * STAGE, tid);
        asm volatile("cp.async.commit_group;");
    }

    for (int it = 0; it < nIter; ++it) {
        if (it + NSTAGE - 2 < nIter)
            asm volatile("cp.async.wait_group %0;" :: "n"(NSTAGE - 2));
        else
            asm volatile("cp.async.wait_group 0;");
        __syncthreads();
        if (it + NSTAGE - 1 < nIter) {
            load_stage(A, lda, B, ldb, (it + NSTAGE - 1) * 64,
                       sb + (uint32_t)((it + NSTAGE - 1) % NSTAGE) * STAGE, tid);
            asm volatile("cp.async.commit_group;");
        }

        char* stg = smem + (it % NSTAGE) * STAGE;
        const __half* As = reinterpret_cast<const __half*>(stg);
        const __half* Bs = reinterpret_cast<const __half*>(stg + A_BYTES);

#pragma unroll
        for (int kk = 0; kk < 64; kk += 16) {
            wmma::fragment<wmma::matrix_a, 16, 16, 16, __half, wmma::row_major> a[4];
            wmma::fragment<wmma::matrix_b, 16, 16, 16, __half, wmma::row_major> b[4];
#pragma unroll
            for (int m = 0; m < 4; m++)
                wmma::load_matrix_sync(a[m], As + (warp_m * 64 + m * 16) * TLDA + kk, TLDA);
#pragma unroll
            for (int n = 0; n < 4; n++)
                wmma::load_matrix_sync(b[n], Bs + kk * TLDB + warp_n * 64 + n * 16, TLDB);
#pragma unroll
            for (int m = 0; m < 4; m++)
#pragma unroll
                for (int n = 0; n < 4; n++)
                    wmma::mma_sync(acc[m][n], a[m], b[n], acc[m][n]);
        }
    }
    __syncthreads();
}

// ---------------------------------------------------------------------------
// Fused GEMM1 + gate GEMM. Grid (NB, MROWS/128), 1 CTA/SM.
// ---------------------------------------------------------------------------
__global__ __launch_bounds__(256, 1) void gemm1_fused_kernel(
    const __half* __restrict__ Ahi, const __half* __restrict__ Bhi,
    const float* __restrict__ bias,
    const __half* __restrict__ wg2,
    const float* __restrict__ bgx, const float* __restrict__ bga,
    __half* __restrict__ Chi,
    __half* __restrict__ gx, __half* __restrict__ ga)
{
    extern __shared__ __align__(256) char smem[];
    const uint32_t sb = smem_u32(smem);
    const int tid = threadIdx.x, wid = tid >> 5, lane = tid & 31;
    const int warp_m = wid >> 2, warp_n = wid & 3;
    const int nb   = blockIdx.x;          // 0..7
    const int bn   = nb * 256;
    const int row0 = blockIdx.y * 128;

    wmma::fragment<wmma::accumulator, 16, 16, 16, float> acc[4][4];
    gemm_mainloop<4>(Ahi + (size_t)row0 * GK, GK, Bhi + bn, GK, GK,
                     acc, smem, sb, tid, warp_m, warp_n);

    // ---- epilogue 1: bias add; write xh hi to global and fp16 tile to smem
    __half* xhs = reinterpret_cast<__half*>(smem);              // [128][264]
    float* st = reinterpret_cast<float*>(smem + ST_OFF) + wid * (16 * 64);
#pragma unroll
    for (int m = 0; m < 4; m++) {
#pragma unroll
        for (int n = 0; n < 4; n++)
            wmma::store_matrix_sync(st + n * 16, acc[m][n], 64, wmma::mem_row_major);
        __syncwarp();
        int r = lane >> 1, cs = (lane & 1) * 32;
        int lrow = warp_m * 64 + m * 16 + r;
        int lcol = warp_n * 64 + cs;
#pragma unroll
        for (int c = 0; c < 32; c += 4) {
            float4 v = *reinterpret_cast<float4*>(st + r * 64 + cs + c);
            v.x += bias[bn + lcol + c + 0];
            v.y += bias[bn + lcol + c + 1];
            v.z += bias[bn + lcol + c + 2];
            v.w += bias[bn + lcol + c + 3];
            uint2 u = make_uint2(pack4h(__float2half_rn(v.x), __float2half_rn(v.y)),
                                 pack4h(__float2half_rn(v.z), __float2half_rn(v.w)));
            *reinterpret_cast<uint2*>(Chi + (size_t)(row0 + lrow) * GK + bn + lcol + c) = u;
            *reinterpret_cast<uint2*>(xhs + lrow * TLDB + lcol + c) = u;
        }
        __syncwarp();
    }
    __syncthreads();

    // ---- gate GEMM: [128 x 256] @ wg2[nb] (256 x 256), K streamed in 4 chunks
    const __half* wgb = wg2 + (size_t)nb * 65536;
    char* gb = smem + GB_OFF;   // double buffer, 2 x B_BYTES

#pragma unroll
    for (int i = 0; i < 8; i++) {
        int u = tid + (i << 8);
        int r = u >> 5;
        int ch = u & 31;
        cp16(sb + GB_OFF + (uint32_t)(r * 528 + ch * 16),
             wgb + (size_t)r * 256 + ch * 8);
    }
    asm volatile("cp.async.commit_group;");

    wmma::fragment<wmma::accumulator, 16, 16, 16, float> acc2[4][4];
#pragma unroll
    for (int m = 0; m < 4; m++)
#pragma unroll
        for (int n = 0; n < 4; n++) wmma::fill_fragment(acc2[m][n], 0.0f);

    for (int chunk = 0; chunk < 4; ++chunk) {
        if (chunk < 3) {
            uint32_t dst = sb + GB_OFF + (uint32_t)((chunk + 1) & 1) * B_BYTES;
#pragma unroll
            for (int i = 0; i < 8; i++) {
                int u = tid + (i << 8);
                int r = u >> 5;
                int ch = u & 31;
                cp16(dst + (uint32_t)(r * 528 + ch * 16),
                     wgb + (size_t)((chunk + 1) * 64 + r) * 256 + ch * 8);
            }
            asm volatile("cp.async.commit_group;");
            asm volatile("cp.async.wait_group 1;");
        } else {
            asm volatile("cp.async.wait_group 0;");
        }
        __syncthreads();

        const __half* Bs = reinterpret_cast<const __half*>(gb + (chunk & 1) * B_BYTES);
#pragma unroll
        for (int kk = 0; kk < 64; kk += 16) {
            int kabs = chunk * 64 + kk;
            wmma::fragment<wmma::matrix_a, 16, 16, 16, __half, wmma::row_major> a[4];
            wmma::fragment<wmma::matrix_b, 16, 16, 16, __half, wmma::row_major> b[4];
#pragma unroll
            for (int m = 0; m < 4; m++)
                wmma::load_matrix_sync(a[m], xhs + (warp_m * 64 + m * 16) * TLDB + kabs, TLDB);
#pragma unroll
            for (int n = 0; n < 4; n++)
                wmma::load_matrix_sync(b[n], Bs + kk * TLDB + warp_n * 64 + n * 16, TLDB);
#pragma unroll
            for (int m = 0; m < 4; m++)
#pragma unroll
                for (int n = 0; n < 4; n++)
                    wmma::mma_sync(acc2[m][n], a[m], b[n], acc2[m][n]);
        }
        __syncthreads();
    }

    // ---- epilogue 2: gate bias + fp16 logits
#pragma unroll
    for (int m = 0; m < 4; m++) {
#pragma unroll
        for (int n = 0; n < 4; n++)
            wmma::store_matrix_sync(st + n * 16, acc2[m][n], 64, wmma::mem_row_major);
        __syncwarp();
        int r = lane >> 1, cs = (lane & 1) * 32;
        int lrow = warp_m * 64 + m * 16 + r;
        int gcol = warp_n * 64 + cs;     // 0..255
        bool isx = gcol < 128;
        int col = isx ? gcol : gcol - 128;
        const float* bp = (isx ? bgx : bga) + nb * 128 + col;
        __half* op = (isx ? gx : ga) + (size_t)(row0 + lrow) * DH + nb * 128 + col;
#pragma unroll
        for (int c = 0; c < 32; c += 4) {
            float4 v = *reinterpret_cast<float4*>(st + r * 64 + cs + c);
            v.x += bp[c + 0];
            v.y += bp[c + 1];
            v.z += bp[c + 2];
            v.w += bp[c + 3];
            *reinterpret_cast<uint2*>(op + c) =
                make_uint2(pack4h(__float2half_rn(v.x), __float2half_rn(v.y)),
                           pack4h(__float2half_rn(v.z), __float2half_rn(v.w)));
        }
        __syncwarp();
    }
}

// ---------------------------------------------------------------------------
// GEMM2: y = h @ W_out + b_out -> fp32.
// CTA tile 128x128, NSTAGE=3, 2 CTAs/SM, warp tile 64x32 (2m x 4n).
// ---------------------------------------------------------------------------
__global__ __launch_bounds__(256, 2) void gemm2_kernel(
    const __half* __restrict__ Ahi, const __half* __restrict__ Bhi,
    const float* __restrict__ bias, float* __restrict__ C)
{
    extern __shared__ __align__(256) char smem[];
    const uint32_t sb = smem_u32(smem);
    const int tid = threadIdx.x, wid = tid >> 5, lane = tid & 31;
    const int warp_m = wid >> 2;   // 0..1 (64-row slab)
    const int warp_n = wid & 3;    // 0..3 (32-col slab)
    const int row0 = blockIdx.y * 128;
    const int bn   = blockIdx.x * 128;

    const __half* A = Ahi + (size_t)row0 * GK;
    const __half* B = Bhi + bn;

    wmma::fragment<wmma::accumulator, 16, 16, 16, float> acc[4][2];
#pragma unroll
    for (int m = 0; m < 4; m++)
#pragma unroll
        for (int n = 0; n < 2; n++) wmma::fill_fragment(acc[m][n], 0.0f);

    auto load2 = [&](int kt, uint32_t base) {
#pragma unroll
        for (int i = 0; i < 4; i++) {
            int u = tid + (i << 8);
            int r = u >> 3;
            int ch = u & 7;
            cp16(base + (uint32_t)(r * 144 + ch * 16),
                 A + (size_t)r * GK + kt + ch * 8);
        }
#pragma unroll
        for (int i = 0; i < 4; i++) {
            int u = tid + (i << 8);
            int r = u >> 4;
            int ch = u & 15;
            cp16(base + A_BYTES + (uint32_t)(r * 272 + ch * 16),
                 B + (size_t)(kt + r) * GK + ch * 8);
        }
    };

    const int nIter = GK / 64;   // 32
#pragma unroll
    for (int s = 0; s < 2; s++) {
        load2(s * 64, sb + (uint32_t)s * STAGE2);
        asm volatile("cp.async.commit_group;");
    }

    for (int it = 0; it < nIter; ++it) {
        if (it + 1 < nIter) asm volatile("cp.async.wait_group 1;");
        else                asm volatile("cp.async.wait_group 0;");
        __syncthreads();
        if (it + 2 < nIter) {
            load2((it + 2) * 64, sb + (uint32_t)((it + 2) % 3) * STAGE2);
            asm volatile("cp.async.commit_group;");
        }

        char* stg = smem + (it % 3) * STAGE2;
        const __half* As = reinterpret_cast<const __half*>(stg);
        const __half* Bs = reinterpret_cast<const __half*>(stg + A_BYTES);

#pragma unroll
        for (int kk = 0; kk < 64; kk += 16) {
            wmma::fragment<wmma::matrix_a, 16, 16, 16, __half, wmma::row_major> a[4];
            wmma::fragment<wmma::matrix_b, 16, 16, 16, __half, wmma::row_major> b[2];
#pragma unroll
            for (int m = 0; m < 4; m++)
                wmma::load_matrix_sync(a[m], As + (warp_m * 64 + m * 16) * TLDA + kk, TLDA);
#pragma unroll
            for (int n = 0; n < 2; n++)
                wmma::load_matrix_sync(b[n], Bs + kk * T2LDB + warp_n * 32 + n * 16, T2LDB);
#pragma unroll
            for (int m = 0; m < 4; m++)
#pragma unroll
                for (int n = 0; n < 2; n++)
                    wmma::mma_sync(acc[m][n], a[m], b[n], acc[m][n]);
        }
    }
    __syncthreads();

    float* st = reinterpret_cast<float*>(smem) + wid * (16 * 32);
#pragma unroll
    for (int m = 0; m < 4; m++) {
        wmma::store_matrix_sync(st,      acc[m][0], 32, wmma::mem_row_major);
        wmma::store_matrix_sync(st + 16, acc[m][1], 32, wmma::mem_row_major);
        __syncwarp();
        int r  = lane >> 1;
        int cs = (lane & 1) * 16;
        int grow = row0 + warp_m * 64 + m * 16 + r;
        int gcol = bn + warp_n * 32 + cs;
#pragma unroll
        for (int c = 0; c < 16; c += 4) {
            float4 v = *reinterpret_cast<float4*>(st + r * 32 + cs + c);
            v.x += bias[gcol + c + 0];
            v.y += bias[gcol + c + 1];
            v.z += bias[gcol + c + 2];
            v.w += bias[gcol + c + 3];
            *reinterpret_cast<float4*>(C + (size_t)grow * GK + gcol + c) = v;
        }
        __syncwarp();
    }
}

// ---------------------------------------------------------------------------
// Fused pointwise + warp scan, cp.async pipelined, 64 steps/tile with
// 2 elements per lane (pair scan). Dynamic smem, pad 38 (4B-aligned rows).
// Grid: 128 CTAs (4 batches x 32 d-blocks), 1024 threads (32 warps).
// ---------------------------------------------------------------------------
__global__ __launch_bounds__(1024) void scanfused_kernel(
    const __half* __restrict__ xhhi,
    const __half* __restrict__ gxl, const __half* __restrict__ gal,
    const float* __restrict__ arp, const float* __restrict__ aip,
    __half* __restrict__ hout, float* __restrict__ h_last)
{
    extern __shared__ __align__(16) char ssm[];
    __half* sIn = reinterpret_cast<__half*>(ssm);
    float* sHr = reinterpret_cast<float*>(ssm + SHR_OFF);   // [64][33]
    float* sHi = reinterpret_cast<float*>(ssm + SHI_OFF);   // [64][33]

    const int b  = blockIdx.x >> 5;
    const int db = (blockIdx.x & 31) * 32;
    const int tid = threadIdx.x;
    const int w = tid >> 5;    // warp -> chain d = db + w
    const int j = tid & 31;    // lane -> step pair (2j, 2j+1) within tile
    const int d = db + w;
    const uint32_t sInb = smem_u32(ssm);

    float av = arp[d];
    float sp = fmaxf(av, 0.f) + log1pf(__expf(-fabsf(av)));   // softplus
    float aipd = aip[d];

    // issue one 64-step tile (4 arrays x 64 rows x 64B) via cp.async 4B
    const int lr = tid >> 4;          // row within tile (0..63)
    const int lc = (tid & 15) << 1;   // half index (even)
    auto issue_tile = [&](int s0, int buf) {
        size_t row = (size_t)(b * S_SZ + s0 + lr);
        const __half* s0p = gxl  + row * DH   + db + lc;
        const __half* s1p = gal  + row * DH   + db + lc;
        const __half* s2p = xhhi + row * DHID + db + lc;
        const __half* s3p = xhhi + row * DHID + DH + db + lc;
        uint32_t base = sInb + (uint32_t)(((buf * 4) * 64 + lr) * SPAD + lc) * 2;
        const uint32_t astep = (uint32_t)(64 * SPAD * 2);
        cp4(base,             s0p);
        cp4(base + astep,     s1p);
        cp4(base + 2 * astep, s2p);
        cp4(base + 3 * astep, s3p);
        asm volatile("cp.async.commit_group;");
    };

    float cr = 0.f, ci = 0.f;

    issue_tile(0, 0);

    const int nTiles = S_SZ / 64;   // 64
    for (int t = 0; t < nTiles; ++t) {
        asm volatile("cp.async.wait_group 0;");
        __syncthreads();
        if (t + 1 < nTiles) issue_tile((t + 1) * 64, (t + 1) & 1);

        const int cur = t & 1;
        const int r0 = 2 * j, r1 = 2 * j + 1;
        const int ib = (cur * 4) * 64 * SPAD;

        // pointwise for both steps of this lane's pair
        auto pw = [&](int r, float& oar, float& oai, float& oxr, float& oxi) {
            float gxv = __fdividef(1.f, 1.f + __expf(
                -__half2float(sIn[ib + (0 * 64 + r) * SPAD + w])));
            float gav = __fdividef(1.f, 1.f + __expf(
                -__half2float(sIn[ib + (1 * 64 + r) * SPAD + w])));
            float log_a = -8.f * gav * sp;
            float mag = __expf(log_a);
            float th = aipd * gav;
            float sn = __sinf(th);
            float cs = __cosf(th);
            oar = mag * cs;
            oai = mag * sn;
            float nrm = sqrtf(fmaxf(1.f - mag * mag, 0.f));
            float scale = gxv * nrm;
            oxr = scale * __half2float(sIn[ib + (2 * 64 + r) * SPAD + w]);
            oxi = scale * __half2float(sIn[ib + (3 * 64 + r) * SPAD + w]);
        };
        float a0r, a0i, x0r, x0i, a1r, a1i, x1r, x1i;
        pw(r0, a0r, a0i, x0r, x0i);
        pw(r1, a1r, a1i, x1r, x1i);

        // pair composite p = e1 o e0
        float apr = a1r * a0r - a1i * a0i;
        float api = a1r * a0i + a1i * a0r;
        float xpr = fmaf(a1r, x0r, fmaf(-a1i, x0i, x1r));
        float xpi = fmaf(a1r, x0i, fmaf(a1i, x0r, x1i));

        // inclusive warp scan over pair composites
#pragma unroll
        for (int off = 1; off < 32; off <<= 1) {
            float par = __shfl_up_sync(0xffffffffu, apr, off);
            float pai = __shfl_up_sync(0xffffffffu, api, off);
            float pxr = __shfl_up_sync(0xffffffffu, xpr, off);
            float pxi = __shfl_up_sync(0xffffffffu, xpi, off);
            if (j >= off) {
                float nar = apr * par - api * pai;
                float nai = apr * pai + api * par;
                float nxr = fmaf(apr, pxr, fmaf(-api, pxi, xpr));
                float nxi = fmaf(apr, pxi, fmaf(api, pxr, xpi));
                apr = nar; api = nai; xpr = nxr; xpi = nxi;
            }
        }

        // exclusive prefix (shift by one lane; lane 0 = identity)
        float epr = __shfl_up_sync(0xffffffffu, apr, 1);
        float epi = __shfl_up_sync(0xffffffffu, api, 1);
        float exr = __shfl_up_sync(0xffffffffu, xpr, 1);
        float exi = __shfl_up_sync(0xffffffffu, xpi, 1);
        if (j == 0) { epr = 1.f; epi = 0.f; exr = 0.f; exi = 0.f; }

        // state entering this lane's pair
        float sr = fmaf(epr, cr, fmaf(-epi, ci, exr));
        float si = fmaf(epr, ci, fmaf(epi, cr, exi));
        // h for even step, then odd step
        float her = fmaf(a0r, sr, fmaf(-a0i, si, x0r));
        float hei = fmaf(a0r, si, fmaf(a0i, sr, x0i));
        float hor = fmaf(a1r, her, fmaf(-a1i, hei, x1r));
        float hoi = fmaf(a1r, hei, fmaf(a1i, her, x1i));

        cr = __shfl_sync(0xffffffffu, hor, 31);
        ci = __shfl_sync(0xffffffffu, hoi, 31);

        sHr[r0 * 33 + w] = her;
        sHr[r1 * 33 + w] = hor;
        sHi[r0 * 33 + w] = hei;
        sHi[r1 * 33 + w] = hoi;
        __syncthreads();

        // coalesced store: thread (w = s-row, j = d-col), two row rounds
#pragma unroll
        for (int rr = 0; rr < 2; rr++) {
            int lrow = w + rr * 32;
            size_t orow = (size_t)(b * S_SZ + t * 64 + lrow) * DHID;
            hout[orow + db + j]      = __float2half_rn(sHr[lrow * 33 + j]);
            hout[orow + DH + db + j] = __float2half_rn(sHi[lrow * 33 + j]);
        }
        __syncthreads();
    }

    if (j == 0) {
        h_last[(size_t)b * DHID + d]      = cr;
        h_last[(size_t)b * DHID + DH + d] = ci;
    }
}

// ---------------------------------------------------------------------------
// Launch
// ---------------------------------------------------------------------------
extern "C" void kernel_launch(void* const* d_in, const int* in_sizes, int n_in,
                              void* d_out, int out_size)
{
    const float* x     = (const float*)d_in[0];
    const float* arp   = (const float*)d_in[1];
    const float* aip   = (const float*)d_in[2];
    const float* W_in  = (const float*)d_in[3];
    const float* b_in  = (const float*)d_in[4];
    const float* Wgx   = (const float*)d_in[5];
    const float* bgx   = (const float*)d_in[6];
    const float* Wga   = (const float*)d_in[7];
    const float* bga   = (const float*)d_in[8];
    const float* W_out = (const float*)d_in[9];
    const float* b_out = (const float*)d_in[10];

    float* y = (float*)d_out;
    float* h_last = (float*)d_out + ((size_t)out_size - (size_t)B_SZ * DHID);

    __half *gx, *ga, *xsp, *h, *xhhi, *win, *wout, *wg2;
    cudaGetSymbolAddress((void**)&gx,   g_gx);
    cudaGetSymbolAddress((void**)&ga,   g_ga);
    cudaGetSymbolAddress((void**)&xsp,  g_xsp);
    cudaGetSymbolAddress((void**)&h,    g_h);
    cudaGetSymbolAddress((void**)&xhhi, g_xhhi);
    cudaGetSymbolAddress((void**)&win,  g_win);
    cudaGetSymbolAddress((void**)&wout, g_wout);
    cudaGetSymbolAddress((void**)&wg2,  g_wg2);

    cudaFuncSetAttribute(gemm1_fused_kernel,
                         cudaFuncAttributeMaxDynamicSharedMemorySize, SMEM_BIG);
    cudaFuncSetAttribute(gemm2_kernel,
                         cudaFuncAttributeMaxDynamicSharedMemorySize, SMEM_G2);
    cudaFuncSetAttribute(scanfused_kernel,
                         cudaFuncAttributeMaxDynamicSharedMemorySize, SMEM_SCAN);

    const size_t nx4 = (size_t)MROWS * GK / 4;
    const size_t nw4 = (size_t)GK * GK / 4;

    // 0) conversions (independent)
    cvt_hi16_kernel<<<(unsigned)((nx4 + 255) / 256), 256>>>(
        (const float4*)x, (uint2*)xsp, nx4);
    cvt_hi16_kernel<<<(unsigned)((nw4 + 255) / 256), 256>>>(
        (const float4*)W_in, (uint2*)win, nw4);
    cvt_hi16_kernel<<<(unsigned)((nw4 + 255) / 256), 256>>>(
        (const float4*)W_out, (uint2*)wout, nw4);
    cvt_gatew_kernel<<<(NB * 256 * 256) / 256, 256>>>(Wgx, Wga, wg2);

    // 1+2) fused: xh = x @ W_in + b_in (hi out) AND gate logits
    gemm1_fused_kernel<<<dim3(NB, MROWS / 128), 256, SMEM_BIG>>>(
        xsp, win, b_in, wg2, bgx, bga, xhhi, gx, ga);

    // 3+4) fused pointwise + pair-scan (cp.async pipelined); h as fp16 hi
    scanfused_kernel<<<B_SZ * (DH / 32), 1024, SMEM_SCAN>>>(
        xhhi, gx, ga, arp, aip, h, h_last);

    // 5) y = h @ W_out + b_out (128x128 tiles, 2 CTAs/SM)
    gemm2_kernel<<<dim3(GK / 128, MROWS / 128), 256, SMEM_G2>>>(
        h, wout, b_out, y);
}